// round 6
// baseline (speedup 1.0000x reference)
#include <cuda_runtime.h>
#include <math.h>

// Problem constants
constexpr int B_  = 256;
constexpr int N_  = 2048;
constexpr int M_  = 64;
constexpr int C_  = 512;
constexpr int PR_ = 70;   // M + 3 + SHIFT
constexpr int PW_ = 198;  // PR + 2M
constexpr float EPSF = 1e-8f;

// Output layout (floats): ntm_out, memory, read_out, new_read_w, new_write_w
constexpr size_t OUT_MEM = 65536;
constexpr size_t OUT_RO  = 33619968;
constexpr size_t OUT_RW  = 33685504;
constexpr size_t OUT_WW  = 35782656;

// ---------------- device scratch (no allocations allowed) ----------------
__device__ float g_ctrl[B_*C_];
__device__ float g_rp  [4*B_*PR_];
__device__ float g_wp  [4*B_*PW_];
__device__ float g_dot [5*(size_t)B_*N_];
__device__ float g_norm[(size_t)B_*N_];
__device__ float g_base[6*(size_t)B_*N_];   // base dots: Da,Db,S1,S2,T0,T1
__device__ float g_ropart[2*B_*256];

__device__ __forceinline__ float softplusf(float x){ return x > 20.f ? x : log1pf(expf(x)); }
__device__ __forceinline__ float sigmoidf (float x){ return 1.f/(1.f+expf(-x)); }

// ---------------- GEMM body: out[256,Nc] = concat(A0,A1)[256,K] @ W[K,Nc] + bias ----------------
// Tile 32(M) x 64(N), K-step 64, 256 threads.
__device__ __forceinline__ void gemm_body(
    const float* __restrict__ A0, int ca,
    const float* __restrict__ A1, int cb,
    const float* __restrict__ W, const float* __restrict__ bias,
    float* __restrict__ out, int Nc)
{
    int col0 = blockIdx.x * 64;
    if (col0 >= Nc) return;
    int row0 = blockIdx.y * 32;
    int K = ca + cb;

    __shared__ float As[32][65];
    __shared__ float Ws[64][64];
    int tid = threadIdx.x;
    int tx = tid & 15, ty = tid >> 4;
    float acc[2][4] = {};

    for (int k0 = 0; k0 < K; k0 += 64) {
        // A tile: 32 x 64 — each thread 8 elems (2 float4). ca,cb are multiples of 64,
        // so a whole 64-k block lies on one side of the concat.
        {
            int m  = tid >> 3;
            int kk = (tid & 7) * 8;
            int r = row0 + m, c = k0 + kk;
            float4 v0, v1;
            if (c < ca) {
                const float* s = A0 + (size_t)r*ca + c;
                v0 = *(const float4*)s; v1 = *(const float4*)(s + 4);
            } else {
                const float* s = A1 + (size_t)r*cb + (c - ca);
                v0 = *(const float4*)s; v1 = *(const float4*)(s + 4);
            }
            As[m][kk+0] = v0.x; As[m][kk+1] = v0.y; As[m][kk+2] = v0.z; As[m][kk+3] = v0.w;
            As[m][kk+4] = v1.x; As[m][kk+5] = v1.y; As[m][kk+6] = v1.z; As[m][kk+7] = v1.w;
        }
        // W tile: 64 x 64 — each thread 16 elems from one k-row
        {
            int wk = tid >> 2;
            int n0 = (tid & 3) * 16;
            const float* wrow = W + (size_t)(k0 + wk)*Nc + col0;
            #pragma unroll
            for (int j = 0; j < 16; j++) {
                int gn = col0 + n0 + j;
                Ws[wk][n0 + j] = (gn < Nc) ? wrow[n0 + j] : 0.f;
            }
        }
        __syncthreads();
        #pragma unroll
        for (int kk = 0; kk < 64; kk++) {
            float a0 = As[ty*2 + 0][kk];
            float a1 = As[ty*2 + 1][kk];
            float4 w4 = *(const float4*)&Ws[kk][tx*4];
            acc[0][0] += a0*w4.x; acc[0][1] += a0*w4.y; acc[0][2] += a0*w4.z; acc[0][3] += a0*w4.w;
            acc[1][0] += a1*w4.x; acc[1][1] += a1*w4.y; acc[1][2] += a1*w4.z; acc[1][3] += a1*w4.w;
        }
        __syncthreads();
    }
    #pragma unroll
    for (int i = 0; i < 2; i++) {
        int gm = row0 + ty*2 + i;
        #pragma unroll
        for (int j = 0; j < 4; j++) {
            int gn = col0 + tx*4 + j;
            if (gn < Nc) out[(size_t)gm*Nc + gn] = acc[i][j] + bias[gn];
        }
    }
}

__global__ void gemm_cat_kernel(const float* __restrict__ A0, int ca,
                                const float* __restrict__ A1, int cb,
                                const float* __restrict__ W, const float* __restrict__ bias,
                                float* __restrict__ out, int Nc)
{
    gemm_body(A0, ca, A1, cb, W, bias, out, Nc);
}

__global__ void gemm_heads_kernel(const float* __restrict__ ctrl,
                                  const float* __restrict__ readW, const float* __restrict__ readb,
                                  float* __restrict__ rp,
                                  const float* __restrict__ writeW, const float* __restrict__ writeb,
                                  float* __restrict__ wp)
{
    int h = blockIdx.z;
    const float *W, *bias; float* out; int Nc;
    if (h < 4) {
        W = readW + (size_t)h*C_*PR_; bias = readb + h*PR_;
        out = rp + (size_t)h*B_*PR_;  Nc = PR_;
    } else {
        int g = h - 4;
        W = writeW + (size_t)g*C_*PW_; bias = writeb + g*PW_;
        out = wp + (size_t)g*B_*PW_;   Nc = PW_;
    }
    gemm_body(ctrl, C_, nullptr, 0, W, bias, out, Nc);
}

// ---------------- Pass A: mem norms + 5 key dots + head-1 base dots ----------------
// Half-warp (16 lanes, float4/lane) per row; 2-row unroll (MLP 4).
__global__ void __launch_bounds__(256) passA_kernel(const float* __restrict__ mem)
{
    int bc = blockIdx.x; int b = bc >> 1; int nb = (bc & 1) << 10;
    int tid = threadIdx.x, wid = tid >> 5, lane = tid & 31;
    int hw = lane >> 4, l16 = lane & 15;

    // Scalar key loads (key rows are NOT 16B aligned: PR_=70, PW_=198)
    float kk[5][4];
    #pragma unroll
    for (int h = 0; h < 5; h++) {
        const float* kp = (h < 4) ? (g_rp + ((size_t)h*B_ + b)*PR_) : (g_wp + (size_t)b*PW_);
        #pragma unroll
        for (int j = 0; j < 4; j++) kk[h][j] = kp[l16*4 + j];
    }
    // Head-0 erase/add + head-1 key, per-lane (4 m's each)
    const float* wp0 = g_wp + (size_t)b*PW_;
    const float* wp1 = g_wp + ((size_t)1*B_ + b)*PW_;
    float e0[4], a0[4], k1[4], e0sq[4], e0a0[4], e0k1[4];
    #pragma unroll
    for (int j = 0; j < 4; j++) {
        int m = l16*4 + j;
        e0[j] = sigmoidf(wp0[70 + m]);
        a0[j] = tanhf(wp0[134 + m]);
        k1[j] = wp1[m];
        e0sq[j] = e0[j]*e0[j];
        e0a0[j] = e0[j]*a0[j];
        e0k1[j] = e0[j]*k1[j];
    }

    const float* base = mem + ((size_t)b*N_ + nb)*M_;
    for (int it = 0; it < 64; it += 2) {
        int rA = it*16 + wid*2 + hw;
        int rB = rA + 16;
        float4 va = *(const float4*)(base + (size_t)rA*M_ + l16*4);
        float4 vb = *(const float4*)(base + (size_t)rB*M_ + l16*4);

        float v[4]  = {va.x, va.y, va.z, va.w};
        float u[4]  = {vb.x, vb.y, vb.z, vb.w};
        float accA[12] = {}, accB[12] = {};
        #pragma unroll
        for (int j = 0; j < 4; j++) {
            float vj = v[j], uj = u[j];
            float vs = vj*vj, us = uj*uj;
            accA[0] += vs;               accB[0] += us;                 // norm^2
            #pragma unroll
            for (int h = 0; h < 5; h++) {
                accA[1+h] += vj*kk[h][j];
                accB[1+h] += uj*kk[h][j];
            }
            accA[6]  += vj*k1[j];        accB[6]  += uj*k1[j];          // Da
            accA[7]  += vj*e0k1[j];      accB[7]  += uj*e0k1[j];        // Db
            accA[8]  += vs*e0[j];        accB[8]  += us*e0[j];          // S1
            accA[9]  += vs*e0sq[j];      accB[9]  += us*e0sq[j];        // S2
            accA[10] += vj*a0[j];        accB[10] += uj*a0[j];          // T0
            accA[11] += vj*e0a0[j];      accB[11] += uj*e0a0[j];        // T1
        }
        #pragma unroll
        for (int o = 8; o > 0; o >>= 1) {
            #pragma unroll
            for (int r = 0; r < 12; r++) {
                accA[r] += __shfl_xor_sync(0xffffffffu, accA[r], o);
                accB[r] += __shfl_xor_sync(0xffffffffu, accB[r], o);
            }
        }
        if (l16 == 0) {
            size_t ixA = (size_t)b*N_ + nb + rA;
            size_t ixB = (size_t)b*N_ + nb + rB;
            g_norm[ixA] = sqrtf(accA[0]);
            g_norm[ixB] = sqrtf(accB[0]);
            #pragma unroll
            for (int h = 0; h < 5; h++) {
                g_dot[(size_t)h*B_*N_ + ixA] = accA[1+h];
                g_dot[(size_t)h*B_*N_ + ixB] = accB[1+h];
            }
            #pragma unroll
            for (int r = 0; r < 6; r++) {
                g_base[(size_t)r*B_*N_ + ixA] = accA[6+r];
                g_base[(size_t)r*B_*N_ + ixB] = accB[6+r];
            }
        }
    }
}

// ---------------- block reduction helpers (256 threads) ----------------
__device__ __forceinline__ float block_reduce_sum(float v, float* sbuf)
{
    int tid = threadIdx.x;
    #pragma unroll
    for (int o = 16; o > 0; o >>= 1) v += __shfl_xor_sync(0xffffffffu, v, o);
    if ((tid & 31) == 0) sbuf[tid >> 5] = v;
    __syncthreads();
    if (tid < 32) {
        float x = (tid < 8) ? sbuf[tid] : 0.f;
        #pragma unroll
        for (int o = 4; o > 0; o >>= 1) x += __shfl_xor_sync(0xffffffffu, x, o);
        if (tid == 0) sbuf[0] = x;
    }
    __syncthreads();
    float r = sbuf[0];
    __syncthreads();
    return r;
}

__device__ __forceinline__ float block_reduce_max(float v, float* sbuf)
{
    int tid = threadIdx.x;
    #pragma unroll
    for (int o = 16; o > 0; o >>= 1) v = fmaxf(v, __shfl_xor_sync(0xffffffffu, v, o));
    if ((tid & 31) == 0) sbuf[tid >> 5] = v;
    __syncthreads();
    if (tid < 32) {
        float x = (tid < 8) ? sbuf[tid] : -3.4e38f;
        #pragma unroll
        for (int o = 4; o > 0; o >>= 1) x = fmaxf(x, __shfl_xor_sync(0xffffffffu, x, o));
        if (tid == 0) sbuf[0] = x;
    }
    __syncthreads();
    float r = sbuf[0];
    __syncthreads();
    return r;
}

// ---------------- addressing tail (after per-n scaled-cos values x[8] are built) --------------
__device__ __forceinline__ void address_tail(
    float* x, float knorm_unused, float g, float s0, float s1, float s2, float gamma,
    const float* __restrict__ wpb, float* __restrict__ woutb,
    float* wg, float* rbuf)
{
    int tid = threadIdx.x;
    float mx = -3.4e38f;
    #pragma unroll
    for (int i = 0; i < 8; i++) mx = fmaxf(mx, x[i]);
    float bmax = block_reduce_max(mx, rbuf);
    float lsum = 0.f;
    #pragma unroll
    for (int i = 0; i < 8; i++) {
        float e = __expf(x[i] - bmax);
        wg[tid + i*256] = e;
        lsum += e;
    }
    float bsum = block_reduce_sum(lsum, rbuf);
    float inv = 1.f / bsum;
    #pragma unroll
    for (int i = 0; i < 8; i++) {
        int n = tid + i*256;
        wg[n] = g * (wg[n]*inv) + (1.f-g) * wpb[n];
    }
    __syncthreads();
    float wpow[8];
    lsum = 0.f;
    #pragma unroll
    for (int i = 0; i < 8; i++) {
        int n = tid + i*256;
        float ws = s0*wg[(n+1)&(N_-1)] + s1*wg[n] + s2*wg[(n-1)&(N_-1)];
        float t = __powf(ws + EPSF, gamma);
        wpow[i] = t;
        lsum += t;
    }
    float psum = block_reduce_sum(lsum, rbuf);
    float ip = 1.f / psum;
    #pragma unroll
    for (int i = 0; i < 8; i++)
        woutb[tid + i*256] = wpow[i]*ip;
}

// ---------------- NTM addressing body (dot/norm from planes) ----------------
__device__ __forceinline__ void address_body(
    const float* __restrict__ p,
    const float* __restrict__ dotb,
    const float* __restrict__ nrmb,
    const float* __restrict__ wpb,
    float* __restrict__ woutb)
{
    int tid = threadIdx.x;
    __shared__ float wg[2048];
    __shared__ float rbuf[32];
    __shared__ float sc[7];

    float kv = 0.f;
    if (tid < 64) { float x = p[tid]; kv = x*x; }
    float ksum = block_reduce_sum(kv, rbuf);
    if (tid == 0) {
        sc[0] = sqrtf(ksum);
        sc[1] = softplusf(p[64]);
        sc[2] = sigmoidf(p[65]);
        float a0 = p[66], a1 = p[67], a2 = p[68];
        float mx = fmaxf(a0, fmaxf(a1, a2));
        float e0 = expf(a0-mx), e1 = expf(a1-mx), e2 = expf(a2-mx);
        float es = e0 + e1 + e2;
        sc[3] = e0/es; sc[4] = e1/es; sc[5] = e2/es;
        sc[6] = 1.f + softplusf(p[69]);
    }
    __syncthreads();
    float knorm = sc[0], beta = sc[1], g = sc[2];
    float s0 = sc[3], s1 = sc[4], s2 = sc[5], gamma = sc[6];

    float x[8];
    #pragma unroll
    for (int i = 0; i < 8; i++) {
        int n = tid + i*256;
        float cosv = dotb[n] / (nrmb[n]*knorm + EPSF);
        x[i] = beta * cosv;
    }
    address_tail(x, knorm, g, s0, s1, s2, gamma, wpb, woutb, wg, rbuf);
}

__global__ void address5_kernel(const float* __restrict__ prw,
                                const float* __restrict__ pww,
                                float* __restrict__ o_rw,
                                float* __restrict__ o_ww)
{
    int b = blockIdx.x, h = blockIdx.y;
    const float *p, *dotp, *wprev; float* wout;
    if (h < 4) {
        p     = g_rp + ((size_t)h*B_ + b)*PR_;
        dotp  = g_dot + (size_t)h*B_*N_ + (size_t)b*N_;
        wprev = prw  + (size_t)h*B_*N_ + (size_t)b*N_;
        wout  = o_rw + (size_t)h*B_*N_ + (size_t)b*N_;
    } else {
        p     = g_wp + (size_t)b*PW_;
        dotp  = g_dot + (size_t)4*B_*N_ + (size_t)b*N_;
        wprev = pww  + (size_t)b*N_;
        wout  = o_ww + (size_t)b*N_;
    }
    address_body(p, dotp, g_norm + (size_t)b*N_, wprev, wout);
}

// exact-plane addressing for write head h (head 2)
__global__ void address1_kernel(int h,
                                const float* __restrict__ pww,
                                float* __restrict__ o_ww)
{
    int b = blockIdx.x;
    address_body(g_wp + ((size_t)h*B_ + b)*PW_,
                 g_dot + (size_t)4*B_*N_ + (size_t)b*N_,
                 g_norm + (size_t)b*N_,
                 pww  + (size_t)h*B_*N_ + (size_t)b*N_,
                 o_ww + (size_t)h*B_*N_ + (size_t)b*N_);
}

// ---------------- fused poly + addressing for write heads 1,3 ----------------
// dot/norm computed inline from base dots + new weight of the previous head.
__global__ void address_poly_kernel(int he, int hk,
                                    const float* __restrict__ wprev,  // past_write_w plane hk
                                    const float* __restrict__ wdone,  // new write w plane he
                                    float* __restrict__ wout)         // new write w plane hk
{
    int b = blockIdx.x, tid = threadIdx.x;
    __shared__ float wg[2048];
    __shared__ float rbuf[32];
    __shared__ float sc[9];

    const float* pe = g_wp + ((size_t)he*B_ + b)*PW_;
    const float* p  = g_wp + ((size_t)hk*B_ + b)*PW_;

    float kv = 0.f, c1 = 0.f, c2 = 0.f;
    if (tid < 64) {
        float k = p[tid];
        float a = tanhf(pe[134 + tid]);
        kv = k*k; c1 = a*k; c2 = a*a;
    }
    float ksum = block_reduce_sum(kv, rbuf);
    float Cc   = block_reduce_sum(c1, rbuf);
    float U    = block_reduce_sum(c2, rbuf);
    if (tid == 0) {
        sc[0] = sqrtf(ksum);
        sc[1] = softplusf(p[64]);
        sc[2] = sigmoidf(p[65]);
        float a0 = p[66], a1 = p[67], a2 = p[68];
        float mx = fmaxf(a0, fmaxf(a1, a2));
        float e0 = expf(a0-mx), e1 = expf(a1-mx), e2 = expf(a2-mx);
        float es = e0 + e1 + e2;
        sc[3] = e0/es; sc[4] = e1/es; sc[5] = e2/es;
        sc[6] = 1.f + softplusf(p[69]);
        sc[7] = Cc; sc[8] = U;
    }
    __syncthreads();
    float knorm = sc[0], beta = sc[1], g = sc[2];
    float s0 = sc[3], s1 = sc[4], s2 = sc[5], gamma = sc[6];
    float CC = sc[7], UU = sc[8];

    size_t base = (size_t)b*N_;
    const size_t P = (size_t)B_*N_;
    const float* nrmp = g_norm + base;

    float x[8];
    #pragma unroll
    for (int i = 0; i < 8; i++) {
        int n = tid + i*256;
        float w  = wdone[base + n];
        float Da = g_base[0*P + base + n];
        float Db = g_base[1*P + base + n];
        float S1 = g_base[2*P + base + n];
        float S2 = g_base[3*P + base + n];
        float T0 = g_base[4*P + base + n];
        float T1 = g_base[5*P + base + n];
        float nr = nrmp[n];
        float S0 = nr*nr;
        float dotv = Da - w*Db + w*CC;
        float w2 = w*w;
        float nsq = S0 - 2.f*w*S1 + w2*S2 + 2.f*w*T0 - 2.f*w2*T1 + w2*UU;
        float nn = sqrtf(fmaxf(nsq, 0.f));
        x[i] = beta * (dotv / (nn*knorm + EPSF));
    }
    address_tail(x, knorm, g, s0, s1, s2, gamma, wprev + base, wout + base, wg, rbuf);
}

// ---------------- Sweep 1: reads einsum + heads 0&1 update + dot2/norm2 + head-3 bases ---------
__global__ void __launch_bounds__(256) sweep1_kernel(
    const float* __restrict__ mem_in, float* __restrict__ mem_out,
    const float* __restrict__ wr,    // new_read_w [4][B][N]
    const float* __restrict__ wwp,   // new_write_w planes (0,1 used)
    float* __restrict__ ro_part)
{
    int bc = blockIdx.x; int b = bc >> 1; int nb = (bc & 1) << 10;
    int tid = threadIdx.x, wid = tid >> 5, lane = tid & 31;
    int hw = lane >> 4, l16 = lane & 15;

    __shared__ float4 sred[8][4][32];

    const float* p0 = g_wp + (size_t)b*PW_;
    const float* p1 = g_wp + ((size_t)1*B_ + b)*PW_;
    const float* p2 = g_wp + ((size_t)2*B_ + b)*PW_;
    const float* p3 = g_wp + ((size_t)3*B_ + b)*PW_;
    float e0[4], a0[4], e1[4], a1[4], k2[4], e2[4], a2[4], k3[4];
    float e2k3[4], e2sq[4], e2a2[4];
    #pragma unroll
    for (int j = 0; j < 4; j++) {
        int m = l16*4 + j;
        e0[j] = sigmoidf(p0[70 + m]);  a0[j] = tanhf(p0[134 + m]);
        e1[j] = sigmoidf(p1[70 + m]);  a1[j] = tanhf(p1[134 + m]);
        k2[j] = p2[m];
        e2[j] = sigmoidf(p2[70 + m]);  a2[j] = tanhf(p2[134 + m]);
        k3[j] = p3[m];
        e2k3[j] = e2[j]*k3[j];
        e2sq[j] = e2[j]*e2[j];
        e2a2[j] = e2[j]*a2[j];
    }

    float4 racc[4] = {{0,0,0,0},{0,0,0,0},{0,0,0,0},{0,0,0,0}};
    const size_t P = (size_t)B_*N_;
    float* dot2p = g_dot + 4*P;

    for (int it = 0; it < 64; it += 2) {
        int rA = it*16 + wid*2 + hw;
        int rB = rA + 16;
        size_t ixA = (size_t)b*N_ + nb + rA;
        size_t ixB = (size_t)b*N_ + nb + rB;

        float4 va = *(const float4*)(mem_in + ixA*M_ + l16*4);
        float4 vb = *(const float4*)(mem_in + ixB*M_ + l16*4);
        float w0A = wwp[ixA],     w0B = wwp[ixB];
        float w1A = wwp[P + ixA], w1B = wwp[P + ixB];
        float wvA[4], wvB[4];
        #pragma unroll
        for (int h = 0; h < 4; h++) {
            wvA[h] = wr[(size_t)h*P + ixA];
            wvB[h] = wr[(size_t)h*P + ixB];
        }

        float v[4]  = {va.x, va.y, va.z, va.w};
        float u[4]  = {vb.x, vb.y, vb.z, vb.w};
        float m2A[4], m2B[4];
        float accA[8] = {}, accB[8] = {};
        #pragma unroll
        for (int j = 0; j < 4; j++) {
            float m1a = v[j]*(1.f - w0A*e0[j]) + w0A*a0[j];
            float m1b = u[j]*(1.f - w0B*e0[j]) + w0B*a0[j];
            float m2a = m1a*(1.f - w1A*e1[j]) + w1A*a1[j];
            float m2b = m1b*(1.f - w1B*e1[j]) + w1B*a1[j];
            m2A[j] = m2a; m2B[j] = m2b;
            float sa = m2a*m2a, sb = m2b*m2b;
            accA[0] += m2a*k2[j];    accB[0] += m2b*k2[j];    // dot2
            accA[1] += sa;           accB[1] += sb;           // norm2^2
            accA[2] += m2a*k3[j];    accB[2] += m2b*k3[j];    // Da
            accA[3] += m2a*e2k3[j];  accB[3] += m2b*e2k3[j];  // Db
            accA[4] += sa*e2[j];     accB[4] += sb*e2[j];     // S1
            accA[5] += sa*e2sq[j];   accB[5] += sb*e2sq[j];   // S2
            accA[6] += m2a*a2[j];    accB[6] += m2b*a2[j];    // T0
            accA[7] += m2a*e2a2[j];  accB[7] += m2b*e2a2[j];  // T1
        }
        #pragma unroll
        for (int h = 0; h < 4; h++) {
            racc[h].x += wvA[h]*v[0] + wvB[h]*u[0];
            racc[h].y += wvA[h]*v[1] + wvB[h]*u[1];
            racc[h].z += wvA[h]*v[2] + wvB[h]*u[2];
            racc[h].w += wvA[h]*v[3] + wvB[h]*u[3];
        }

        *(float4*)(mem_out + ixA*M_ + l16*4) = make_float4(m2A[0], m2A[1], m2A[2], m2A[3]);
        *(float4*)(mem_out + ixB*M_ + l16*4) = make_float4(m2B[0], m2B[1], m2B[2], m2B[3]);

        #pragma unroll
        for (int o = 8; o > 0; o >>= 1) {
            #pragma unroll
            for (int r = 0; r < 8; r++) {
                accA[r] += __shfl_xor_sync(0xffffffffu, accA[r], o);
                accB[r] += __shfl_xor_sync(0xffffffffu, accB[r], o);
            }
        }
        if (l16 == 0) {
            dot2p[ixA] = accA[0];            dot2p[ixB] = accB[0];
            g_norm[ixA] = sqrtf(accA[1]);    g_norm[ixB] = sqrtf(accB[1]);
            #pragma unroll
            for (int r = 0; r < 6; r++) {
                g_base[(size_t)r*P + ixA] = accA[2+r];
                g_base[(size_t)r*P + ixB] = accB[2+r];
            }
        }
    }

    #pragma unroll
    for (int h = 0; h < 4; h++) sred[wid][h][lane] = racc[h];
    __syncthreads();
    int h = tid >> 6, m = tid & 63;
    int l = m >> 2, c = m & 3;
    float s = 0.f;
    #pragma unroll
    for (int w = 0; w < 8; w++) {
        s += ((const float*)&sred[w][h][l])[c];
        s += ((const float*)&sred[w][h][l + 16])[c];
    }
    ro_part[(size_t)(bc & 1)*B_*256 + (size_t)b*256 + h*64 + m] = s;
}

__global__ void sum_ro_kernel(const float* __restrict__ part, float* __restrict__ o_ro)
{
    int i = blockIdx.x*blockDim.x + threadIdx.x;
    o_ro[i] = part[i] + part[B_*256 + i];
}

// ---------------- Sweep 2: heads 2&3 update in place (half-warp float4, 4 rows) ----------------
__global__ void __launch_bounds__(256) sweep2_kernel(
    float* __restrict__ memio,
    const float* __restrict__ wwp)   // planes 2,3 used
{
    int bc = blockIdx.x; int b = bc >> 1; int nb = (bc & 1) << 10;
    int tid = threadIdx.x, wid = tid >> 5, lane = tid & 31;
    int hw = lane >> 4, l16 = lane & 15;

    const float* p2 = g_wp + ((size_t)2*B_ + b)*PW_;
    const float* p3 = g_wp + ((size_t)3*B_ + b)*PW_;
    float e2[4], a2[4], e3[4], a3[4];
    #pragma unroll
    for (int j = 0; j < 4; j++) {
        int m = l16*4 + j;
        e2[j] = sigmoidf(p2[70 + m]);  a2[j] = tanhf(p2[134 + m]);
        e3[j] = sigmoidf(p3[70 + m]);  a3[j] = tanhf(p3[134 + m]);
    }

    const size_t P = (size_t)B_*N_;
    for (int it = 0; it < 64; it += 4) {
        int r0 = it*16 + wid*2 + hw;
        size_t ix[4];
        float4 v[4];
        #pragma unroll
        for (int q = 0; q < 4; q++) {
            ix[q] = (size_t)b*N_ + nb + r0 + q*16;
            v[q] = *(const float4*)(memio + ix[q]*M_ + l16*4);
        }
        float w2[4], w3[4];
        #pragma unroll
        for (int q = 0; q < 4; q++) {
            w2[q] = wwp[2*P + ix[q]];
            w3[q] = wwp[3*P + ix[q]];
        }
        #pragma unroll
        for (int q = 0; q < 4; q++) {
            float vv[4] = {v[q].x, v[q].y, v[q].z, v[q].w};
            float tt[4];
            #pragma unroll
            for (int j = 0; j < 4; j++) {
                float uu = vv[j]*(1.f - w2[q]*e2[j]) + w2[q]*a2[j];
                tt[j]    = uu*(1.f - w3[q]*e3[j]) + w3[q]*a3[j];
            }
            *(float4*)(memio + ix[q]*M_ + l16*4) = make_float4(tt[0], tt[1], tt[2], tt[3]);
        }
    }
}

// ---------------- host launcher ----------------
extern "C" void kernel_launch(void* const* d_in, const int* in_sizes, int n_in,
                              void* d_out, int out_size)
{
    const float* ext    = (const float*)d_in[0];
    const float* pread  = (const float*)d_in[1];
    const float* prw    = (const float*)d_in[2];
    const float* pww    = (const float*)d_in[3];
    const float* mem    = (const float*)d_in[4];
    const float* ctrlW  = (const float*)d_in[5];
    const float* ctrlb  = (const float*)d_in[6];
    const float* readW  = (const float*)d_in[7];
    const float* readb  = (const float*)d_in[8];
    const float* writeW = (const float*)d_in[9];
    const float* writeb = (const float*)d_in[10];
    const float* outW   = (const float*)d_in[11];
    const float* outb   = (const float*)d_in[12];
    float* out = (float*)d_out;

    float *ctrl, *rp, *wp, *ropart;
    cudaGetSymbolAddress((void**)&ctrl,   g_ctrl);
    cudaGetSymbolAddress((void**)&rp,     g_rp);
    cudaGetSymbolAddress((void**)&wp,     g_wp);
    cudaGetSymbolAddress((void**)&ropart, g_ropart);

    float* o_mem = out + OUT_MEM;
    float* o_ro  = out + OUT_RO;
    float* o_rw  = out + OUT_RW;
    float* o_ww  = out + OUT_WW;
    const size_t P = (size_t)B_*N_;

    // Controller GEMM with fused concat
    gemm_cat_kernel<<<dim3(8, 8), 256>>>(ext, 256, pread, 256, ctrlW, ctrlb, ctrl, 512);

    // All 8 head parameter GEMMs in one launch
    gemm_heads_kernel<<<dim3(4, 8, 8), 256>>>(ctrl, readW, readb, rp, writeW, writeb, wp);

    // Pass A: norms + dots (reads + write head0) + head-1 base dots
    passA_kernel<<<512, 256>>>(mem);

    // Addressing for 4 read heads + write head 0 (fused)
    address5_kernel<<<dim3(256, 5), 256>>>(prw, pww, o_rw, o_ww);

    // Head 1: fused poly + addressing
    address_poly_kernel<<<256, 256>>>(0, 1, pww + P, o_ww, o_ww + P);

    // Sweep 1: reads einsum + heads 0&1 update + dot2/norm2 + head-3 bases
    sweep1_kernel<<<512, 256>>>(mem, o_mem, o_rw, o_ww, ropart);
    sum_ro_kernel<<<64, 1024>>>(ropart, o_ro);

    // Head 2: exact addressing; Head 3: fused poly + addressing
    address1_kernel<<<256, 256>>>(2, pww, o_ww);
    address_poly_kernel<<<256, 256>>>(2, 3, pww + 3*P, o_ww + 2*P, o_ww + 3*P);

    // Sweep 2: heads 2&3 update in place
    sweep2_kernel<<<512, 256>>>(o_mem, o_ww);

    // Output GEMM with fused concat
    gemm_cat_kernel<<<dim3(4, 8), 256>>>(ctrl, 512, o_ro, 256, outW, outb, out, 256);
}

// round 7
// speedup vs baseline: 1.0763x; 1.0763x over previous
#include <cuda_runtime.h>
#include <math.h>

// Problem constants
constexpr int B_  = 256;
constexpr int N_  = 2048;
constexpr int M_  = 64;
constexpr int C_  = 512;
constexpr int PR_ = 70;   // M + 3 + SHIFT
constexpr int PW_ = 198;  // PR + 2M
constexpr float EPSF = 1e-8f;

// Output layout (floats): ntm_out, memory, read_out, new_read_w, new_write_w
constexpr size_t OUT_MEM = 65536;
constexpr size_t OUT_RO  = 33619968;
constexpr size_t OUT_RW  = 33685504;
constexpr size_t OUT_WW  = 35782656;

// ---------------- device scratch (no allocations allowed) ----------------
__device__ float g_ctrl[B_*C_];
__device__ float g_rp  [4*B_*PR_];
__device__ float g_wp  [4*B_*PW_];
__device__ float g_dot [5*(size_t)B_*N_];
__device__ float g_norm[(size_t)B_*N_];
__device__ float g_base[6*(size_t)B_*N_];   // base dots: Da,Db,S1,S2,T0,T1
__device__ float g_ropart[2*B_*256];

__device__ __forceinline__ float softplusf(float x){ return x > 20.f ? x : log1pf(expf(x)); }
__device__ __forceinline__ float sigmoidf (float x){ return 1.f/(1.f+expf(-x)); }

// ---------------- GEMM body (round-5 proven version): tile 32x64, K-step 32 ----------------
__device__ __forceinline__ void gemm_body(
    const float* __restrict__ A0, int ca,
    const float* __restrict__ A1, int cb,
    const float* __restrict__ W, const float* __restrict__ bias,
    float* __restrict__ out, int Nc)
{
    int col0 = blockIdx.x * 64;
    if (col0 >= Nc) return;
    int row0 = blockIdx.y * 32;
    int K = ca + cb;

    __shared__ float As[32][33];
    __shared__ float Ws[32][64];
    int tid = threadIdx.x;
    int tx = tid & 15, ty = tid >> 4;
    float acc[2][4] = {};

    for (int k0 = 0; k0 < K; k0 += 32) {
        {
            int m  = tid >> 3;
            int kk = (tid & 7) * 4;
            int r = row0 + m, c = k0 + kk;
            float4 v;
            if (c < ca) v = *(const float4*)(A0 + (size_t)r*ca + c);
            else        v = *(const float4*)(A1 + (size_t)r*cb + (c - ca));
            As[m][kk] = v.x; As[m][kk+1] = v.y; As[m][kk+2] = v.z; As[m][kk+3] = v.w;
        }
        {
            int kk = tid >> 3;
            int n0 = (tid & 7) * 8;
            const float* wrow = W + (size_t)(k0 + kk)*Nc + col0 + n0;
            #pragma unroll
            for (int j = 0; j < 8; j++) {
                int gn = col0 + n0 + j;
                Ws[kk][n0 + j] = (gn < Nc) ? wrow[j] : 0.f;
            }
        }
        __syncthreads();
        #pragma unroll
        for (int kk = 0; kk < 32; kk++) {
            float a0 = As[ty*2 + 0][kk];
            float a1 = As[ty*2 + 1][kk];
            float4 w4 = *(const float4*)&Ws[kk][tx*4];
            acc[0][0] += a0*w4.x; acc[0][1] += a0*w4.y; acc[0][2] += a0*w4.z; acc[0][3] += a0*w4.w;
            acc[1][0] += a1*w4.x; acc[1][1] += a1*w4.y; acc[1][2] += a1*w4.z; acc[1][3] += a1*w4.w;
        }
        __syncthreads();
    }
    #pragma unroll
    for (int i = 0; i < 2; i++) {
        int gm = row0 + ty*2 + i;
        #pragma unroll
        for (int j = 0; j < 4; j++) {
            int gn = col0 + tx*4 + j;
            if (gn < Nc) out[(size_t)gm*Nc + gn] = acc[i][j] + bias[gn];
        }
    }
}

__global__ void gemm_cat_kernel(const float* __restrict__ A0, int ca,
                                const float* __restrict__ A1, int cb,
                                const float* __restrict__ W, const float* __restrict__ bias,
                                float* __restrict__ out, int Nc)
{
    gemm_body(A0, ca, A1, cb, W, bias, out, Nc);
}

__global__ void gemm_heads_kernel(const float* __restrict__ ctrl,
                                  const float* __restrict__ readW, const float* __restrict__ readb,
                                  float* __restrict__ rp,
                                  const float* __restrict__ writeW, const float* __restrict__ writeb,
                                  float* __restrict__ wp)
{
    int h = blockIdx.z;
    const float *W, *bias; float* out; int Nc;
    if (h < 4) {
        W = readW + (size_t)h*C_*PR_; bias = readb + h*PR_;
        out = rp + (size_t)h*B_*PR_;  Nc = PR_;
    } else {
        int g = h - 4;
        W = writeW + (size_t)g*C_*PW_; bias = writeb + g*PW_;
        out = wp + (size_t)g*B_*PW_;   Nc = PW_;
    }
    gemm_body(ctrl, C_, nullptr, 0, W, bias, out, Nc);
}

// ---------------- Pass A: mem norms + 5 key dots + head-1 base dots ----------------
// Half-warp (16 lanes, float4/lane) per row; 2-row unroll (MLP 4).
__global__ void __launch_bounds__(256) passA_kernel(const float* __restrict__ mem)
{
    int bc = blockIdx.x; int b = bc >> 1; int nb = (bc & 1) << 10;
    int tid = threadIdx.x, wid = tid >> 5, lane = tid & 31;
    int hw = lane >> 4, l16 = lane & 15;

    // Scalar key loads (key rows are NOT 16B aligned: PR_=70, PW_=198)
    float kk[5][4];
    #pragma unroll
    for (int h = 0; h < 5; h++) {
        const float* kp = (h < 4) ? (g_rp + ((size_t)h*B_ + b)*PR_) : (g_wp + (size_t)b*PW_);
        #pragma unroll
        for (int j = 0; j < 4; j++) kk[h][j] = kp[l16*4 + j];
    }
    // Head-0 erase/add + head-1 key, per-lane (4 m's each)
    const float* wp0 = g_wp + (size_t)b*PW_;
    const float* wp1 = g_wp + ((size_t)1*B_ + b)*PW_;
    float e0[4], a0[4], k1[4], e0sq[4], e0a0[4], e0k1[4];
    #pragma unroll
    for (int j = 0; j < 4; j++) {
        int m = l16*4 + j;
        e0[j] = sigmoidf(wp0[70 + m]);
        a0[j] = tanhf(wp0[134 + m]);
        k1[j] = wp1[m];
        e0sq[j] = e0[j]*e0[j];
        e0a0[j] = e0[j]*a0[j];
        e0k1[j] = e0[j]*k1[j];
    }

    const float* base = mem + ((size_t)b*N_ + nb)*M_;
    for (int it = 0; it < 64; it += 2) {
        int rA = it*16 + wid*2 + hw;
        int rB = rA + 16;
        float4 va = *(const float4*)(base + (size_t)rA*M_ + l16*4);
        float4 vb = *(const float4*)(base + (size_t)rB*M_ + l16*4);

        float v[4]  = {va.x, va.y, va.z, va.w};
        float u[4]  = {vb.x, vb.y, vb.z, vb.w};
        float accA[12] = {}, accB[12] = {};
        #pragma unroll
        for (int j = 0; j < 4; j++) {
            float vj = v[j], uj = u[j];
            float vs = vj*vj, us = uj*uj;
            accA[0] += vs;               accB[0] += us;                 // norm^2
            #pragma unroll
            for (int h = 0; h < 5; h++) {
                accA[1+h] += vj*kk[h][j];
                accB[1+h] += uj*kk[h][j];
            }
            accA[6]  += vj*k1[j];        accB[6]  += uj*k1[j];          // Da
            accA[7]  += vj*e0k1[j];      accB[7]  += uj*e0k1[j];        // Db
            accA[8]  += vs*e0[j];        accB[8]  += us*e0[j];          // S1
            accA[9]  += vs*e0sq[j];      accB[9]  += us*e0sq[j];        // S2
            accA[10] += vj*a0[j];        accB[10] += uj*a0[j];          // T0
            accA[11] += vj*e0a0[j];      accB[11] += uj*e0a0[j];        // T1
        }
        #pragma unroll
        for (int o = 8; o > 0; o >>= 1) {
            #pragma unroll
            for (int r = 0; r < 12; r++) {
                accA[r] += __shfl_xor_sync(0xffffffffu, accA[r], o);
                accB[r] += __shfl_xor_sync(0xffffffffu, accB[r], o);
            }
        }
        if (l16 == 0) {
            size_t ixA = (size_t)b*N_ + nb + rA;
            size_t ixB = (size_t)b*N_ + nb + rB;
            g_norm[ixA] = sqrtf(accA[0]);
            g_norm[ixB] = sqrtf(accB[0]);
            #pragma unroll
            for (int h = 0; h < 5; h++) {
                g_dot[(size_t)h*B_*N_ + ixA] = accA[1+h];
                g_dot[(size_t)h*B_*N_ + ixB] = accB[1+h];
            }
            #pragma unroll
            for (int r = 0; r < 6; r++) {
                g_base[(size_t)r*B_*N_ + ixA] = accA[6+r];
                g_base[(size_t)r*B_*N_ + ixB] = accB[6+r];
            }
        }
    }
}

// ---------------- block reduction helpers (256 threads) ----------------
__device__ __forceinline__ float block_reduce_sum(float v, float* sbuf)
{
    int tid = threadIdx.x;
    #pragma unroll
    for (int o = 16; o > 0; o >>= 1) v += __shfl_xor_sync(0xffffffffu, v, o);
    if ((tid & 31) == 0) sbuf[tid >> 5] = v;
    __syncthreads();
    if (tid < 32) {
        float x = (tid < 8) ? sbuf[tid] : 0.f;
        #pragma unroll
        for (int o = 4; o > 0; o >>= 1) x += __shfl_xor_sync(0xffffffffu, x, o);
        if (tid == 0) sbuf[0] = x;
    }
    __syncthreads();
    float r = sbuf[0];
    __syncthreads();
    return r;
}

__device__ __forceinline__ float block_reduce_max(float v, float* sbuf)
{
    int tid = threadIdx.x;
    #pragma unroll
    for (int o = 16; o > 0; o >>= 1) v = fmaxf(v, __shfl_xor_sync(0xffffffffu, v, o));
    if ((tid & 31) == 0) sbuf[tid >> 5] = v;
    __syncthreads();
    if (tid < 32) {
        float x = (tid < 8) ? sbuf[tid] : -3.4e38f;
        #pragma unroll
        for (int o = 4; o > 0; o >>= 1) x = fmaxf(x, __shfl_xor_sync(0xffffffffu, x, o));
        if (tid == 0) sbuf[0] = x;
    }
    __syncthreads();
    float r = sbuf[0];
    __syncthreads();
    return r;
}

// ---------------- addressing tail (after per-n scaled-cos values x[8] are built) --------------
__device__ __forceinline__ void address_tail(
    float* x, float g, float s0, float s1, float s2, float gamma,
    const float* __restrict__ wpb, float* __restrict__ woutb,
    float* wg, float* rbuf)
{
    int tid = threadIdx.x;
    float mx = -3.4e38f;
    #pragma unroll
    for (int i = 0; i < 8; i++) mx = fmaxf(mx, x[i]);
    float bmax = block_reduce_max(mx, rbuf);
    float lsum = 0.f;
    #pragma unroll
    for (int i = 0; i < 8; i++) {
        float e = __expf(x[i] - bmax);
        wg[tid + i*256] = e;
        lsum += e;
    }
    float bsum = block_reduce_sum(lsum, rbuf);
    float inv = 1.f / bsum;
    #pragma unroll
    for (int i = 0; i < 8; i++) {
        int n = tid + i*256;
        wg[n] = g * (wg[n]*inv) + (1.f-g) * wpb[n];
    }
    __syncthreads();
    float wpow[8];
    lsum = 0.f;
    #pragma unroll
    for (int i = 0; i < 8; i++) {
        int n = tid + i*256;
        float ws = s0*wg[(n+1)&(N_-1)] + s1*wg[n] + s2*wg[(n-1)&(N_-1)];
        float t = __powf(ws + EPSF, gamma);
        wpow[i] = t;
        lsum += t;
    }
    float psum = block_reduce_sum(lsum, rbuf);
    float ip = 1.f / psum;
    #pragma unroll
    for (int i = 0; i < 8; i++)
        woutb[tid + i*256] = wpow[i]*ip;
}

// ---------------- NTM addressing body (dot/norm from planes) ----------------
__device__ __forceinline__ void address_body(
    const float* __restrict__ p,
    const float* __restrict__ dotb,
    const float* __restrict__ nrmb,
    const float* __restrict__ wpb,
    float* __restrict__ woutb)
{
    int tid = threadIdx.x;
    __shared__ float wg[2048];
    __shared__ float rbuf[32];
    __shared__ float sc[7];

    float kv = 0.f;
    if (tid < 64) { float x = p[tid]; kv = x*x; }
    float ksum = block_reduce_sum(kv, rbuf);
    if (tid == 0) {
        sc[0] = sqrtf(ksum);
        sc[1] = softplusf(p[64]);
        sc[2] = sigmoidf(p[65]);
        float a0 = p[66], a1 = p[67], a2 = p[68];
        float mx = fmaxf(a0, fmaxf(a1, a2));
        float e0 = expf(a0-mx), e1 = expf(a1-mx), e2 = expf(a2-mx);
        float es = e0 + e1 + e2;
        sc[3] = e0/es; sc[4] = e1/es; sc[5] = e2/es;
        sc[6] = 1.f + softplusf(p[69]);
    }
    __syncthreads();
    float knorm = sc[0], beta = sc[1], g = sc[2];
    float s0 = sc[3], s1 = sc[4], s2 = sc[5], gamma = sc[6];

    float x[8];
    #pragma unroll
    for (int i = 0; i < 8; i++) {
        int n = tid + i*256;
        float cosv = dotb[n] / (nrmb[n]*knorm + EPSF);
        x[i] = beta * cosv;
    }
    address_tail(x, g, s0, s1, s2, gamma, wpb, woutb, wg, rbuf);
}

__global__ void address5_kernel(const float* __restrict__ prw,
                                const float* __restrict__ pww,
                                float* __restrict__ o_rw,
                                float* __restrict__ o_ww)
{
    int b = blockIdx.x, h = blockIdx.y;
    const float *p, *dotp, *wprev; float* wout;
    if (h < 4) {
        p     = g_rp + ((size_t)h*B_ + b)*PR_;
        dotp  = g_dot + (size_t)h*B_*N_ + (size_t)b*N_;
        wprev = prw  + (size_t)h*B_*N_ + (size_t)b*N_;
        wout  = o_rw + (size_t)h*B_*N_ + (size_t)b*N_;
    } else {
        p     = g_wp + (size_t)b*PW_;
        dotp  = g_dot + (size_t)4*B_*N_ + (size_t)b*N_;
        wprev = pww  + (size_t)b*N_;
        wout  = o_ww + (size_t)b*N_;
    }
    address_body(p, dotp, g_norm + (size_t)b*N_, wprev, wout);
}

// exact-plane addressing for write head h (head 2)
__global__ void address1_kernel(int h,
                                const float* __restrict__ pww,
                                float* __restrict__ o_ww)
{
    int b = blockIdx.x;
    address_body(g_wp + ((size_t)h*B_ + b)*PW_,
                 g_dot + (size_t)4*B_*N_ + (size_t)b*N_,
                 g_norm + (size_t)b*N_,
                 pww  + (size_t)h*B_*N_ + (size_t)b*N_,
                 o_ww + (size_t)h*B_*N_ + (size_t)b*N_);
}

// ---------------- fused poly + addressing for write heads 1,3 ----------------
// dot/norm computed inline from base dots + new weight of the previous head.
__global__ void address_poly_kernel(int he, int hk,
                                    const float* __restrict__ wprev,  // past_write_w plane hk
                                    const float* __restrict__ wdone,  // new write w plane he
                                    float* __restrict__ wout)         // new write w plane hk
{
    int b = blockIdx.x, tid = threadIdx.x;
    __shared__ float wg[2048];
    __shared__ float rbuf[32];
    __shared__ float sc[9];

    const float* pe = g_wp + ((size_t)he*B_ + b)*PW_;
    const float* p  = g_wp + ((size_t)hk*B_ + b)*PW_;

    float kv = 0.f, c1 = 0.f, c2 = 0.f;
    if (tid < 64) {
        float k = p[tid];
        float a = tanhf(pe[134 + tid]);
        kv = k*k; c1 = a*k; c2 = a*a;
    }
    float ksum = block_reduce_sum(kv, rbuf);
    float Cc   = block_reduce_sum(c1, rbuf);
    float U    = block_reduce_sum(c2, rbuf);
    if (tid == 0) {
        sc[0] = sqrtf(ksum);
        sc[1] = softplusf(p[64]);
        sc[2] = sigmoidf(p[65]);
        float a0 = p[66], a1 = p[67], a2 = p[68];
        float mx = fmaxf(a0, fmaxf(a1, a2));
        float e0 = expf(a0-mx), e1 = expf(a1-mx), e2 = expf(a2-mx);
        float es = e0 + e1 + e2;
        sc[3] = e0/es; sc[4] = e1/es; sc[5] = e2/es;
        sc[6] = 1.f + softplusf(p[69]);
        sc[7] = Cc; sc[8] = U;
    }
    __syncthreads();
    float knorm = sc[0], beta = sc[1], g = sc[2];
    float s0 = sc[3], s1 = sc[4], s2 = sc[5], gamma = sc[6];
    float CC = sc[7], UU = sc[8];

    size_t base = (size_t)b*N_;
    const size_t P = (size_t)B_*N_;
    const float* nrmp = g_norm + base;

    float x[8];
    #pragma unroll
    for (int i = 0; i < 8; i++) {
        int n = tid + i*256;
        float w  = wdone[base + n];
        float Da = g_base[0*P + base + n];
        float Db = g_base[1*P + base + n];
        float S1 = g_base[2*P + base + n];
        float S2 = g_base[3*P + base + n];
        float T0 = g_base[4*P + base + n];
        float T1 = g_base[5*P + base + n];
        float nr = nrmp[n];
        float S0 = nr*nr;
        float dotv = Da - w*Db + w*CC;
        float w2 = w*w;
        float nsq = S0 - 2.f*w*S1 + w2*S2 + 2.f*w*T0 - 2.f*w2*T1 + w2*UU;
        float nn = sqrtf(fmaxf(nsq, 0.f));
        x[i] = beta * (dotv / (nn*knorm + EPSF));
    }
    address_tail(x, g, s0, s1, s2, gamma, wprev + base, wout + base, wg, rbuf);
}

// ---------------- Sweep 1: reads einsum + heads 0&1 update + dot2/norm2 + head-3 bases ---------
__global__ void __launch_bounds__(256) sweep1_kernel(
    const float* __restrict__ mem_in, float* __restrict__ mem_out,
    const float* __restrict__ wr,    // new_read_w [4][B][N]
    const float* __restrict__ wwp,   // new_write_w planes (0,1 used)
    float* __restrict__ ro_part)
{
    int bc = blockIdx.x; int b = bc >> 1; int nb = (bc & 1) << 10;
    int tid = threadIdx.x, wid = tid >> 5, lane = tid & 31;
    int hw = lane >> 4, l16 = lane & 15;

    __shared__ float4 sred[8][4][32];

    const float* p0 = g_wp + (size_t)b*PW_;
    const float* p1 = g_wp + ((size_t)1*B_ + b)*PW_;
    const float* p2 = g_wp + ((size_t)2*B_ + b)*PW_;
    const float* p3 = g_wp + ((size_t)3*B_ + b)*PW_;
    float e0[4], a0[4], e1[4], a1[4], k2[4], e2[4], a2[4], k3[4];
    float e2k3[4], e2sq[4], e2a2[4];
    #pragma unroll
    for (int j = 0; j < 4; j++) {
        int m = l16*4 + j;
        e0[j] = sigmoidf(p0[70 + m]);  a0[j] = tanhf(p0[134 + m]);
        e1[j] = sigmoidf(p1[70 + m]);  a1[j] = tanhf(p1[134 + m]);
        k2[j] = p2[m];
        e2[j] = sigmoidf(p2[70 + m]);  a2[j] = tanhf(p2[134 + m]);
        k3[j] = p3[m];
        e2k3[j] = e2[j]*k3[j];
        e2sq[j] = e2[j]*e2[j];
        e2a2[j] = e2[j]*a2[j];
    }

    float4 racc[4] = {{0,0,0,0},{0,0,0,0},{0,0,0,0},{0,0,0,0}};
    const size_t P = (size_t)B_*N_;
    float* dot2p = g_dot + 4*P;

    for (int it = 0; it < 64; it += 2) {
        int rA = it*16 + wid*2 + hw;
        int rB = rA + 16;
        size_t ixA = (size_t)b*N_ + nb + rA;
        size_t ixB = (size_t)b*N_ + nb + rB;

        float4 va = *(const float4*)(mem_in + ixA*M_ + l16*4);
        float4 vb = *(const float4*)(mem_in + ixB*M_ + l16*4);
        float w0A = wwp[ixA],     w0B = wwp[ixB];
        float w1A = wwp[P + ixA], w1B = wwp[P + ixB];
        float wvA[4], wvB[4];
        #pragma unroll
        for (int h = 0; h < 4; h++) {
            wvA[h] = wr[(size_t)h*P + ixA];
            wvB[h] = wr[(size_t)h*P + ixB];
        }

        float v[4]  = {va.x, va.y, va.z, va.w};
        float u[4]  = {vb.x, vb.y, vb.z, vb.w};
        float m2A[4], m2B[4];
        float accA[8] = {}, accB[8] = {};
        #pragma unroll
        for (int j = 0; j < 4; j++) {
            float m1a = v[j]*(1.f - w0A*e0[j]) + w0A*a0[j];
            float m1b = u[j]*(1.f - w0B*e0[j]) + w0B*a0[j];
            float m2a = m1a*(1.f - w1A*e1[j]) + w1A*a1[j];
            float m2b = m1b*(1.f - w1B*e1[j]) + w1B*a1[j];
            m2A[j] = m2a; m2B[j] = m2b;
            float sa = m2a*m2a, sb = m2b*m2b;
            accA[0] += m2a*k2[j];    accB[0] += m2b*k2[j];    // dot2
            accA[1] += sa;           accB[1] += sb;           // norm2^2
            accA[2] += m2a*k3[j];    accB[2] += m2b*k3[j];    // Da
            accA[3] += m2a*e2k3[j];  accB[3] += m2b*e2k3[j];  // Db
            accA[4] += sa*e2[j];     accB[4] += sb*e2[j];     // S1
            accA[5] += sa*e2sq[j];   accB[5] += sb*e2sq[j];   // S2
            accA[6] += m2a*a2[j];    accB[6] += m2b*a2[j];    // T0
            accA[7] += m2a*e2a2[j];  accB[7] += m2b*e2a2[j];  // T1
        }
        #pragma unroll
        for (int h = 0; h < 4; h++) {
            racc[h].x += wvA[h]*v[0] + wvB[h]*u[0];
            racc[h].y += wvA[h]*v[1] + wvB[h]*u[1];
            racc[h].z += wvA[h]*v[2] + wvB[h]*u[2];
            racc[h].w += wvA[h]*v[3] + wvB[h]*u[3];
        }

        *(float4*)(mem_out + ixA*M_ + l16*4) = make_float4(m2A[0], m2A[1], m2A[2], m2A[3]);
        *(float4*)(mem_out + ixB*M_ + l16*4) = make_float4(m2B[0], m2B[1], m2B[2], m2B[3]);

        #pragma unroll
        for (int o = 8; o > 0; o >>= 1) {
            #pragma unroll
            for (int r = 0; r < 8; r++) {
                accA[r] += __shfl_xor_sync(0xffffffffu, accA[r], o);
                accB[r] += __shfl_xor_sync(0xffffffffu, accB[r], o);
            }
        }
        if (l16 == 0) {
            dot2p[ixA] = accA[0];            dot2p[ixB] = accB[0];
            g_norm[ixA] = sqrtf(accA[1]);    g_norm[ixB] = sqrtf(accB[1]);
            #pragma unroll
            for (int r = 0; r < 6; r++) {
                g_base[(size_t)r*P + ixA] = accA[2+r];
                g_base[(size_t)r*P + ixB] = accB[2+r];
            }
        }
    }

    #pragma unroll
    for (int h = 0; h < 4; h++) sred[wid][h][lane] = racc[h];
    __syncthreads();
    int h = tid >> 6, m = tid & 63;
    int l = m >> 2, c = m & 3;
    float s = 0.f;
    #pragma unroll
    for (int w = 0; w < 8; w++) {
        s += ((const float*)&sred[w][h][l])[c];
        s += ((const float*)&sred[w][h][l + 16])[c];
    }
    ro_part[(size_t)(bc & 1)*B_*256 + (size_t)b*256 + h*64 + m] = s;
}

__global__ void sum_ro_kernel(const float* __restrict__ part, float* __restrict__ o_ro)
{
    int i = blockIdx.x*blockDim.x + threadIdx.x;
    o_ro[i] = part[i] + part[B_*256 + i];
}

// ---------------- Sweep 2: heads 2&3 update in place (half-warp float4, 4 rows) ----------------
__global__ void __launch_bounds__(256) sweep2_kernel(
    float* __restrict__ memio,
    const float* __restrict__ wwp)   // planes 2,3 used
{
    int bc = blockIdx.x; int b = bc >> 1; int nb = (bc & 1) << 10;
    int tid = threadIdx.x, wid = tid >> 5, lane = tid & 31;
    int hw = lane >> 4, l16 = lane & 15;

    const float* p2 = g_wp + ((size_t)2*B_ + b)*PW_;
    const float* p3 = g_wp + ((size_t)3*B_ + b)*PW_;
    float e2[4], a2[4], e3[4], a3[4];
    #pragma unroll
    for (int j = 0; j < 4; j++) {
        int m = l16*4 + j;
        e2[j] = sigmoidf(p2[70 + m]);  a2[j] = tanhf(p2[134 + m]);
        e3[j] = sigmoidf(p3[70 + m]);  a3[j] = tanhf(p3[134 + m]);
    }

    const size_t P = (size_t)B_*N_;
    for (int it = 0; it < 64; it += 4) {
        int r0 = it*16 + wid*2 + hw;
        size_t ix[4];
        float4 v[4];
        #pragma unroll
        for (int q = 0; q < 4; q++) {
            ix[q] = (size_t)b*N_ + nb + r0 + q*16;
            v[q] = *(const float4*)(memio + ix[q]*M_ + l16*4);
        }
        float w2[4], w3[4];
        #pragma unroll
        for (int q = 0; q < 4; q++) {
            w2[q] = wwp[2*P + ix[q]];
            w3[q] = wwp[3*P + ix[q]];
        }
        #pragma unroll
        for (int q = 0; q < 4; q++) {
            float vv[4] = {v[q].x, v[q].y, v[q].z, v[q].w};
            float tt[4];
            #pragma unroll
            for (int j = 0; j < 4; j++) {
                float uu = vv[j]*(1.f - w2[q]*e2[j]) + w2[q]*a2[j];
                tt[j]    = uu*(1.f - w3[q]*e3[j]) + w3[q]*a3[j];
            }
            *(float4*)(memio + ix[q]*M_ + l16*4) = make_float4(tt[0], tt[1], tt[2], tt[3]);
        }
    }
}

// ---------------- host launcher ----------------
extern "C" void kernel_launch(void* const* d_in, const int* in_sizes, int n_in,
                              void* d_out, int out_size)
{
    const float* ext    = (const float*)d_in[0];
    const float* pread  = (const float*)d_in[1];
    const float* prw    = (const float*)d_in[2];
    const float* pww    = (const float*)d_in[3];
    const float* mem    = (const float*)d_in[4];
    const float* ctrlW  = (const float*)d_in[5];
    const float* ctrlb  = (const float*)d_in[6];
    const float* readW  = (const float*)d_in[7];
    const float* readb  = (const float*)d_in[8];
    const float* writeW = (const float*)d_in[9];
    const float* writeb = (const float*)d_in[10];
    const float* outW   = (const float*)d_in[11];
    const float* outb   = (const float*)d_in[12];
    float* out = (float*)d_out;

    float *ctrl, *rp, *wp, *ropart;
    cudaGetSymbolAddress((void**)&ctrl,   g_ctrl);
    cudaGetSymbolAddress((void**)&rp,     g_rp);
    cudaGetSymbolAddress((void**)&wp,     g_wp);
    cudaGetSymbolAddress((void**)&ropart, g_ropart);

    float* o_mem = out + OUT_MEM;
    float* o_ro  = out + OUT_RO;
    float* o_rw  = out + OUT_RW;
    float* o_ww  = out + OUT_WW;
    const size_t P = (size_t)B_*N_;

    // Controller GEMM with fused concat
    gemm_cat_kernel<<<dim3(8, 8), 256>>>(ext, 256, pread, 256, ctrlW, ctrlb, ctrl, 512);

    // All 8 head parameter GEMMs in one launch
    gemm_heads_kernel<<<dim3(4, 8, 8), 256>>>(ctrl, readW, readb, rp, writeW, writeb, wp);

    // Pass A: norms + dots (reads + write head0) + head-1 base dots
    passA_kernel<<<512, 256>>>(mem);

    // Addressing for 4 read heads + write head 0 (fused)
    address5_kernel<<<dim3(256, 5), 256>>>(prw, pww, o_rw, o_ww);

    // Head 1: fused poly + addressing
    address_poly_kernel<<<256, 256>>>(0, 1, pww + P, o_ww, o_ww + P);

    // Sweep 1: reads einsum + heads 0&1 update + dot2/norm2 + head-3 bases
    sweep1_kernel<<<512, 256>>>(mem, o_mem, o_rw, o_ww, ropart);
    sum_ro_kernel<<<64, 1024>>>(ropart, o_ro);

    // Head 2: exact addressing; Head 3: fused poly + addressing
    address1_kernel<<<256, 256>>>(2, pww, o_ww);
    address_poly_kernel<<<256, 256>>>(2, 3, pww + 3*P, o_ww + 2*P, o_ww + 3*P);

    // Sweep 2: heads 2&3 update in place
    sweep2_kernel<<<512, 256>>>(o_mem, o_ww);

    // Output GEMM with fused concat
    gemm_cat_kernel<<<dim3(4, 8), 256>>>(ctrl, 512, o_ro, 256, outW, outb, out, 256);
}

// round 8
// speedup vs baseline: 1.1064x; 1.0279x over previous
#include <cuda_runtime.h>
#include <math.h>

// Problem constants
constexpr int B_  = 256;
constexpr int N_  = 2048;
constexpr int M_  = 64;
constexpr int C_  = 512;
constexpr int PR_ = 70;   // M + 3 + SHIFT
constexpr int PW_ = 198;  // PR + 2M
constexpr float EPSF = 1e-8f;

// Output layout (floats): ntm_out, memory, read_out, new_read_w, new_write_w
constexpr size_t OUT_MEM = 65536;
constexpr size_t OUT_RO  = 33619968;
constexpr size_t OUT_RW  = 33685504;
constexpr size_t OUT_WW  = 35782656;

// ---------------- device scratch ----------------
__device__ float g_ctrl[B_*C_];
__device__ float g_rp  [4*B_*PR_];
__device__ float g_wp  [4*B_*PW_];
__device__ float g_dot [5*(size_t)B_*N_];
__device__ float g_norm[(size_t)B_*N_];
__device__ float g_base[6*(size_t)B_*N_];   // base dots: Da,Db,S1,S2,T0,T1
__device__ float g_ropart[2*B_*256];

__device__ __forceinline__ float softplusf(float x){ return x > 20.f ? x : log1pf(expf(x)); }
__device__ __forceinline__ float sigmoidf (float x){ return 1.f/(1.f+expf(-x)); }

// ---------------- GEMM body (proven round-5 version): tile 32x64, K-step 32 ----------------
__device__ __forceinline__ void gemm_body(
    const float* __restrict__ A0, int ca,
    const float* __restrict__ A1, int cb,
    const float* __restrict__ W, const float* __restrict__ bias,
    float* __restrict__ out, int Nc)
{
    int col0 = blockIdx.x * 64;
    if (col0 >= Nc) return;
    int row0 = blockIdx.y * 32;
    int K = ca + cb;

    __shared__ float As[32][33];
    __shared__ float Ws[32][64];
    int tid = threadIdx.x;
    int tx = tid & 15, ty = tid >> 4;
    float acc[2][4] = {};

    for (int k0 = 0; k0 < K; k0 += 32) {
        {
            int m  = tid >> 3;
            int kk = (tid & 7) * 4;
            int r = row0 + m, c = k0 + kk;
            float4 v;
            if (c < ca) v = *(const float4*)(A0 + (size_t)r*ca + c);
            else        v = *(const float4*)(A1 + (size_t)r*cb + (c - ca));
            As[m][kk] = v.x; As[m][kk+1] = v.y; As[m][kk+2] = v.z; As[m][kk+3] = v.w;
        }
        {
            int kk = tid >> 3;
            int n0 = (tid & 7) * 8;
            const float* wrow = W + (size_t)(k0 + kk)*Nc + col0 + n0;
            #pragma unroll
            for (int j = 0; j < 8; j++) {
                int gn = col0 + n0 + j;
                Ws[kk][n0 + j] = (gn < Nc) ? wrow[j] : 0.f;
            }
        }
        __syncthreads();
        #pragma unroll
        for (int kk = 0; kk < 32; kk++) {
            float a0 = As[ty*2 + 0][kk];
            float a1 = As[ty*2 + 1][kk];
            float4 w4 = *(const float4*)&Ws[kk][tx*4];
            acc[0][0] += a0*w4.x; acc[0][1] += a0*w4.y; acc[0][2] += a0*w4.z; acc[0][3] += a0*w4.w;
            acc[1][0] += a1*w4.x; acc[1][1] += a1*w4.y; acc[1][2] += a1*w4.z; acc[1][3] += a1*w4.w;
        }
        __syncthreads();
    }
    #pragma unroll
    for (int i = 0; i < 2; i++) {
        int gm = row0 + ty*2 + i;
        #pragma unroll
        for (int j = 0; j < 4; j++) {
            int gn = col0 + tx*4 + j;
            if (gn < Nc) out[(size_t)gm*Nc + gn] = acc[i][j] + bias[gn];
        }
    }
}

__global__ void gemm_cat_kernel(const float* __restrict__ A0, int ca,
                                const float* __restrict__ A1, int cb,
                                const float* __restrict__ W, const float* __restrict__ bias,
                                float* __restrict__ out, int Nc)
{
    gemm_body(A0, ca, A1, cb, W, bias, out, Nc);
}

__global__ void gemm_heads_kernel(const float* __restrict__ ctrl,
                                  const float* __restrict__ readW, const float* __restrict__ readb,
                                  float* __restrict__ rp,
                                  const float* __restrict__ writeW, const float* __restrict__ writeb,
                                  float* __restrict__ wp)
{
    int h = blockIdx.z;
    const float *W, *bias; float* out; int Nc;
    if (h < 4) {
        W = readW + (size_t)h*C_*PR_; bias = readb + h*PR_;
        out = rp + (size_t)h*B_*PR_;  Nc = PR_;
    } else {
        int g = h - 4;
        W = writeW + (size_t)g*C_*PW_; bias = writeb + g*PW_;
        out = wp + (size_t)g*B_*PW_;   Nc = PW_;
    }
    gemm_body(ctrl, C_, nullptr, 0, W, bias, out, Nc);
}

// ---------------- Pass A: mem norms + 5 key dots + head-1 base dots ----------------
__global__ void __launch_bounds__(256) passA_kernel(const float* __restrict__ mem)
{
    int bc = blockIdx.x; int b = bc >> 1; int nb = (bc & 1) << 10;
    int tid = threadIdx.x, wid = tid >> 5, lane = tid & 31;
    int hw = lane >> 4, l16 = lane & 15;

    float kk[5][4];
    #pragma unroll
    for (int h = 0; h < 5; h++) {
        const float* kp = (h < 4) ? (g_rp + ((size_t)h*B_ + b)*PR_) : (g_wp + (size_t)b*PW_);
        #pragma unroll
        for (int j = 0; j < 4; j++) kk[h][j] = kp[l16*4 + j];
    }
    const float* wp0 = g_wp + (size_t)b*PW_;
    const float* wp1 = g_wp + ((size_t)1*B_ + b)*PW_;
    float e0[4], a0[4], k1[4], e0sq[4], e0a0[4], e0k1[4];
    #pragma unroll
    for (int j = 0; j < 4; j++) {
        int m = l16*4 + j;
        e0[j] = sigmoidf(wp0[70 + m]);
        a0[j] = tanhf(wp0[134 + m]);
        k1[j] = wp1[m];
        e0sq[j] = e0[j]*e0[j];
        e0a0[j] = e0[j]*a0[j];
        e0k1[j] = e0[j]*k1[j];
    }

    const float* base = mem + ((size_t)b*N_ + nb)*M_;
    for (int it = 0; it < 64; it += 2) {
        int rA = it*16 + wid*2 + hw;
        int rB = rA + 16;
        float4 va = *(const float4*)(base + (size_t)rA*M_ + l16*4);
        float4 vb = *(const float4*)(base + (size_t)rB*M_ + l16*4);

        float v[4]  = {va.x, va.y, va.z, va.w};
        float u[4]  = {vb.x, vb.y, vb.z, vb.w};
        float accA[12] = {}, accB[12] = {};
        #pragma unroll
        for (int j = 0; j < 4; j++) {
            float vj = v[j], uj = u[j];
            float vs = vj*vj, us = uj*uj;
            accA[0] += vs;               accB[0] += us;
            #pragma unroll
            for (int h = 0; h < 5; h++) {
                accA[1+h] += vj*kk[h][j];
                accB[1+h] += uj*kk[h][j];
            }
            accA[6]  += vj*k1[j];        accB[6]  += uj*k1[j];
            accA[7]  += vj*e0k1[j];      accB[7]  += uj*e0k1[j];
            accA[8]  += vs*e0[j];        accB[8]  += us*e0[j];
            accA[9]  += vs*e0sq[j];      accB[9]  += us*e0sq[j];
            accA[10] += vj*a0[j];        accB[10] += uj*a0[j];
            accA[11] += vj*e0a0[j];      accB[11] += uj*e0a0[j];
        }
        #pragma unroll
        for (int o = 8; o > 0; o >>= 1) {
            #pragma unroll
            for (int r = 0; r < 12; r++) {
                accA[r] += __shfl_xor_sync(0xffffffffu, accA[r], o);
                accB[r] += __shfl_xor_sync(0xffffffffu, accB[r], o);
            }
        }
        if (l16 == 0) {
            size_t ixA = (size_t)b*N_ + nb + rA;
            size_t ixB = (size_t)b*N_ + nb + rB;
            g_norm[ixA] = sqrtf(accA[0]);
            g_norm[ixB] = sqrtf(accB[0]);
            #pragma unroll
            for (int h = 0; h < 5; h++) {
                g_dot[(size_t)h*B_*N_ + ixA] = accA[1+h];
                g_dot[(size_t)h*B_*N_ + ixB] = accB[1+h];
            }
            #pragma unroll
            for (int r = 0; r < 6; r++) {
                g_base[(size_t)r*B_*N_ + ixA] = accA[6+r];
                g_base[(size_t)r*B_*N_ + ixB] = accB[6+r];
            }
        }
    }
}

// ---------------- block reduction helpers (256 threads) ----------------
__device__ __forceinline__ float block_reduce_sum(float v, float* sbuf)
{
    int tid = threadIdx.x;
    #pragma unroll
    for (int o = 16; o > 0; o >>= 1) v += __shfl_xor_sync(0xffffffffu, v, o);
    if ((tid & 31) == 0) sbuf[tid >> 5] = v;
    __syncthreads();
    if (tid < 32) {
        float x = (tid < 8) ? sbuf[tid] : 0.f;
        #pragma unroll
        for (int o = 4; o > 0; o >>= 1) x += __shfl_xor_sync(0xffffffffu, x, o);
        if (tid == 0) sbuf[0] = x;
    }
    __syncthreads();
    float r = sbuf[0];
    __syncthreads();
    return r;
}

__device__ __forceinline__ float block_reduce_max(float v, float* sbuf)
{
    int tid = threadIdx.x;
    #pragma unroll
    for (int o = 16; o > 0; o >>= 1) v = fmaxf(v, __shfl_xor_sync(0xffffffffu, v, o));
    if ((tid & 31) == 0) sbuf[tid >> 5] = v;
    __syncthreads();
    if (tid < 32) {
        float x = (tid < 8) ? sbuf[tid] : -3.4e38f;
        #pragma unroll
        for (int o = 4; o > 0; o >>= 1) x = fmaxf(x, __shfl_xor_sync(0xffffffffu, x, o));
        if (tid == 0) sbuf[0] = x;
    }
    __syncthreads();
    float r = sbuf[0];
    __syncthreads();
    return r;
}

// ---------------- addressing tail: consumes x = beta*cos, leaves final w in x ----------------
__device__ __forceinline__ void address_tail(
    float* x, float g, float s0, float s1, float s2, float gamma,
    const float* __restrict__ wpb, float* __restrict__ woutb,
    float* wg, float* rbuf)
{
    int tid = threadIdx.x;
    float mx = -3.4e38f;
    #pragma unroll
    for (int i = 0; i < 8; i++) mx = fmaxf(mx, x[i]);
    float bmax = block_reduce_max(mx, rbuf);
    float lsum = 0.f;
    #pragma unroll
    for (int i = 0; i < 8; i++) {
        float e = __expf(x[i] - bmax);
        wg[tid + i*256] = e;
        lsum += e;
    }
    float bsum = block_reduce_sum(lsum, rbuf);
    float inv = 1.f / bsum;
    #pragma unroll
    for (int i = 0; i < 8; i++) {
        int n = tid + i*256;
        wg[n] = g * (wg[n]*inv) + (1.f-g) * wpb[n];
    }
    __syncthreads();
    float wpow[8];
    lsum = 0.f;
    #pragma unroll
    for (int i = 0; i < 8; i++) {
        int n = tid + i*256;
        float ws = s0*wg[(n+1)&(N_-1)] + s1*wg[n] + s2*wg[(n-1)&(N_-1)];
        float t = __powf(ws + EPSF, gamma);
        wpow[i] = t;
        lsum += t;
    }
    float psum = block_reduce_sum(lsum, rbuf);
    float ip = 1.f / psum;
    #pragma unroll
    for (int i = 0; i < 8; i++) {
        float wv = wpow[i]*ip;
        woutb[tid + i*256] = wv;
        x[i] = wv;
    }
}

// scalars: sc[0]=knorm sc[1]=beta sc[2]=g sc[3..5]=s sc[6]=gamma (call from tid==0)
__device__ __forceinline__ void head_scalars(const float* __restrict__ p, float ksum, float* sc)
{
    sc[0] = sqrtf(ksum);
    sc[1] = softplusf(p[64]);
    sc[2] = sigmoidf(p[65]);
    float a0 = p[66], a1 = p[67], a2 = p[68];
    float mx = fmaxf(a0, fmaxf(a1, a2));
    float e0 = expf(a0-mx), e1 = expf(a1-mx), e2 = expf(a2-mx);
    float es = e0 + e1 + e2;
    sc[3] = e0/es; sc[4] = e1/es; sc[5] = e2/es;
    sc[6] = 1.f + softplusf(p[69]);
}

// poly eval: x[i] = beta * cos for head hk given previous head's new w (in wdone[])
__device__ __forceinline__ void poly_x(
    float* x, const float* wdone, size_t base,
    float CC, float UU, float knorm, float beta)
{
    int tid = threadIdx.x;
    const size_t P = (size_t)B_*N_;
    const float* nrmp = g_norm + base;
    #pragma unroll
    for (int i = 0; i < 8; i++) {
        int n = tid + i*256;
        float w  = wdone[i];
        float Da = g_base[0*P + base + n];
        float Db = g_base[1*P + base + n];
        float S1 = g_base[2*P + base + n];
        float S2 = g_base[3*P + base + n];
        float T0 = g_base[4*P + base + n];
        float T1 = g_base[5*P + base + n];
        float nr = nrmp[n];
        float S0 = nr*nr;
        float dotv = Da - w*Db + w*CC;
        float w2 = w*w;
        float nsq = S0 - 2.f*w*S1 + w2*S2 + 2.f*w*T0 - 2.f*w2*T1 + w2*UU;
        float nn = sqrtf(fmaxf(nsq, 0.f));
        x[i] = beta * (dotv / (nn*knorm + EPSF));
    }
}

// ---------------- fused addressing: 4 read heads (y=0..3) + write heads 0&1 (y=4) -------------
__global__ void address5_kernel(const float* __restrict__ prw,
                                const float* __restrict__ pww,
                                float* __restrict__ o_rw,
                                float* __restrict__ o_ww)
{
    __shared__ float wg[2048];
    __shared__ float rbuf[32];
    __shared__ float sc[16];
    int b = blockIdx.x, h = blockIdx.y, tid = threadIdx.x;
    size_t base = (size_t)b*N_;
    const size_t P = (size_t)B_*N_;

    if (h < 4) {
        const float* p = g_rp + ((size_t)h*B_ + b)*PR_;
        float kv = 0.f;
        if (tid < 64) { float xx = p[tid]; kv = xx*xx; }
        float ksum = block_reduce_sum(kv, rbuf);
        if (tid == 0) head_scalars(p, ksum, sc);
        __syncthreads();
        float knorm = sc[0], beta = sc[1], g = sc[2];
        float s0 = sc[3], s1 = sc[4], s2 = sc[5], gamma = sc[6];

        const float* dotb = g_dot + (size_t)h*P + base;
        const float* nrmb = g_norm + base;
        float x[8];
        #pragma unroll
        for (int i = 0; i < 8; i++) {
            int n = tid + i*256;
            x[i] = beta * (dotb[n] / (nrmb[n]*knorm + EPSF));
        }
        address_tail(x, g, s0, s1, s2, gamma,
                     prw + (size_t)h*P + base, o_rw + (size_t)h*P + base, wg, rbuf);
    } else {
        const float* p0 = g_wp + (size_t)b*PW_;
        const float* p1 = g_wp + ((size_t)1*B_ + b)*PW_;
        float kv0 = 0.f, kv1 = 0.f, c1 = 0.f, c2 = 0.f;
        if (tid < 64) {
            float k0 = p0[tid], k1 = p1[tid];
            float a0 = tanhf(p0[134 + tid]);
            kv0 = k0*k0; kv1 = k1*k1; c1 = a0*k1; c2 = a0*a0;
        }
        float ks0 = block_reduce_sum(kv0, rbuf);
        float ks1 = block_reduce_sum(kv1, rbuf);
        float Cc  = block_reduce_sum(c1, rbuf);
        float U   = block_reduce_sum(c2, rbuf);
        if (tid == 0) {
            head_scalars(p0, ks0, sc);
            head_scalars(p1, ks1, sc + 7);
            sc[14] = Cc; sc[15] = U;
        }
        __syncthreads();

        // head 0 (exact dot/norm from passA planes)
        {
            float knorm = sc[0], beta = sc[1], g = sc[2];
            float s0 = sc[3], s1 = sc[4], s2 = sc[5], gamma = sc[6];
            const float* dotb = g_dot + 4*P + base;
            const float* nrmb = g_norm + base;
            float x[8];
            #pragma unroll
            for (int i = 0; i < 8; i++) {
                int n = tid + i*256;
                x[i] = beta * (dotb[n] / (nrmb[n]*knorm + EPSF));
            }
            address_tail(x, g, s0, s1, s2, gamma, pww + base, o_ww + base, wg, rbuf);
            __syncthreads();
            // head 1 (poly from x = new w0, still in registers)
            float y[8];
            poly_x(y, x, base, sc[14], sc[15], sc[7], sc[8]);
            address_tail(y, sc[9], sc[10], sc[11], sc[12], sc[13],
                         pww + P + base, o_ww + P + base, wg, rbuf);
        }
    }
}

// ---------------- fused write heads 2 & 3 ----------------
__global__ void addr23_kernel(const float* __restrict__ pww,
                              float* __restrict__ o_ww)
{
    __shared__ float wg[2048];
    __shared__ float rbuf[32];
    __shared__ float sc[16];
    int b = blockIdx.x, tid = threadIdx.x;
    size_t base = (size_t)b*N_;
    const size_t P = (size_t)B_*N_;

    const float* p2 = g_wp + ((size_t)2*B_ + b)*PW_;
    const float* p3 = g_wp + ((size_t)3*B_ + b)*PW_;
    float kv2 = 0.f, kv3 = 0.f, c1 = 0.f, c2 = 0.f;
    if (tid < 64) {
        float k2 = p2[tid], k3 = p3[tid];
        float a2 = tanhf(p2[134 + tid]);
        kv2 = k2*k2; kv3 = k3*k3; c1 = a2*k3; c2 = a2*a2;
    }
    float ks2 = block_reduce_sum(kv2, rbuf);
    float ks3 = block_reduce_sum(kv3, rbuf);
    float Cc  = block_reduce_sum(c1, rbuf);
    float U   = block_reduce_sum(c2, rbuf);
    if (tid == 0) {
        head_scalars(p2, ks2, sc);
        head_scalars(p3, ks3, sc + 7);
        sc[14] = Cc; sc[15] = U;
    }
    __syncthreads();

    // head 2 (exact dot2/norm2 from sweep1)
    float knorm = sc[0], beta = sc[1], g = sc[2];
    float s0 = sc[3], s1 = sc[4], s2 = sc[5], gamma = sc[6];
    const float* dotb = g_dot + 4*P + base;
    const float* nrmb = g_norm + base;
    float x[8];
    #pragma unroll
    for (int i = 0; i < 8; i++) {
        int n = tid + i*256;
        x[i] = beta * (dotb[n] / (nrmb[n]*knorm + EPSF));
    }
    address_tail(x, g, s0, s1, s2, gamma, pww + 2*P + base, o_ww + 2*P + base, wg, rbuf);
    __syncthreads();
    // head 3 (poly from x = new w2)
    float y[8];
    poly_x(y, x, base, sc[14], sc[15], sc[7], sc[8]);
    address_tail(y, sc[9], sc[10], sc[11], sc[12], sc[13],
                 pww + 3*P + base, o_ww + 3*P + base, wg, rbuf);
}

// ---------------- Sweep 1: reads einsum + dot2/norm2 + head-3 bases (NO memory write) ---------
__global__ void __launch_bounds__(256) sweep1_kernel(
    const float* __restrict__ mem_in,
    const float* __restrict__ wr,    // new_read_w [4][B][N]
    const float* __restrict__ wwp,   // new_write_w planes (0,1 used)
    float* __restrict__ ro_part)
{
    int bc = blockIdx.x; int b = bc >> 1; int nb = (bc & 1) << 10;
    int tid = threadIdx.x, wid = tid >> 5, lane = tid & 31;
    int hw = lane >> 4, l16 = lane & 15;

    __shared__ float4 sred[8][4][32];

    const float* p0 = g_wp + (size_t)b*PW_;
    const float* p1 = g_wp + ((size_t)1*B_ + b)*PW_;
    const float* p2 = g_wp + ((size_t)2*B_ + b)*PW_;
    const float* p3 = g_wp + ((size_t)3*B_ + b)*PW_;
    float e0[4], a0[4], e1[4], a1[4], k2[4], e2[4], a2[4], k3[4];
    float e2k3[4], e2sq[4], e2a2[4];
    #pragma unroll
    for (int j = 0; j < 4; j++) {
        int m = l16*4 + j;
        e0[j] = sigmoidf(p0[70 + m]);  a0[j] = tanhf(p0[134 + m]);
        e1[j] = sigmoidf(p1[70 + m]);  a1[j] = tanhf(p1[134 + m]);
        k2[j] = p2[m];
        e2[j] = sigmoidf(p2[70 + m]);  a2[j] = tanhf(p2[134 + m]);
        k3[j] = p3[m];
        e2k3[j] = e2[j]*k3[j];
        e2sq[j] = e2[j]*e2[j];
        e2a2[j] = e2[j]*a2[j];
    }

    float4 racc[4] = {{0,0,0,0},{0,0,0,0},{0,0,0,0},{0,0,0,0}};
    const size_t P = (size_t)B_*N_;
    float* dot2p = g_dot + 4*P;

    for (int it = 0; it < 64; it += 2) {
        int rA = it*16 + wid*2 + hw;
        int rB = rA + 16;
        size_t ixA = (size_t)b*N_ + nb + rA;
        size_t ixB = (size_t)b*N_ + nb + rB;

        float4 va = *(const float4*)(mem_in + ixA*M_ + l16*4);
        float4 vb = *(const float4*)(mem_in + ixB*M_ + l16*4);
        float w0A = wwp[ixA],     w0B = wwp[ixB];
        float w1A = wwp[P + ixA], w1B = wwp[P + ixB];
        float wvA[4], wvB[4];
        #pragma unroll
        for (int h = 0; h < 4; h++) {
            wvA[h] = wr[(size_t)h*P + ixA];
            wvB[h] = wr[(size_t)h*P + ixB];
        }

        float v[4]  = {va.x, va.y, va.z, va.w};
        float u[4]  = {vb.x, vb.y, vb.z, vb.w};
        float accA[8] = {}, accB[8] = {};
        #pragma unroll
        for (int j = 0; j < 4; j++) {
            float m1a = v[j]*(1.f - w0A*e0[j]) + w0A*a0[j];
            float m1b = u[j]*(1.f - w0B*e0[j]) + w0B*a0[j];
            float m2a = m1a*(1.f - w1A*e1[j]) + w1A*a1[j];
            float m2b = m1b*(1.f - w1B*e1[j]) + w1B*a1[j];
            float sa = m2a*m2a, sb = m2b*m2b;
            accA[0] += m2a*k2[j];    accB[0] += m2b*k2[j];
            accA[1] += sa;           accB[1] += sb;
            accA[2] += m2a*k3[j];    accB[2] += m2b*k3[j];
            accA[3] += m2a*e2k3[j];  accB[3] += m2b*e2k3[j];
            accA[4] += sa*e2[j];     accB[4] += sb*e2[j];
            accA[5] += sa*e2sq[j];   accB[5] += sb*e2sq[j];
            accA[6] += m2a*a2[j];    accB[6] += m2b*a2[j];
            accA[7] += m2a*e2a2[j];  accB[7] += m2b*e2a2[j];
        }
        #pragma unroll
        for (int h = 0; h < 4; h++) {
            racc[h].x += wvA[h]*v[0] + wvB[h]*u[0];
            racc[h].y += wvA[h]*v[1] + wvB[h]*u[1];
            racc[h].z += wvA[h]*v[2] + wvB[h]*u[2];
            racc[h].w += wvA[h]*v[3] + wvB[h]*u[3];
        }

        #pragma unroll
        for (int o = 8; o > 0; o >>= 1) {
            #pragma unroll
            for (int r = 0; r < 8; r++) {
                accA[r] += __shfl_xor_sync(0xffffffffu, accA[r], o);
                accB[r] += __shfl_xor_sync(0xffffffffu, accB[r], o);
            }
        }
        if (l16 == 0) {
            dot2p[ixA] = accA[0];            dot2p[ixB] = accB[0];
            g_norm[ixA] = sqrtf(accA[1]);    g_norm[ixB] = sqrtf(accB[1]);
            #pragma unroll
            for (int r = 0; r < 6; r++) {
                g_base[(size_t)r*P + ixA] = accA[2+r];
                g_base[(size_t)r*P + ixB] = accB[2+r];
            }
        }
    }

    #pragma unroll
    for (int h = 0; h < 4; h++) sred[wid][h][lane] = racc[h];
    __syncthreads();
    int h = tid >> 6, m = tid & 63;
    int l = m >> 2, c = m & 3;
    float s = 0.f;
    #pragma unroll
    for (int w = 0; w < 8; w++) {
        s += ((const float*)&sred[w][h][l])[c];
        s += ((const float*)&sred[w][h][l + 16])[c];
    }
    ro_part[(size_t)(bc & 1)*B_*256 + (size_t)b*256 + h*64 + m] = s;
}

__global__ void sum_ro_kernel(const float* __restrict__ part, float* __restrict__ o_ro)
{
    int i = blockIdx.x*blockDim.x + threadIdx.x;
    o_ro[i] = part[i] + part[B_*256 + i];
}

// ---------------- Sweep 2: all 4 head updates, original mem -> final mem ----------------
__global__ void __launch_bounds__(256) sweep2_kernel(
    const float* __restrict__ mem_in, float* __restrict__ mem_out,
    const float* __restrict__ wwp)   // all 4 planes
{
    int bc = blockIdx.x; int b = bc >> 1; int nb = (bc & 1) << 10;
    int tid = threadIdx.x, wid = tid >> 5, lane = tid & 31;
    int hw = lane >> 4, l16 = lane & 15;

    float e[4][4], a[4][4];
    #pragma unroll
    for (int h = 0; h < 4; h++) {
        const float* ph = g_wp + ((size_t)h*B_ + b)*PW_;
        #pragma unroll
        for (int j = 0; j < 4; j++) {
            int m = l16*4 + j;
            e[h][j] = sigmoidf(ph[70 + m]);
            a[h][j] = tanhf(ph[134 + m]);
        }
    }

    const size_t P = (size_t)B_*N_;
    for (int it = 0; it < 64; it += 4) {
        int r0 = it*16 + wid*2 + hw;
        size_t ix[4];
        float4 v[4];
        #pragma unroll
        for (int q = 0; q < 4; q++) {
            ix[q] = (size_t)b*N_ + nb + r0 + q*16;
            v[q] = *(const float4*)(mem_in + ix[q]*M_ + l16*4);
        }
        float w[4][4];
        #pragma unroll
        for (int q = 0; q < 4; q++)
            #pragma unroll
            for (int h = 0; h < 4; h++)
                w[q][h] = wwp[(size_t)h*P + ix[q]];

        #pragma unroll
        for (int q = 0; q < 4; q++) {
            float vv[4] = {v[q].x, v[q].y, v[q].z, v[q].w};
            #pragma unroll
            for (int j = 0; j < 4; j++) {
                float m = vv[j];
                #pragma unroll
                for (int h = 0; h < 4; h++)
                    m = m*(1.f - w[q][h]*e[h][j]) + w[q][h]*a[h][j];
                vv[j] = m;
            }
            *(float4*)(mem_out + ix[q]*M_ + l16*4) = make_float4(vv[0], vv[1], vv[2], vv[3]);
        }
    }
}

// ---------------- host launcher ----------------
extern "C" void kernel_launch(void* const* d_in, const int* in_sizes, int n_in,
                              void* d_out, int out_size)
{
    const float* ext    = (const float*)d_in[0];
    const float* pread  = (const float*)d_in[1];
    const float* prw    = (const float*)d_in[2];
    const float* pww    = (const float*)d_in[3];
    const float* mem    = (const float*)d_in[4];
    const float* ctrlW  = (const float*)d_in[5];
    const float* ctrlb  = (const float*)d_in[6];
    const float* readW  = (const float*)d_in[7];
    const float* readb  = (const float*)d_in[8];
    const float* writeW = (const float*)d_in[9];
    const float* writeb = (const float*)d_in[10];
    const float* outW   = (const float*)d_in[11];
    const float* outb   = (const float*)d_in[12];
    float* out = (float*)d_out;

    float *ctrl, *rp, *wp, *ropart;
    cudaGetSymbolAddress((void**)&ctrl,   g_ctrl);
    cudaGetSymbolAddress((void**)&rp,     g_rp);
    cudaGetSymbolAddress((void**)&wp,     g_wp);
    cudaGetSymbolAddress((void**)&ropart, g_ropart);

    float* o_mem = out + OUT_MEM;
    float* o_ro  = out + OUT_RO;
    float* o_rw  = out + OUT_RW;
    float* o_ww  = out + OUT_WW;

    // Controller GEMM with fused concat
    gemm_cat_kernel<<<dim3(8, 8), 256>>>(ext, 256, pread, 256, ctrlW, ctrlb, ctrl, 512);

    // All 8 head parameter GEMMs in one launch
    gemm_heads_kernel<<<dim3(4, 8, 8), 256>>>(ctrl, readW, readb, rp, writeW, writeb, wp);

    // Pass A: norms + dots (reads + write head0) + head-1 base dots
    passA_kernel<<<512, 256>>>(mem);

    // Addressing: 4 read heads + write heads 0&1 (fused, poly for head 1)
    address5_kernel<<<dim3(256, 5), 256>>>(prw, pww, o_rw, o_ww);

    // Sweep 1: reads einsum + dot2/norm2 + head-3 bases (no memory write)
    sweep1_kernel<<<512, 256>>>(mem, o_rw, o_ww, ropart);
    sum_ro_kernel<<<64, 1024>>>(ropart, o_ro);

    // Write heads 2 & 3 (fused, poly for head 3)
    addr23_kernel<<<256, 256>>>(pww, o_ww);

    // Sweep 2: apply all 4 head updates, original mem -> output mem
    sweep2_kernel<<<512, 256>>>(mem, o_mem, o_ww);

    // Output GEMM with fused concat
    gemm_cat_kernel<<<dim3(4, 8), 256>>>(ctrl, 512, o_ro, 256, outW, outb, out, 256);
}

// round 9
// speedup vs baseline: 1.1177x; 1.0103x over previous
#include <cuda_runtime.h>
#include <math.h>

// Problem constants
constexpr int B_  = 256;
constexpr int N_  = 2048;
constexpr int M_  = 64;
constexpr int C_  = 512;
constexpr int PR_ = 70;   // M + 3 + SHIFT
constexpr int PW_ = 198;  // PR + 2M
constexpr float EPSF = 1e-8f;

// Output layout (floats): ntm_out, memory, read_out, new_read_w, new_write_w
constexpr size_t OUT_MEM = 65536;
constexpr size_t OUT_RO  = 33619968;
constexpr size_t OUT_RW  = 33685504;
constexpr size_t OUT_WW  = 35782656;

// ---------------- device scratch ----------------
__device__ float g_ctrl[B_*C_];
__device__ float g_rp  [4*B_*PR_];
__device__ float g_wp  [4*B_*PW_];
__device__ float g_dot [5*(size_t)B_*N_];
__device__ float g_norm[(size_t)B_*N_];
__device__ float g_base[6*(size_t)B_*N_];   // base dots: Da,Db,S1,S2,T0,T1
__device__ float g_ropart[4*B_*256];

__device__ __forceinline__ float softplusf(float x){ return x > 20.f ? x : log1pf(expf(x)); }
__device__ __forceinline__ float sigmoidf (float x){ return 1.f/(1.f+expf(-x)); }

// ---------------- GEMM body (proven): tile 32x64, K-step 32 ----------------
__device__ __forceinline__ void gemm_body(
    const float* __restrict__ A0, int ca,
    const float* __restrict__ A1, int cb,
    const float* __restrict__ W, const float* __restrict__ bias,
    float* __restrict__ out, int Nc)
{
    int col0 = blockIdx.x * 64;
    if (col0 >= Nc) return;
    int row0 = blockIdx.y * 32;
    int K = ca + cb;

    __shared__ float As[32][33];
    __shared__ float Ws[32][64];
    int tid = threadIdx.x;
    int tx = tid & 15, ty = tid >> 4;
    float acc[2][4] = {};

    for (int k0 = 0; k0 < K; k0 += 32) {
        {
            int m  = tid >> 3;
            int kk = (tid & 7) * 4;
            int r = row0 + m, c = k0 + kk;
            float4 v;
            if (c < ca) v = *(const float4*)(A0 + (size_t)r*ca + c);
            else        v = *(const float4*)(A1 + (size_t)r*cb + (c - ca));
            As[m][kk] = v.x; As[m][kk+1] = v.y; As[m][kk+2] = v.z; As[m][kk+3] = v.w;
        }
        {
            int kk = tid >> 3;
            int n0 = (tid & 7) * 8;
            const float* wrow = W + (size_t)(k0 + kk)*Nc + col0 + n0;
            #pragma unroll
            for (int j = 0; j < 8; j++) {
                int gn = col0 + n0 + j;
                Ws[kk][n0 + j] = (gn < Nc) ? wrow[j] : 0.f;
            }
        }
        __syncthreads();
        #pragma unroll
        for (int kk = 0; kk < 32; kk++) {
            float a0 = As[ty*2 + 0][kk];
            float a1 = As[ty*2 + 1][kk];
            float4 w4 = *(const float4*)&Ws[kk][tx*4];
            acc[0][0] += a0*w4.x; acc[0][1] += a0*w4.y; acc[0][2] += a0*w4.z; acc[0][3] += a0*w4.w;
            acc[1][0] += a1*w4.x; acc[1][1] += a1*w4.y; acc[1][2] += a1*w4.z; acc[1][3] += a1*w4.w;
        }
        __syncthreads();
    }
    #pragma unroll
    for (int i = 0; i < 2; i++) {
        int gm = row0 + ty*2 + i;
        #pragma unroll
        for (int j = 0; j < 4; j++) {
            int gn = col0 + tx*4 + j;
            if (gn < Nc) out[(size_t)gm*Nc + gn] = acc[i][j] + bias[gn];
        }
    }
}

__global__ void gemm_cat_kernel(const float* __restrict__ A0, int ca,
                                const float* __restrict__ A1, int cb,
                                const float* __restrict__ W, const float* __restrict__ bias,
                                float* __restrict__ out, int Nc)
{
    gemm_body(A0, ca, A1, cb, W, bias, out, Nc);
}

__global__ void gemm_heads_kernel(const float* __restrict__ ctrl,
                                  const float* __restrict__ readW, const float* __restrict__ readb,
                                  float* __restrict__ rp,
                                  const float* __restrict__ writeW, const float* __restrict__ writeb,
                                  float* __restrict__ wp)
{
    int h = blockIdx.z;
    const float *W, *bias; float* out; int Nc;
    if (h < 4) {
        W = readW + (size_t)h*C_*PR_; bias = readb + h*PR_;
        out = rp + (size_t)h*B_*PR_;  Nc = PR_;
    } else {
        int g = h - 4;
        W = writeW + (size_t)g*C_*PW_; bias = writeb + g*PW_;
        out = wp + (size_t)g*B_*PW_;   Nc = PW_;
    }
    gemm_body(ctrl, C_, nullptr, 0, W, bias, out, Nc);
}

// ---------------- Pass A: mem norms + 5 key dots + head-1 base dots ----------------
// grid 1024 = (b, quarterN); half-warp per row, 2-row unroll.
__global__ void __launch_bounds__(256) passA_kernel(const float* __restrict__ mem)
{
    int bc = blockIdx.x; int b = bc >> 2; int nb = (bc & 3) << 9;
    int tid = threadIdx.x, wid = tid >> 5, lane = tid & 31;
    int hw = lane >> 4, l16 = lane & 15;

    float kk[5][4];
    #pragma unroll
    for (int h = 0; h < 5; h++) {
        const float* kp = (h < 4) ? (g_rp + ((size_t)h*B_ + b)*PR_) : (g_wp + (size_t)b*PW_);
        #pragma unroll
        for (int j = 0; j < 4; j++) kk[h][j] = kp[l16*4 + j];
    }
    const float* wp0 = g_wp + (size_t)b*PW_;
    const float* wp1 = g_wp + ((size_t)1*B_ + b)*PW_;
    float e0[4], a0[4], k1[4], e0sq[4], e0a0[4], e0k1[4];
    #pragma unroll
    for (int j = 0; j < 4; j++) {
        int m = l16*4 + j;
        e0[j] = sigmoidf(wp0[70 + m]);
        a0[j] = tanhf(wp0[134 + m]);
        k1[j] = wp1[m];
        e0sq[j] = e0[j]*e0[j];
        e0a0[j] = e0[j]*a0[j];
        e0k1[j] = e0[j]*k1[j];
    }

    const float* base = mem + ((size_t)b*N_ + nb)*M_;
    for (int it = 0; it < 32; it += 2) {
        int rA = it*16 + wid*2 + hw;
        int rB = rA + 16;
        float4 va = *(const float4*)(base + (size_t)rA*M_ + l16*4);
        float4 vb = *(const float4*)(base + (size_t)rB*M_ + l16*4);

        float v[4]  = {va.x, va.y, va.z, va.w};
        float u[4]  = {vb.x, vb.y, vb.z, vb.w};
        float accA[12] = {}, accB[12] = {};
        #pragma unroll
        for (int j = 0; j < 4; j++) {
            float vj = v[j], uj = u[j];
            float vs = vj*vj, us = uj*uj;
            accA[0] += vs;               accB[0] += us;
            #pragma unroll
            for (int h = 0; h < 5; h++) {
                accA[1+h] += vj*kk[h][j];
                accB[1+h] += uj*kk[h][j];
            }
            accA[6]  += vj*k1[j];        accB[6]  += uj*k1[j];
            accA[7]  += vj*e0k1[j];      accB[7]  += uj*e0k1[j];
            accA[8]  += vs*e0[j];        accB[8]  += us*e0[j];
            accA[9]  += vs*e0sq[j];      accB[9]  += us*e0sq[j];
            accA[10] += vj*a0[j];        accB[10] += uj*a0[j];
            accA[11] += vj*e0a0[j];      accB[11] += uj*e0a0[j];
        }
        #pragma unroll
        for (int o = 8; o > 0; o >>= 1) {
            #pragma unroll
            for (int r = 0; r < 12; r++) {
                accA[r] += __shfl_xor_sync(0xffffffffu, accA[r], o);
                accB[r] += __shfl_xor_sync(0xffffffffu, accB[r], o);
            }
        }
        if (l16 == 0) {
            size_t ixA = (size_t)b*N_ + nb + rA;
            size_t ixB = (size_t)b*N_ + nb + rB;
            g_norm[ixA] = sqrtf(accA[0]);
            g_norm[ixB] = sqrtf(accB[0]);
            #pragma unroll
            for (int h = 0; h < 5; h++) {
                g_dot[(size_t)h*B_*N_ + ixA] = accA[1+h];
                g_dot[(size_t)h*B_*N_ + ixB] = accB[1+h];
            }
            #pragma unroll
            for (int r = 0; r < 6; r++) {
                g_base[(size_t)r*B_*N_ + ixA] = accA[6+r];
                g_base[(size_t)r*B_*N_ + ixB] = accB[6+r];
            }
        }
    }
}

// ---------------- block reduction helpers (256 threads) ----------------
__device__ __forceinline__ float block_reduce_sum(float v, float* sbuf)
{
    int tid = threadIdx.x;
    #pragma unroll
    for (int o = 16; o > 0; o >>= 1) v += __shfl_xor_sync(0xffffffffu, v, o);
    if ((tid & 31) == 0) sbuf[tid >> 5] = v;
    __syncthreads();
    if (tid < 32) {
        float x = (tid < 8) ? sbuf[tid] : 0.f;
        #pragma unroll
        for (int o = 4; o > 0; o >>= 1) x += __shfl_xor_sync(0xffffffffu, x, o);
        if (tid == 0) sbuf[0] = x;
    }
    __syncthreads();
    float r = sbuf[0];
    __syncthreads();
    return r;
}

__device__ __forceinline__ float block_reduce_max(float v, float* sbuf)
{
    int tid = threadIdx.x;
    #pragma unroll
    for (int o = 16; o > 0; o >>= 1) v = fmaxf(v, __shfl_xor_sync(0xffffffffu, v, o));
    if ((tid & 31) == 0) sbuf[tid >> 5] = v;
    __syncthreads();
    if (tid < 32) {
        float x = (tid < 8) ? sbuf[tid] : -3.4e38f;
        #pragma unroll
        for (int o = 4; o > 0; o >>= 1) x = fmaxf(x, __shfl_xor_sync(0xffffffffu, x, o));
        if (tid == 0) sbuf[0] = x;
    }
    __syncthreads();
    float r = sbuf[0];
    __syncthreads();
    return r;
}

// ---------------- addressing tail: consumes x = beta*cos, leaves final w in x ----------------
__device__ __forceinline__ void address_tail(
    float* x, float g, float s0, float s1, float s2, float gamma,
    const float* __restrict__ wpb, float* __restrict__ woutb,
    float* wg, float* rbuf)
{
    int tid = threadIdx.x;
    float mx = -3.4e38f;
    #pragma unroll
    for (int i = 0; i < 8; i++) mx = fmaxf(mx, x[i]);
    float bmax = block_reduce_max(mx, rbuf);
    float lsum = 0.f;
    #pragma unroll
    for (int i = 0; i < 8; i++) {
        float e = __expf(x[i] - bmax);
        wg[tid + i*256] = e;
        lsum += e;
    }
    float bsum = block_reduce_sum(lsum, rbuf);
    float inv = 1.f / bsum;
    #pragma unroll
    for (int i = 0; i < 8; i++) {
        int n = tid + i*256;
        wg[n] = g * (wg[n]*inv) + (1.f-g) * wpb[n];
    }
    __syncthreads();
    float wpow[8];
    lsum = 0.f;
    #pragma unroll
    for (int i = 0; i < 8; i++) {
        int n = tid + i*256;
        float ws = s0*wg[(n+1)&(N_-1)] + s1*wg[n] + s2*wg[(n-1)&(N_-1)];
        float t = __powf(ws + EPSF, gamma);
        wpow[i] = t;
        lsum += t;
    }
    float psum = block_reduce_sum(lsum, rbuf);
    float ip = 1.f / psum;
    #pragma unroll
    for (int i = 0; i < 8; i++) {
        float wv = wpow[i]*ip;
        woutb[tid + i*256] = wv;
        x[i] = wv;
    }
}

__device__ __forceinline__ void head_scalars(const float* __restrict__ p, float ksum, float* sc)
{
    sc[0] = sqrtf(ksum);
    sc[1] = softplusf(p[64]);
    sc[2] = sigmoidf(p[65]);
    float a0 = p[66], a1 = p[67], a2 = p[68];
    float mx = fmaxf(a0, fmaxf(a1, a2));
    float e0 = expf(a0-mx), e1 = expf(a1-mx), e2 = expf(a2-mx);
    float es = e0 + e1 + e2;
    sc[3] = e0/es; sc[4] = e1/es; sc[5] = e2/es;
    sc[6] = 1.f + softplusf(p[69]);
}

__device__ __forceinline__ void poly_x(
    float* x, const float* wdone, size_t base,
    float CC, float UU, float knorm, float beta)
{
    int tid = threadIdx.x;
    const size_t P = (size_t)B_*N_;
    const float* nrmp = g_norm + base;
    #pragma unroll
    for (int i = 0; i < 8; i++) {
        int n = tid + i*256;
        float w  = wdone[i];
        float Da = g_base[0*P + base + n];
        float Db = g_base[1*P + base + n];
        float S1 = g_base[2*P + base + n];
        float S2 = g_base[3*P + base + n];
        float T0 = g_base[4*P + base + n];
        float T1 = g_base[5*P + base + n];
        float nr = nrmp[n];
        float S0 = nr*nr;
        float dotv = Da - w*Db + w*CC;
        float w2 = w*w;
        float nsq = S0 - 2.f*w*S1 + w2*S2 + 2.f*w*T0 - 2.f*w2*T1 + w2*UU;
        float nn = sqrtf(fmaxf(nsq, 0.f));
        x[i] = beta * (dotv / (nn*knorm + EPSF));
    }
}

// ---------------- fused addressing: 4 read heads (y=0..3) + write heads 0&1 (y=4) -------------
__global__ void address5_kernel(const float* __restrict__ prw,
                                const float* __restrict__ pww,
                                float* __restrict__ o_rw,
                                float* __restrict__ o_ww)
{
    __shared__ float wg[2048];
    __shared__ float rbuf[32];
    __shared__ float sc[16];
    int b = blockIdx.x, h = blockIdx.y, tid = threadIdx.x;
    size_t base = (size_t)b*N_;
    const size_t P = (size_t)B_*N_;

    if (h < 4) {
        const float* p = g_rp + ((size_t)h*B_ + b)*PR_;
        float kv = 0.f;
        if (tid < 64) { float xx = p[tid]; kv = xx*xx; }
        float ksum = block_reduce_sum(kv, rbuf);
        if (tid == 0) head_scalars(p, ksum, sc);
        __syncthreads();
        float knorm = sc[0], beta = sc[1], g = sc[2];
        float s0 = sc[3], s1 = sc[4], s2 = sc[5], gamma = sc[6];

        const float* dotb = g_dot + (size_t)h*P + base;
        const float* nrmb = g_norm + base;
        float x[8];
        #pragma unroll
        for (int i = 0; i < 8; i++) {
            int n = tid + i*256;
            x[i] = beta * (dotb[n] / (nrmb[n]*knorm + EPSF));
        }
        address_tail(x, g, s0, s1, s2, gamma,
                     prw + (size_t)h*P + base, o_rw + (size_t)h*P + base, wg, rbuf);
    } else {
        const float* p0 = g_wp + (size_t)b*PW_;
        const float* p1 = g_wp + ((size_t)1*B_ + b)*PW_;
        float kv0 = 0.f, kv1 = 0.f, c1 = 0.f, c2 = 0.f;
        if (tid < 64) {
            float k0 = p0[tid], k1 = p1[tid];
            float a0 = tanhf(p0[134 + tid]);
            kv0 = k0*k0; kv1 = k1*k1; c1 = a0*k1; c2 = a0*a0;
        }
        float ks0 = block_reduce_sum(kv0, rbuf);
        float ks1 = block_reduce_sum(kv1, rbuf);
        float Cc  = block_reduce_sum(c1, rbuf);
        float U   = block_reduce_sum(c2, rbuf);
        if (tid == 0) {
            head_scalars(p0, ks0, sc);
            head_scalars(p1, ks1, sc + 7);
            sc[14] = Cc; sc[15] = U;
        }
        __syncthreads();

        {
            float knorm = sc[0], beta = sc[1], g = sc[2];
            float s0 = sc[3], s1 = sc[4], s2 = sc[5], gamma = sc[6];
            const float* dotb = g_dot + 4*P + base;
            const float* nrmb = g_norm + base;
            float x[8];
            #pragma unroll
            for (int i = 0; i < 8; i++) {
                int n = tid + i*256;
                x[i] = beta * (dotb[n] / (nrmb[n]*knorm + EPSF));
            }
            address_tail(x, g, s0, s1, s2, gamma, pww + base, o_ww + base, wg, rbuf);
            __syncthreads();
            float y[8];
            poly_x(y, x, base, sc[14], sc[15], sc[7], sc[8]);
            address_tail(y, sc[9], sc[10], sc[11], sc[12], sc[13],
                         pww + P + base, o_ww + P + base, wg, rbuf);
        }
    }
}

// ---------------- fused write heads 2 & 3 ----------------
__global__ void addr23_kernel(const float* __restrict__ pww,
                              float* __restrict__ o_ww)
{
    __shared__ float wg[2048];
    __shared__ float rbuf[32];
    __shared__ float sc[16];
    int b = blockIdx.x, tid = threadIdx.x;
    size_t base = (size_t)b*N_;
    const size_t P = (size_t)B_*N_;

    const float* p2 = g_wp + ((size_t)2*B_ + b)*PW_;
    const float* p3 = g_wp + ((size_t)3*B_ + b)*PW_;
    float kv2 = 0.f, kv3 = 0.f, c1 = 0.f, c2 = 0.f;
    if (tid < 64) {
        float k2 = p2[tid], k3 = p3[tid];
        float a2 = tanhf(p2[134 + tid]);
        kv2 = k2*k2; kv3 = k3*k3; c1 = a2*k3; c2 = a2*a2;
    }
    float ks2 = block_reduce_sum(kv2, rbuf);
    float ks3 = block_reduce_sum(kv3, rbuf);
    float Cc  = block_reduce_sum(c1, rbuf);
    float U   = block_reduce_sum(c2, rbuf);
    if (tid == 0) {
        head_scalars(p2, ks2, sc);
        head_scalars(p3, ks3, sc + 7);
        sc[14] = Cc; sc[15] = U;
    }
    __syncthreads();

    float knorm = sc[0], beta = sc[1], g = sc[2];
    float s0 = sc[3], s1 = sc[4], s2 = sc[5], gamma = sc[6];
    const float* dotb = g_dot + 4*P + base;
    const float* nrmb = g_norm + base;
    float x[8];
    #pragma unroll
    for (int i = 0; i < 8; i++) {
        int n = tid + i*256;
        x[i] = beta * (dotb[n] / (nrmb[n]*knorm + EPSF));
    }
    address_tail(x, g, s0, s1, s2, gamma, pww + 2*P + base, o_ww + 2*P + base, wg, rbuf);
    __syncthreads();
    float y[8];
    poly_x(y, x, base, sc[14], sc[15], sc[7], sc[8]);
    address_tail(y, sc[9], sc[10], sc[11], sc[12], sc[13],
                 pww + 3*P + base, o_ww + 3*P + base, wg, rbuf);
}

// ---------------- Sweep 1: reads einsum + dot2/norm2 + head-3 bases (no memory write) ---------
// grid 1024 = (b, quarterN)
__global__ void __launch_bounds__(256) sweep1_kernel(
    const float* __restrict__ mem_in,
    const float* __restrict__ wr,
    const float* __restrict__ wwp,
    float* __restrict__ ro_part)
{
    int bc = blockIdx.x; int b = bc >> 2; int nb = (bc & 3) << 9;
    int tid = threadIdx.x, wid = tid >> 5, lane = tid & 31;
    int hw = lane >> 4, l16 = lane & 15;

    __shared__ float4 sred[8][4][32];

    const float* p0 = g_wp + (size_t)b*PW_;
    const float* p1 = g_wp + ((size_t)1*B_ + b)*PW_;
    const float* p2 = g_wp + ((size_t)2*B_ + b)*PW_;
    const float* p3 = g_wp + ((size_t)3*B_ + b)*PW_;
    float e0[4], a0[4], e1[4], a1[4], k2[4], e2[4], a2[4], k3[4];
    float e2k3[4], e2sq[4], e2a2[4];
    #pragma unroll
    for (int j = 0; j < 4; j++) {
        int m = l16*4 + j;
        e0[j] = sigmoidf(p0[70 + m]);  a0[j] = tanhf(p0[134 + m]);
        e1[j] = sigmoidf(p1[70 + m]);  a1[j] = tanhf(p1[134 + m]);
        k2[j] = p2[m];
        e2[j] = sigmoidf(p2[70 + m]);  a2[j] = tanhf(p2[134 + m]);
        k3[j] = p3[m];
        e2k3[j] = e2[j]*k3[j];
        e2sq[j] = e2[j]*e2[j];
        e2a2[j] = e2[j]*a2[j];
    }

    float4 racc[4] = {{0,0,0,0},{0,0,0,0},{0,0,0,0},{0,0,0,0}};
    const size_t P = (size_t)B_*N_;
    float* dot2p = g_dot + 4*P;

    for (int it = 0; it < 32; it += 2) {
        int rA = it*16 + wid*2 + hw;
        int rB = rA + 16;
        size_t ixA = (size_t)b*N_ + nb + rA;
        size_t ixB = (size_t)b*N_ + nb + rB;

        float4 va = *(const float4*)(mem_in + ixA*M_ + l16*4);
        float4 vb = *(const float4*)(mem_in + ixB*M_ + l16*4);
        float w0A = wwp[ixA],     w0B = wwp[ixB];
        float w1A = wwp[P + ixA], w1B = wwp[P + ixB];
        float wvA[4], wvB[4];
        #pragma unroll
        for (int h = 0; h < 4; h++) {
            wvA[h] = wr[(size_t)h*P + ixA];
            wvB[h] = wr[(size_t)h*P + ixB];
        }

        float v[4]  = {va.x, va.y, va.z, va.w};
        float u[4]  = {vb.x, vb.y, vb.z, vb.w};
        float accA[8] = {}, accB[8] = {};
        #pragma unroll
        for (int j = 0; j < 4; j++) {
            float m1a = v[j]*(1.f - w0A*e0[j]) + w0A*a0[j];
            float m1b = u[j]*(1.f - w0B*e0[j]) + w0B*a0[j];
            float m2a = m1a*(1.f - w1A*e1[j]) + w1A*a1[j];
            float m2b = m1b*(1.f - w1B*e1[j]) + w1B*a1[j];
            float sa = m2a*m2a, sb = m2b*m2b;
            accA[0] += m2a*k2[j];    accB[0] += m2b*k2[j];
            accA[1] += sa;           accB[1] += sb;
            accA[2] += m2a*k3[j];    accB[2] += m2b*k3[j];
            accA[3] += m2a*e2k3[j];  accB[3] += m2b*e2k3[j];
            accA[4] += sa*e2[j];     accB[4] += sb*e2[j];
            accA[5] += sa*e2sq[j];   accB[5] += sb*e2sq[j];
            accA[6] += m2a*a2[j];    accB[6] += m2b*a2[j];
            accA[7] += m2a*e2a2[j];  accB[7] += m2b*e2a2[j];
        }
        #pragma unroll
        for (int h = 0; h < 4; h++) {
            racc[h].x += wvA[h]*v[0] + wvB[h]*u[0];
            racc[h].y += wvA[h]*v[1] + wvB[h]*u[1];
            racc[h].z += wvA[h]*v[2] + wvB[h]*u[2];
            racc[h].w += wvA[h]*v[3] + wvB[h]*u[3];
        }

        #pragma unroll
        for (int o = 8; o > 0; o >>= 1) {
            #pragma unroll
            for (int r = 0; r < 8; r++) {
                accA[r] += __shfl_xor_sync(0xffffffffu, accA[r], o);
                accB[r] += __shfl_xor_sync(0xffffffffu, accB[r], o);
            }
        }
        if (l16 == 0) {
            dot2p[ixA] = accA[0];            dot2p[ixB] = accB[0];
            g_norm[ixA] = sqrtf(accA[1]);    g_norm[ixB] = sqrtf(accB[1]);
            #pragma unroll
            for (int r = 0; r < 6; r++) {
                g_base[(size_t)r*P + ixA] = accA[2+r];
                g_base[(size_t)r*P + ixB] = accB[2+r];
            }
        }
    }

    #pragma unroll
    for (int h = 0; h < 4; h++) sred[wid][h][lane] = racc[h];
    __syncthreads();
    int h = tid >> 6, m = tid & 63;
    int l = m >> 2, c = m & 3;
    float s = 0.f;
    #pragma unroll
    for (int w = 0; w < 8; w++) {
        s += ((const float*)&sred[w][h][l])[c];
        s += ((const float*)&sred[w][h][l + 16])[c];
    }
    ro_part[(size_t)(bc & 3)*B_*256 + (size_t)b*256 + h*64 + m] = s;
}

__global__ void sum_ro_kernel(const float* __restrict__ part, float* __restrict__ o_ro)
{
    int i = blockIdx.x*blockDim.x + threadIdx.x;
    o_ro[i] = (part[i] + part[B_*256 + i]) + (part[2*B_*256 + i] + part[3*B_*256 + i]);
}

// ---------------- Sweep 2: all 4 head updates, original mem -> final mem ----------------
// grid 1024 = (b, quarterN), half-warp float4, 4 rows in flight
__global__ void __launch_bounds__(256) sweep2_kernel(
    const float* __restrict__ mem_in, float* __restrict__ mem_out,
    const float* __restrict__ wwp)
{
    int bc = blockIdx.x; int b = bc >> 2; int nb = (bc & 3) << 9;
    int tid = threadIdx.x, wid = tid >> 5, lane = tid & 31;
    int hw = lane >> 4, l16 = lane & 15;

    float e[4][4], a[4][4];
    #pragma unroll
    for (int h = 0; h < 4; h++) {
        const float* ph = g_wp + ((size_t)h*B_ + b)*PW_;
        #pragma unroll
        for (int j = 0; j < 4; j++) {
            int m = l16*4 + j;
            e[h][j] = sigmoidf(ph[70 + m]);
            a[h][j] = tanhf(ph[134 + m]);
        }
    }

    const size_t P = (size_t)B_*N_;
    for (int it = 0; it < 32; it += 4) {
        int r0 = it*16 + wid*2 + hw;
        size_t ix[4];
        float4 v[4];
        #pragma unroll
        for (int q = 0; q < 4; q++) {
            ix[q] = (size_t)b*N_ + nb + r0 + q*16;
            v[q] = *(const float4*)(mem_in + ix[q]*M_ + l16*4);
        }
        float w[4][4];
        #pragma unroll
        for (int q = 0; q < 4; q++)
            #pragma unroll
            for (int h = 0; h < 4; h++)
                w[q][h] = wwp[(size_t)h*P + ix[q]];

        #pragma unroll
        for (int q = 0; q < 4; q++) {
            float vv[4] = {v[q].x, v[q].y, v[q].z, v[q].w};
            #pragma unroll
            for (int j = 0; j < 4; j++) {
                float m = vv[j];
                #pragma unroll
                for (int h = 0; h < 4; h++)
                    m = m*(1.f - w[q][h]*e[h][j]) + w[q][h]*a[h][j];
                vv[j] = m;
            }
            *(float4*)(mem_out + ix[q]*M_ + l16*4) = make_float4(vv[0], vv[1], vv[2], vv[3]);
        }
    }
}

// ---------------- host launcher ----------------
extern "C" void kernel_launch(void* const* d_in, const int* in_sizes, int n_in,
                              void* d_out, int out_size)
{
    const float* ext    = (const float*)d_in[0];
    const float* pread  = (const float*)d_in[1];
    const float* prw    = (const float*)d_in[2];
    const float* pww    = (const float*)d_in[3];
    const float* mem    = (const float*)d_in[4];
    const float* ctrlW  = (const float*)d_in[5];
    const float* ctrlb  = (const float*)d_in[6];
    const float* readW  = (const float*)d_in[7];
    const float* readb  = (const float*)d_in[8];
    const float* writeW = (const float*)d_in[9];
    const float* writeb = (const float*)d_in[10];
    const float* outW   = (const float*)d_in[11];
    const float* outb   = (const float*)d_in[12];
    float* out = (float*)d_out;

    float *ctrl, *rp, *wp, *ropart;
    cudaGetSymbolAddress((void**)&ctrl,   g_ctrl);
    cudaGetSymbolAddress((void**)&rp,     g_rp);
    cudaGetSymbolAddress((void**)&wp,     g_wp);
    cudaGetSymbolAddress((void**)&ropart, g_ropart);

    float* o_mem = out + OUT_MEM;
    float* o_ro  = out + OUT_RO;
    float* o_rw  = out + OUT_RW;
    float* o_ww  = out + OUT_WW;

    // Controller GEMM with fused concat
    gemm_cat_kernel<<<dim3(8, 8), 256>>>(ext, 256, pread, 256, ctrlW, ctrlb, ctrl, 512);

    // All 8 head parameter GEMMs in one launch
    gemm_heads_kernel<<<dim3(4, 8, 8), 256>>>(ctrl, readW, readb, rp, writeW, writeb, wp);

    // Pass A: norms + dots (reads + write head0) + head-1 base dots
    passA_kernel<<<1024, 256>>>(mem);

    // Addressing: 4 read heads + write heads 0&1 (fused, poly for head 1)
    address5_kernel<<<dim3(256, 5), 256>>>(prw, pww, o_rw, o_ww);

    // Sweep 1: reads einsum + dot2/norm2 + head-3 bases (no memory write)
    sweep1_kernel<<<1024, 256>>>(mem, o_rw, o_ww, ropart);
    sum_ro_kernel<<<64, 1024>>>(ropart, o_ro);

    // Write heads 2 & 3 (fused, poly for head 3)
    addr23_kernel<<<256, 256>>>(pww, o_ww);

    // Sweep 2: apply all 4 head updates, original mem -> output mem
    sweep2_kernel<<<1024, 256>>>(mem, o_mem, o_ww);

    // Output GEMM with fused concat
    gemm_cat_kernel<<<dim3(4, 8), 256>>>(ctrl, 512, o_ro, 256, outW, outb, out, 256);
}

// round 10
// speedup vs baseline: 1.1599x; 1.0378x over previous
#include <cuda_runtime.h>
#include <math.h>

// Problem constants
constexpr int B_  = 256;
constexpr int N_  = 2048;
constexpr int M_  = 64;
constexpr int C_  = 512;
constexpr int PR_ = 70;   // M + 3 + SHIFT
constexpr int PW_ = 198;  // PR + 2M
constexpr float EPSF = 1e-8f;

// Output layout (floats): ntm_out, memory, read_out, new_read_w, new_write_w
constexpr size_t OUT_MEM = 65536;
constexpr size_t OUT_RO  = 33619968;
constexpr size_t OUT_RW  = 33685504;
constexpr size_t OUT_WW  = 35782656;

// ---------------- device scratch ----------------
__device__ float g_ctrl[B_*C_];
__device__ float g_rp  [4*B_*PR_];
__device__ float g_wp  [4*B_*PW_];
__device__ float g_dot [5*(size_t)B_*N_];
__device__ float g_norm[(size_t)B_*N_];
__device__ float g_base[6*(size_t)B_*N_];   // base dots: Da,Db,S1,S2,T0,T1
__device__ float g_ropart[4*B_*256];

__device__ __forceinline__ float softplusf(float x){ return x > 20.f ? x : log1pf(expf(x)); }
__device__ __forceinline__ float sigmoidf (float x){ return 1.f/(1.f+expf(-x)); }

// ---------------- GEMM body (proven): tile 32x64, K-step 32, 256 threads ----------------
__device__ __forceinline__ void gemm_body(
    const float* __restrict__ A0, int ca,
    const float* __restrict__ A1, int cb,
    const float* __restrict__ W, const float* __restrict__ bias,
    float* __restrict__ out, int Nc)
{
    int col0 = blockIdx.x * 64;
    if (col0 >= Nc) return;
    int row0 = blockIdx.y * 32;
    int K = ca + cb;

    __shared__ float As[32][33];
    __shared__ float Ws[32][64];
    int tid = threadIdx.x;
    int tx = tid & 15, ty = tid >> 4;
    float acc[2][4] = {};

    for (int k0 = 0; k0 < K; k0 += 32) {
        {
            int m  = tid >> 3;
            int kk = (tid & 7) * 4;
            int r = row0 + m, c = k0 + kk;
            float4 v;
            if (c < ca) v = *(const float4*)(A0 + (size_t)r*ca + c);
            else        v = *(const float4*)(A1 + (size_t)r*cb + (c - ca));
            As[m][kk] = v.x; As[m][kk+1] = v.y; As[m][kk+2] = v.z; As[m][kk+3] = v.w;
        }
        {
            int kk = tid >> 3;
            int n0 = (tid & 7) * 8;
            const float* wrow = W + (size_t)(k0 + kk)*Nc + col0 + n0;
            #pragma unroll
            for (int j = 0; j < 8; j++) {
                int gn = col0 + n0 + j;
                Ws[kk][n0 + j] = (gn < Nc) ? wrow[j] : 0.f;
            }
        }
        __syncthreads();
        #pragma unroll
        for (int kk = 0; kk < 32; kk++) {
            float a0 = As[ty*2 + 0][kk];
            float a1 = As[ty*2 + 1][kk];
            float4 w4 = *(const float4*)&Ws[kk][tx*4];
            acc[0][0] += a0*w4.x; acc[0][1] += a0*w4.y; acc[0][2] += a0*w4.z; acc[0][3] += a0*w4.w;
            acc[1][0] += a1*w4.x; acc[1][1] += a1*w4.y; acc[1][2] += a1*w4.z; acc[1][3] += a1*w4.w;
        }
        __syncthreads();
    }
    #pragma unroll
    for (int i = 0; i < 2; i++) {
        int gm = row0 + ty*2 + i;
        #pragma unroll
        for (int j = 0; j < 4; j++) {
            int gn = col0 + tx*4 + j;
            if (gn < Nc) out[(size_t)gm*Nc + gn] = acc[i][j] + bias[gn];
        }
    }
}

__global__ void gemm_cat_kernel(const float* __restrict__ A0, int ca,
                                const float* __restrict__ A1, int cb,
                                const float* __restrict__ W, const float* __restrict__ bias,
                                float* __restrict__ out, int Nc)
{
    gemm_body(A0, ca, A1, cb, W, bias, out, Nc);
}

__global__ void gemm_heads_kernel(const float* __restrict__ ctrl,
                                  const float* __restrict__ readW, const float* __restrict__ readb,
                                  float* __restrict__ rp,
                                  const float* __restrict__ writeW, const float* __restrict__ writeb,
                                  float* __restrict__ wp)
{
    int h = blockIdx.z;
    const float *W, *bias; float* out; int Nc;
    if (h < 4) {
        W = readW + (size_t)h*C_*PR_; bias = readb + h*PR_;
        out = rp + (size_t)h*B_*PR_;  Nc = PR_;
    } else {
        int g = h - 4;
        W = writeW + (size_t)g*C_*PW_; bias = writeb + g*PW_;
        out = wp + (size_t)g*B_*PW_;   Nc = PW_;
    }
    gemm_body(ctrl, C_, nullptr, 0, W, bias, out, Nc);
}

// ---------------- Output GEMM with fused ro-sum: A = [ctrl | sum4(ro_part)] ----------------
// Also writes o_ro (column-tile 0 CTAs only; deterministic duplicate-free by blockIdx.x==0).
__global__ void gemm_out_kernel(const float* __restrict__ ctrl,
                                const float* __restrict__ part,
                                const float* __restrict__ W, const float* __restrict__ bias,
                                float* __restrict__ out, float* __restrict__ o_ro)
{
    constexpr int Nc = 256;
    int col0 = blockIdx.x * 64;
    int row0 = blockIdx.y * 32;

    __shared__ float As[32][33];
    __shared__ float Ws[32][64];
    int tid = threadIdx.x;
    int tx = tid & 15, ty = tid >> 4;
    float acc[2][4] = {};

    for (int k0 = 0; k0 < 768; k0 += 32) {
        {
            int m  = tid >> 3;
            int kk = (tid & 7) * 4;
            int r = row0 + m, c = k0 + kk;
            float4 v;
            if (c < 512) {
                v = *(const float4*)(ctrl + (size_t)r*512 + c);
            } else {
                int cc = c - 512;
                const float* p = part + (size_t)r*256 + cc;
                float4 v0 = *(const float4*)p;
                float4 v1 = *(const float4*)(p + (size_t)B_*256);
                float4 v2 = *(const float4*)(p + (size_t)2*B_*256);
                float4 v3 = *(const float4*)(p + (size_t)3*B_*256);
                v.x = (v0.x + v1.x) + (v2.x + v3.x);
                v.y = (v0.y + v1.y) + (v2.y + v3.y);
                v.z = (v0.z + v1.z) + (v2.z + v3.z);
                v.w = (v0.w + v1.w) + (v2.w + v3.w);
                if (blockIdx.x == 0)
                    *(float4*)(o_ro + (size_t)r*256 + cc) = v;
            }
            As[m][kk] = v.x; As[m][kk+1] = v.y; As[m][kk+2] = v.z; As[m][kk+3] = v.w;
        }
        {
            int kk = tid >> 3;
            int n0 = (tid & 7) * 8;
            const float* wrow = W + (size_t)(k0 + kk)*Nc + col0 + n0;
            #pragma unroll
            for (int j = 0; j < 8; j++)
                Ws[kk][n0 + j] = wrow[j];
        }
        __syncthreads();
        #pragma unroll
        for (int kk = 0; kk < 32; kk++) {
            float a0 = As[ty*2 + 0][kk];
            float a1 = As[ty*2 + 1][kk];
            float4 w4 = *(const float4*)&Ws[kk][tx*4];
            acc[0][0] += a0*w4.x; acc[0][1] += a0*w4.y; acc[0][2] += a0*w4.z; acc[0][3] += a0*w4.w;
            acc[1][0] += a1*w4.x; acc[1][1] += a1*w4.y; acc[1][2] += a1*w4.z; acc[1][3] += a1*w4.w;
        }
        __syncthreads();
    }
    #pragma unroll
    for (int i = 0; i < 2; i++) {
        int gm = row0 + ty*2 + i;
        #pragma unroll
        for (int j = 0; j < 4; j++) {
            int gn = col0 + tx*4 + j;
            out[(size_t)gm*Nc + gn] = acc[i][j] + bias[gn];
        }
    }
}

// ---------------- Pass A: mem norms + 5 key dots + head-1 base dots ----------------
__global__ void __launch_bounds__(256) passA_kernel(const float* __restrict__ mem)
{
    int bc = blockIdx.x; int b = bc >> 2; int nb = (bc & 3) << 9;
    int tid = threadIdx.x, wid = tid >> 5, lane = tid & 31;
    int hw = lane >> 4, l16 = lane & 15;

    float kk[5][4];
    #pragma unroll
    for (int h = 0; h < 5; h++) {
        const float* kp = (h < 4) ? (g_rp + ((size_t)h*B_ + b)*PR_) : (g_wp + (size_t)b*PW_);
        #pragma unroll
        for (int j = 0; j < 4; j++) kk[h][j] = kp[l16*4 + j];
    }
    const float* wp0 = g_wp + (size_t)b*PW_;
    const float* wp1 = g_wp + ((size_t)1*B_ + b)*PW_;
    float e0[4], a0[4], k1[4], e0sq[4], e0a0[4], e0k1[4];
    #pragma unroll
    for (int j = 0; j < 4; j++) {
        int m = l16*4 + j;
        e0[j] = sigmoidf(wp0[70 + m]);
        a0[j] = tanhf(wp0[134 + m]);
        k1[j] = wp1[m];
        e0sq[j] = e0[j]*e0[j];
        e0a0[j] = e0[j]*a0[j];
        e0k1[j] = e0[j]*k1[j];
    }

    const float* base = mem + ((size_t)b*N_ + nb)*M_;
    for (int it = 0; it < 32; it += 2) {
        int rA = it*16 + wid*2 + hw;
        int rB = rA + 16;
        float4 va = *(const float4*)(base + (size_t)rA*M_ + l16*4);
        float4 vb = *(const float4*)(base + (size_t)rB*M_ + l16*4);

        float v[4]  = {va.x, va.y, va.z, va.w};
        float u[4]  = {vb.x, vb.y, vb.z, vb.w};
        float accA[12] = {}, accB[12] = {};
        #pragma unroll
        for (int j = 0; j < 4; j++) {
            float vj = v[j], uj = u[j];
            float vs = vj*vj, us = uj*uj;
            accA[0] += vs;               accB[0] += us;
            #pragma unroll
            for (int h = 0; h < 5; h++) {
                accA[1+h] += vj*kk[h][j];
                accB[1+h] += uj*kk[h][j];
            }
            accA[6]  += vj*k1[j];        accB[6]  += uj*k1[j];
            accA[7]  += vj*e0k1[j];      accB[7]  += uj*e0k1[j];
            accA[8]  += vs*e0[j];        accB[8]  += us*e0[j];
            accA[9]  += vs*e0sq[j];      accB[9]  += us*e0sq[j];
            accA[10] += vj*a0[j];        accB[10] += uj*a0[j];
            accA[11] += vj*e0a0[j];      accB[11] += uj*e0a0[j];
        }
        #pragma unroll
        for (int o = 8; o > 0; o >>= 1) {
            #pragma unroll
            for (int r = 0; r < 12; r++) {
                accA[r] += __shfl_xor_sync(0xffffffffu, accA[r], o);
                accB[r] += __shfl_xor_sync(0xffffffffu, accB[r], o);
            }
        }
        if (l16 == 0) {
            size_t ixA = (size_t)b*N_ + nb + rA;
            size_t ixB = (size_t)b*N_ + nb + rB;
            g_norm[ixA] = sqrtf(accA[0]);
            g_norm[ixB] = sqrtf(accB[0]);
            #pragma unroll
            for (int h = 0; h < 5; h++) {
                g_dot[(size_t)h*B_*N_ + ixA] = accA[1+h];
                g_dot[(size_t)h*B_*N_ + ixB] = accB[1+h];
            }
            #pragma unroll
            for (int r = 0; r < 6; r++) {
                g_base[(size_t)r*B_*N_ + ixA] = accA[6+r];
                g_base[(size_t)r*B_*N_ + ixB] = accB[6+r];
            }
        }
    }
}

// ---------------- block reduction helpers (512 threads) ----------------
__device__ __forceinline__ float block_reduce_sum512(float v, float* sbuf)
{
    int tid = threadIdx.x;
    #pragma unroll
    for (int o = 16; o > 0; o >>= 1) v += __shfl_xor_sync(0xffffffffu, v, o);
    if ((tid & 31) == 0) sbuf[tid >> 5] = v;
    __syncthreads();
    if (tid < 32) {
        float x = (tid < 16) ? sbuf[tid] : 0.f;
        #pragma unroll
        for (int o = 8; o > 0; o >>= 1) x += __shfl_xor_sync(0xffffffffu, x, o);
        if (tid == 0) sbuf[0] = x;
    }
    __syncthreads();
    float r = sbuf[0];
    __syncthreads();
    return r;
}

__device__ __forceinline__ float block_reduce_max512(float v, float* sbuf)
{
    int tid = threadIdx.x;
    #pragma unroll
    for (int o = 16; o > 0; o >>= 1) v = fmaxf(v, __shfl_xor_sync(0xffffffffu, v, o));
    if ((tid & 31) == 0) sbuf[tid >> 5] = v;
    __syncthreads();
    if (tid < 32) {
        float x = (tid < 16) ? sbuf[tid] : -3.4e38f;
        #pragma unroll
        for (int o = 8; o > 0; o >>= 1) x = fmaxf(x, __shfl_xor_sync(0xffffffffu, x, o));
        if (tid == 0) sbuf[0] = x;
    }
    __syncthreads();
    float r = sbuf[0];
    __syncthreads();
    return r;
}

// ---------------- addressing tail (512 threads, 4 items/thread) ----------------
__device__ __forceinline__ void address_tail(
    float* x, float g, float s0, float s1, float s2, float gamma,
    const float* __restrict__ wpb, float* __restrict__ woutb,
    float* wg, float* rbuf)
{
    int tid = threadIdx.x;
    float mx = fmaxf(fmaxf(x[0], x[1]), fmaxf(x[2], x[3]));
    float bmax = block_reduce_max512(mx, rbuf);
    float lsum = 0.f;
    #pragma unroll
    for (int i = 0; i < 4; i++) {
        float e = __expf(x[i] - bmax);
        wg[tid + i*512] = e;
        lsum += e;
    }
    float bsum = block_reduce_sum512(lsum, rbuf);
    float inv = 1.f / bsum;
    #pragma unroll
    for (int i = 0; i < 4; i++) {
        int n = tid + i*512;
        wg[n] = g * (wg[n]*inv) + (1.f-g) * wpb[n];
    }
    __syncthreads();
    float wpow[4];
    lsum = 0.f;
    #pragma unroll
    for (int i = 0; i < 4; i++) {
        int n = tid + i*512;
        float ws = s0*wg[(n+1)&(N_-1)] + s1*wg[n] + s2*wg[(n-1)&(N_-1)];
        float t = __powf(ws + EPSF, gamma);
        wpow[i] = t;
        lsum += t;
    }
    float psum = block_reduce_sum512(lsum, rbuf);
    float ip = 1.f / psum;
    #pragma unroll
    for (int i = 0; i < 4; i++) {
        float wv = wpow[i]*ip;
        woutb[tid + i*512] = wv;
        x[i] = wv;
    }
}

__device__ __forceinline__ void head_scalars(const float* __restrict__ p, float ksum, float* sc)
{
    sc[0] = sqrtf(ksum);
    sc[1] = softplusf(p[64]);
    sc[2] = sigmoidf(p[65]);
    float a0 = p[66], a1 = p[67], a2 = p[68];
    float mx = fmaxf(a0, fmaxf(a1, a2));
    float e0 = expf(a0-mx), e1 = expf(a1-mx), e2 = expf(a2-mx);
    float es = e0 + e1 + e2;
    sc[3] = e0/es; sc[4] = e1/es; sc[5] = e2/es;
    sc[6] = 1.f + softplusf(p[69]);
}

// poly eval (512 threads, 4 items/thread): x[i] = beta * cos for next head
__device__ __forceinline__ void poly_x(
    float* x, const float* wdone, size_t base,
    float CC, float UU, float knorm, float beta)
{
    int tid = threadIdx.x;
    const size_t P = (size_t)B_*N_;
    const float* nrmp = g_norm + base;
    #pragma unroll
    for (int i = 0; i < 4; i++) {
        int n = tid + i*512;
        float w  = wdone[i];
        float Da = g_base[0*P + base + n];
        float Db = g_base[1*P + base + n];
        float S1 = g_base[2*P + base + n];
        float S2 = g_base[3*P + base + n];
        float T0 = g_base[4*P + base + n];
        float T1 = g_base[5*P + base + n];
        float nr = nrmp[n];
        float S0 = nr*nr;
        float dotv = Da - w*Db + w*CC;
        float w2 = w*w;
        float nsq = S0 - 2.f*w*S1 + w2*S2 + 2.f*w*T0 - 2.f*w2*T1 + w2*UU;
        float nn = sqrtf(fmaxf(nsq, 0.f));
        x[i] = beta * (dotv / (nn*knorm + EPSF));
    }
}

// ---------------- fused addressing: 4 read heads (y=0..3) + write heads 0&1 (y=4) -------------
__global__ void __launch_bounds__(512) address5_kernel(
    const float* __restrict__ prw,
    const float* __restrict__ pww,
    float* __restrict__ o_rw,
    float* __restrict__ o_ww)
{
    __shared__ float wg[2048];
    __shared__ float rbuf[32];
    __shared__ float sc[16];
    int b = blockIdx.x, h = blockIdx.y, tid = threadIdx.x;
    size_t base = (size_t)b*N_;
    const size_t P = (size_t)B_*N_;

    if (h < 4) {
        const float* p = g_rp + ((size_t)h*B_ + b)*PR_;
        float kv = 0.f;
        if (tid < 64) { float xx = p[tid]; kv = xx*xx; }
        float ksum = block_reduce_sum512(kv, rbuf);
        if (tid == 0) head_scalars(p, ksum, sc);
        __syncthreads();
        float knorm = sc[0], beta = sc[1], g = sc[2];
        float s0 = sc[3], s1 = sc[4], s2 = sc[5], gamma = sc[6];

        const float* dotb = g_dot + (size_t)h*P + base;
        const float* nrmb = g_norm + base;
        float x[4];
        #pragma unroll
        for (int i = 0; i < 4; i++) {
            int n = tid + i*512;
            x[i] = beta * (dotb[n] / (nrmb[n]*knorm + EPSF));
        }
        address_tail(x, g, s0, s1, s2, gamma,
                     prw + (size_t)h*P + base, o_rw + (size_t)h*P + base, wg, rbuf);
    } else {
        const float* p0 = g_wp + (size_t)b*PW_;
        const float* p1 = g_wp + ((size_t)1*B_ + b)*PW_;
        float kv0 = 0.f, kv1 = 0.f, c1 = 0.f, c2 = 0.f;
        if (tid < 64) {
            float k0 = p0[tid], k1 = p1[tid];
            float a0 = tanhf(p0[134 + tid]);
            kv0 = k0*k0; kv1 = k1*k1; c1 = a0*k1; c2 = a0*a0;
        }
        float ks0 = block_reduce_sum512(kv0, rbuf);
        float ks1 = block_reduce_sum512(kv1, rbuf);
        float Cc  = block_reduce_sum512(c1, rbuf);
        float U   = block_reduce_sum512(c2, rbuf);
        if (tid == 0) {
            head_scalars(p0, ks0, sc);
            head_scalars(p1, ks1, sc + 7);
            sc[14] = Cc; sc[15] = U;
        }
        __syncthreads();

        float knorm = sc[0], beta = sc[1], g = sc[2];
        float s0 = sc[3], s1 = sc[4], s2 = sc[5], gamma = sc[6];
        const float* dotb = g_dot + 4*P + base;
        const float* nrmb = g_norm + base;
        float x[4];
        #pragma unroll
        for (int i = 0; i < 4; i++) {
            int n = tid + i*512;
            x[i] = beta * (dotb[n] / (nrmb[n]*knorm + EPSF));
        }
        address_tail(x, g, s0, s1, s2, gamma, pww + base, o_ww + base, wg, rbuf);
        __syncthreads();
        float y[4];
        poly_x(y, x, base, sc[14], sc[15], sc[7], sc[8]);
        address_tail(y, sc[9], sc[10], sc[11], sc[12], sc[13],
                     pww + P + base, o_ww + P + base, wg, rbuf);
    }
}

// ---------------- fused write heads 2 & 3 ----------------
__global__ void __launch_bounds__(512) addr23_kernel(
    const float* __restrict__ pww,
    float* __restrict__ o_ww)
{
    __shared__ float wg[2048];
    __shared__ float rbuf[32];
    __shared__ float sc[16];
    int b = blockIdx.x, tid = threadIdx.x;
    size_t base = (size_t)b*N_;
    const size_t P = (size_t)B_*N_;

    const float* p2 = g_wp + ((size_t)2*B_ + b)*PW_;
    const float* p3 = g_wp + ((size_t)3*B_ + b)*PW_;
    float kv2 = 0.f, kv3 = 0.f, c1 = 0.f, c2 = 0.f;
    if (tid < 64) {
        float k2 = p2[tid], k3 = p3[tid];
        float a2 = tanhf(p2[134 + tid]);
        kv2 = k2*k2; kv3 = k3*k3; c1 = a2*k3; c2 = a2*a2;
    }
    float ks2 = block_reduce_sum512(kv2, rbuf);
    float ks3 = block_reduce_sum512(kv3, rbuf);
    float Cc  = block_reduce_sum512(c1, rbuf);
    float U   = block_reduce_sum512(c2, rbuf);
    if (tid == 0) {
        head_scalars(p2, ks2, sc);
        head_scalars(p3, ks3, sc + 7);
        sc[14] = Cc; sc[15] = U;
    }
    __syncthreads();

    float knorm = sc[0], beta = sc[1], g = sc[2];
    float s0 = sc[3], s1 = sc[4], s2 = sc[5], gamma = sc[6];
    const float* dotb = g_dot + 4*P + base;
    const float* nrmb = g_norm + base;
    float x[4];
    #pragma unroll
    for (int i = 0; i < 4; i++) {
        int n = tid + i*512;
        x[i] = beta * (dotb[n] / (nrmb[n]*knorm + EPSF));
    }
    address_tail(x, g, s0, s1, s2, gamma, pww + 2*P + base, o_ww + 2*P + base, wg, rbuf);
    __syncthreads();
    float y[4];
    poly_x(y, x, base, sc[14], sc[15], sc[7], sc[8]);
    address_tail(y, sc[9], sc[10], sc[11], sc[12], sc[13],
                 pww + 3*P + base, o_ww + 3*P + base, wg, rbuf);
}

// ---------------- Sweep 1: reads einsum + dot2/norm2 + head-3 bases (no memory write) ---------
__global__ void __launch_bounds__(256) sweep1_kernel(
    const float* __restrict__ mem_in,
    const float* __restrict__ wr,
    const float* __restrict__ wwp,
    float* __restrict__ ro_part)
{
    int bc = blockIdx.x; int b = bc >> 2; int nb = (bc & 3) << 9;
    int tid = threadIdx.x, wid = tid >> 5, lane = tid & 31;
    int hw = lane >> 4, l16 = lane & 15;

    __shared__ float4 sred[8][4][32];

    const float* p0 = g_wp + (size_t)b*PW_;
    const float* p1 = g_wp + ((size_t)1*B_ + b)*PW_;
    const float* p2 = g_wp + ((size_t)2*B_ + b)*PW_;
    const float* p3 = g_wp + ((size_t)3*B_ + b)*PW_;
    float e0[4], a0[4], e1[4], a1[4], k2[4], e2[4], a2[4], k3[4];
    float e2k3[4], e2sq[4], e2a2[4];
    #pragma unroll
    for (int j = 0; j < 4; j++) {
        int m = l16*4 + j;
        e0[j] = sigmoidf(p0[70 + m]);  a0[j] = tanhf(p0[134 + m]);
        e1[j] = sigmoidf(p1[70 + m]);  a1[j] = tanhf(p1[134 + m]);
        k2[j] = p2[m];
        e2[j] = sigmoidf(p2[70 + m]);  a2[j] = tanhf(p2[134 + m]);
        k3[j] = p3[m];
        e2k3[j] = e2[j]*k3[j];
        e2sq[j] = e2[j]*e2[j];
        e2a2[j] = e2[j]*a2[j];
    }

    float4 racc[4] = {{0,0,0,0},{0,0,0,0},{0,0,0,0},{0,0,0,0}};
    const size_t P = (size_t)B_*N_;
    float* dot2p = g_dot + 4*P;

    for (int it = 0; it < 32; it += 2) {
        int rA = it*16 + wid*2 + hw;
        int rB = rA + 16;
        size_t ixA = (size_t)b*N_ + nb + rA;
        size_t ixB = (size_t)b*N_ + nb + rB;

        float4 va = *(const float4*)(mem_in + ixA*M_ + l16*4);
        float4 vb = *(const float4*)(mem_in + ixB*M_ + l16*4);
        float w0A = wwp[ixA],     w0B = wwp[ixB];
        float w1A = wwp[P + ixA], w1B = wwp[P + ixB];
        float wvA[4], wvB[4];
        #pragma unroll
        for (int h = 0; h < 4; h++) {
            wvA[h] = wr[(size_t)h*P + ixA];
            wvB[h] = wr[(size_t)h*P + ixB];
        }

        float v[4]  = {va.x, va.y, va.z, va.w};
        float u[4]  = {vb.x, vb.y, vb.z, vb.w};
        float accA[8] = {}, accB[8] = {};
        #pragma unroll
        for (int j = 0; j < 4; j++) {
            float m1a = v[j]*(1.f - w0A*e0[j]) + w0A*a0[j];
            float m1b = u[j]*(1.f - w0B*e0[j]) + w0B*a0[j];
            float m2a = m1a*(1.f - w1A*e1[j]) + w1A*a1[j];
            float m2b = m1b*(1.f - w1B*e1[j]) + w1B*a1[j];
            float sa = m2a*m2a, sb = m2b*m2b;
            accA[0] += m2a*k2[j];    accB[0] += m2b*k2[j];
            accA[1] += sa;           accB[1] += sb;
            accA[2] += m2a*k3[j];    accB[2] += m2b*k3[j];
            accA[3] += m2a*e2k3[j];  accB[3] += m2b*e2k3[j];
            accA[4] += sa*e2[j];     accB[4] += sb*e2[j];
            accA[5] += sa*e2sq[j];   accB[5] += sb*e2sq[j];
            accA[6] += m2a*a2[j];    accB[6] += m2b*a2[j];
            accA[7] += m2a*e2a2[j];  accB[7] += m2b*e2a2[j];
        }
        #pragma unroll
        for (int h = 0; h < 4; h++) {
            racc[h].x += wvA[h]*v[0] + wvB[h]*u[0];
            racc[h].y += wvA[h]*v[1] + wvB[h]*u[1];
            racc[h].z += wvA[h]*v[2] + wvB[h]*u[2];
            racc[h].w += wvA[h]*v[3] + wvB[h]*u[3];
        }

        #pragma unroll
        for (int o = 8; o > 0; o >>= 1) {
            #pragma unroll
            for (int r = 0; r < 8; r++) {
                accA[r] += __shfl_xor_sync(0xffffffffu, accA[r], o);
                accB[r] += __shfl_xor_sync(0xffffffffu, accB[r], o);
            }
        }
        if (l16 == 0) {
            dot2p[ixA] = accA[0];            dot2p[ixB] = accB[0];
            g_norm[ixA] = sqrtf(accA[1]);    g_norm[ixB] = sqrtf(accB[1]);
            #pragma unroll
            for (int r = 0; r < 6; r++) {
                g_base[(size_t)r*P + ixA] = accA[2+r];
                g_base[(size_t)r*P + ixB] = accB[2+r];
            }
        }
    }

    #pragma unroll
    for (int h = 0; h < 4; h++) sred[wid][h][lane] = racc[h];
    __syncthreads();
    int h = tid >> 6, m = tid & 63;
    int l = m >> 2, c = m & 3;
    float s = 0.f;
    #pragma unroll
    for (int w = 0; w < 8; w++) {
        s += ((const float*)&sred[w][h][l])[c];
        s += ((const float*)&sred[w][h][l + 16])[c];
    }
    ro_part[(size_t)(bc & 3)*B_*256 + (size_t)b*256 + h*64 + m] = s;
}

// ---------------- Sweep 2: all 4 head updates, original mem -> final mem ----------------
__global__ void __launch_bounds__(256) sweep2_kernel(
    const float* __restrict__ mem_in, float* __restrict__ mem_out,
    const float* __restrict__ wwp)
{
    int bc = blockIdx.x; int b = bc >> 2; int nb = (bc & 3) << 9;
    int tid = threadIdx.x, wid = tid >> 5, lane = tid & 31;
    int hw = lane >> 4, l16 = lane & 15;

    float e[4][4], a[4][4];
    #pragma unroll
    for (int h = 0; h < 4; h++) {
        const float* ph = g_wp + ((size_t)h*B_ + b)*PW_;
        #pragma unroll
        for (int j = 0; j < 4; j++) {
            int m = l16*4 + j;
            e[h][j] = sigmoidf(ph[70 + m]);
            a[h][j] = tanhf(ph[134 + m]);
        }
    }

    const size_t P = (size_t)B_*N_;
    for (int it = 0; it < 32; it += 4) {
        int r0 = it*16 + wid*2 + hw;
        size_t ix[4];
        float4 v[4];
        #pragma unroll
        for (int q = 0; q < 4; q++) {
            ix[q] = (size_t)b*N_ + nb + r0 + q*16;
            v[q] = *(const float4*)(mem_in + ix[q]*M_ + l16*4);
        }
        float w[4][4];
        #pragma unroll
        for (int q = 0; q < 4; q++)
            #pragma unroll
            for (int h = 0; h < 4; h++)
                w[q][h] = wwp[(size_t)h*P + ix[q]];

        #pragma unroll
        for (int q = 0; q < 4; q++) {
            float vv[4] = {v[q].x, v[q].y, v[q].z, v[q].w};
            #pragma unroll
            for (int j = 0; j < 4; j++) {
                float m = vv[j];
                #pragma unroll
                for (int h = 0; h < 4; h++)
                    m = m*(1.f - w[q][h]*e[h][j]) + w[q][h]*a[h][j];
                vv[j] = m;
            }
            *(float4*)(mem_out + ix[q]*M_ + l16*4) = make_float4(vv[0], vv[1], vv[2], vv[3]);
        }
    }
}

// ---------------- host launcher ----------------
extern "C" void kernel_launch(void* const* d_in, const int* in_sizes, int n_in,
                              void* d_out, int out_size)
{
    const float* ext    = (const float*)d_in[0];
    const float* pread  = (const float*)d_in[1];
    const float* prw    = (const float*)d_in[2];
    const float* pww    = (const float*)d_in[3];
    const float* mem    = (const float*)d_in[4];
    const float* ctrlW  = (const float*)d_in[5];
    const float* ctrlb  = (const float*)d_in[6];
    const float* readW  = (const float*)d_in[7];
    const float* readb  = (const float*)d_in[8];
    const float* writeW = (const float*)d_in[9];
    const float* writeb = (const float*)d_in[10];
    const float* outW   = (const float*)d_in[11];
    const float* outb   = (const float*)d_in[12];
    float* out = (float*)d_out;

    float *ctrl, *rp, *wp, *ropart;
    cudaGetSymbolAddress((void**)&ctrl,   g_ctrl);
    cudaGetSymbolAddress((void**)&rp,     g_rp);
    cudaGetSymbolAddress((void**)&wp,     g_wp);
    cudaGetSymbolAddress((void**)&ropart, g_ropart);

    float* o_mem = out + OUT_MEM;
    float* o_ro  = out + OUT_RO;
    float* o_rw  = out + OUT_RW;
    float* o_ww  = out + OUT_WW;

    // Controller GEMM with fused concat
    gemm_cat_kernel<<<dim3(8, 8), 256>>>(ext, 256, pread, 256, ctrlW, ctrlb, ctrl, 512);

    // All 8 head parameter GEMMs in one launch
    gemm_heads_kernel<<<dim3(4, 8, 8), 256>>>(ctrl, readW, readb, rp, writeW, writeb, wp);

    // Pass A: norms + dots (reads + write head0) + head-1 base dots
    passA_kernel<<<1024, 256>>>(mem);

    // Addressing: 4 read heads + write heads 0&1 (fused, poly for head 1) — 512 threads
    address5_kernel<<<dim3(256, 5), 512>>>(prw, pww, o_rw, o_ww);

    // Sweep 1: reads einsum + dot2/norm2 + head-3 bases (no memory write)
    sweep1_kernel<<<1024, 256>>>(mem, o_rw, o_ww, ropart);

    // Write heads 2 & 3 (fused, poly for head 3) — 512 threads
    addr23_kernel<<<256, 512>>>(pww, o_ww);

    // Sweep 2: apply all 4 head updates, original mem -> output mem
    sweep2_kernel<<<1024, 256>>>(mem, o_mem, o_ww);

    // Output GEMM with fused ro-sum (also writes o_ro)
    gemm_out_kernel<<<dim3(4, 8), 256>>>(ctrl, ropart, outW, outb, out, o_ro);
}

// round 11
// speedup vs baseline: 1.2860x; 1.1087x over previous
#include <cuda_runtime.h>
#include <math.h>

// Problem constants
constexpr int B_  = 256;
constexpr int N_  = 2048;
constexpr int M_  = 64;
constexpr int C_  = 512;
constexpr int PR_ = 70;   // M + 3 + SHIFT
constexpr int PW_ = 198;  // PR + 2M
constexpr float EPSF = 1e-8f;

// Output layout (floats): ntm_out, memory, read_out, new_read_w, new_write_w
constexpr size_t OUT_MEM = 65536;
constexpr size_t OUT_RO  = 33619968;
constexpr size_t OUT_RW  = 33685504;
constexpr size_t OUT_WW  = 35782656;

// ---------------- device scratch ----------------
__device__ float g_ctrl[B_*C_];
__device__ float g_rp  [4*B_*PR_];
__device__ float g_wp  [4*B_*PW_];
__device__ float g_dot [5*(size_t)B_*N_];
__device__ float g_norm[(size_t)B_*N_];
__device__ float g_base[6*(size_t)B_*N_];   // base dots: Da,Db,S1,S2,T0,T1
__device__ float g_ropart[4*B_*256];

__device__ __forceinline__ float softplusf(float x){ return x > 20.f ? x : log1pf(expf(x)); }
__device__ __forceinline__ float sigmoidf (float x){ return 1.f/(1.f+expf(-x)); }

// ---------------- GEMM body (proven): tile 32x64, K-step 32, 256 threads ----------------
__device__ __forceinline__ void gemm_body(
    const float* __restrict__ A0, int ca,
    const float* __restrict__ A1, int cb,
    const float* __restrict__ W, const float* __restrict__ bias,
    float* __restrict__ out, int Nc)
{
    int col0 = blockIdx.x * 64;
    if (col0 >= Nc) return;
    int row0 = blockIdx.y * 32;
    int K = ca + cb;

    __shared__ float As[32][33];
    __shared__ float Ws[32][64];
    int tid = threadIdx.x;
    int tx = tid & 15, ty = tid >> 4;
    float acc[2][4] = {};

    for (int k0 = 0; k0 < K; k0 += 32) {
        {
            int m  = tid >> 3;
            int kk = (tid & 7) * 4;
            int r = row0 + m, c = k0 + kk;
            float4 v;
            if (c < ca) v = *(const float4*)(A0 + (size_t)r*ca + c);
            else        v = *(const float4*)(A1 + (size_t)r*cb + (c - ca));
            As[m][kk] = v.x; As[m][kk+1] = v.y; As[m][kk+2] = v.z; As[m][kk+3] = v.w;
        }
        {
            int kk = tid >> 3;
            int n0 = (tid & 7) * 8;
            const float* wrow = W + (size_t)(k0 + kk)*Nc + col0 + n0;
            #pragma unroll
            for (int j = 0; j < 8; j++) {
                int gn = col0 + n0 + j;
                Ws[kk][n0 + j] = (gn < Nc) ? wrow[j] : 0.f;
            }
        }
        __syncthreads();
        #pragma unroll
        for (int kk = 0; kk < 32; kk++) {
            float a0 = As[ty*2 + 0][kk];
            float a1 = As[ty*2 + 1][kk];
            float4 w4 = *(const float4*)&Ws[kk][tx*4];
            acc[0][0] += a0*w4.x; acc[0][1] += a0*w4.y; acc[0][2] += a0*w4.z; acc[0][3] += a0*w4.w;
            acc[1][0] += a1*w4.x; acc[1][1] += a1*w4.y; acc[1][2] += a1*w4.z; acc[1][3] += a1*w4.w;
        }
        __syncthreads();
    }
    #pragma unroll
    for (int i = 0; i < 2; i++) {
        int gm = row0 + ty*2 + i;
        #pragma unroll
        for (int j = 0; j < 4; j++) {
            int gn = col0 + tx*4 + j;
            if (gn < Nc) out[(size_t)gm*Nc + gn] = acc[i][j] + bias[gn];
        }
    }
}

__global__ void gemm_cat_kernel(const float* __restrict__ A0, int ca,
                                const float* __restrict__ A1, int cb,
                                const float* __restrict__ W, const float* __restrict__ bias,
                                float* __restrict__ out, int Nc)
{
    gemm_body(A0, ca, A1, cb, W, bias, out, Nc);
}

__global__ void gemm_heads_kernel(const float* __restrict__ ctrl,
                                  const float* __restrict__ readW, const float* __restrict__ readb,
                                  float* __restrict__ rp,
                                  const float* __restrict__ writeW, const float* __restrict__ writeb,
                                  float* __restrict__ wp)
{
    int h = blockIdx.z;
    const float *W, *bias; float* out; int Nc;
    if (h < 4) {
        W = readW + (size_t)h*C_*PR_; bias = readb + h*PR_;
        out = rp + (size_t)h*B_*PR_;  Nc = PR_;
    } else {
        int g = h - 4;
        W = writeW + (size_t)g*C_*PW_; bias = writeb + g*PW_;
        out = wp + (size_t)g*B_*PW_;   Nc = PW_;
    }
    gemm_body(ctrl, C_, nullptr, 0, W, bias, out, Nc);
}

// ---------------- Pass A: thread-per-row, smem constants, zero shuffles ----------------
// grid 2048 = (b, eighthN=256 rows), 256 threads, one row per thread.
__global__ void __launch_bounds__(256) passA_kernel(const float* __restrict__ mem)
{
    int bc = blockIdx.x; int b = bc >> 3; int nb = (bc & 7) << 8;
    int tid = threadIdx.x;

    // constants: [0..4]=5 dot keys (4 read + wkey0); [5]=k1 [6]=e0*k1 [7]=e0 [8]=e0^2 [9]=a0 [10]=e0*a0
    __shared__ float cst[11][64];
    for (int i = tid; i < 5*64; i += 256) {
        int h = i >> 6, m = i & 63;
        cst[h][m] = (h < 4) ? g_rp[((size_t)h*B_ + b)*PR_ + m]
                            : g_wp[(size_t)b*PW_ + m];
    }
    if (tid < 64) {
        const float* wp0 = g_wp + (size_t)b*PW_;
        const float* wp1 = g_wp + ((size_t)B_ + b)*PW_;
        float e0 = sigmoidf(wp0[70 + tid]);
        float a0 = tanhf(wp0[134 + tid]);
        float k1 = wp1[tid];
        cst[5][tid]  = k1;
        cst[6][tid]  = e0*k1;
        cst[7][tid]  = e0;
        cst[8][tid]  = e0*e0;
        cst[9][tid]  = a0;
        cst[10][tid] = e0*a0;
    }
    __syncthreads();

    size_t ix = (size_t)b*N_ + nb + tid;
    const float4* rp4 = (const float4*)(mem + ix*M_);

    float acc[12] = {};
    #pragma unroll
    for (int mb = 0; mb < 16; mb++) {
        float4 d = rp4[mb];
        float4 c[11];
        #pragma unroll
        for (int ci = 0; ci < 11; ci++)
            c[ci] = *(const float4*)&cst[ci][mb*4];
        float vv[4] = {d.x, d.y, d.z, d.w};
        #pragma unroll
        for (int j = 0; j < 4; j++) {
            float v  = vv[j];
            float vs = v*v;
            acc[0]  += vs;
            acc[1]  += v * ((const float*)&c[0])[j];
            acc[2]  += v * ((const float*)&c[1])[j];
            acc[3]  += v * ((const float*)&c[2])[j];
            acc[4]  += v * ((const float*)&c[3])[j];
            acc[5]  += v * ((const float*)&c[4])[j];
            acc[6]  += v * ((const float*)&c[5])[j];   // Da
            acc[7]  += v * ((const float*)&c[6])[j];   // Db
            acc[8]  += vs * ((const float*)&c[7])[j];  // S1
            acc[9]  += vs * ((const float*)&c[8])[j];  // S2
            acc[10] += v * ((const float*)&c[9])[j];   // T0
            acc[11] += v * ((const float*)&c[10])[j];  // T1
        }
    }

    const size_t P = (size_t)B_*N_;
    g_norm[ix] = sqrtf(acc[0]);
    #pragma unroll
    for (int h = 0; h < 5; h++) g_dot[(size_t)h*P + ix] = acc[1+h];
    #pragma unroll
    for (int r = 0; r < 6; r++) g_base[(size_t)r*P + ix] = acc[6+r];
}

// ---------------- block reduction helpers (512 threads) ----------------
__device__ __forceinline__ float block_reduce_sum512(float v, float* sbuf)
{
    int tid = threadIdx.x;
    #pragma unroll
    for (int o = 16; o > 0; o >>= 1) v += __shfl_xor_sync(0xffffffffu, v, o);
    if ((tid & 31) == 0) sbuf[tid >> 5] = v;
    __syncthreads();
    if (tid < 32) {
        float x = (tid < 16) ? sbuf[tid] : 0.f;
        #pragma unroll
        for (int o = 8; o > 0; o >>= 1) x += __shfl_xor_sync(0xffffffffu, x, o);
        if (tid == 0) sbuf[0] = x;
    }
    __syncthreads();
    float r = sbuf[0];
    __syncthreads();
    return r;
}

__device__ __forceinline__ float block_reduce_max512(float v, float* sbuf)
{
    int tid = threadIdx.x;
    #pragma unroll
    for (int o = 16; o > 0; o >>= 1) v = fmaxf(v, __shfl_xor_sync(0xffffffffu, v, o));
    if ((tid & 31) == 0) sbuf[tid >> 5] = v;
    __syncthreads();
    if (tid < 32) {
        float x = (tid < 16) ? sbuf[tid] : -3.4e38f;
        #pragma unroll
        for (int o = 8; o > 0; o >>= 1) x = fmaxf(x, __shfl_xor_sync(0xffffffffu, x, o));
        if (tid == 0) sbuf[0] = x;
    }
    __syncthreads();
    float r = sbuf[0];
    __syncthreads();
    return r;
}

// ---------------- addressing tail (512 threads, 4 items/thread) ----------------
__device__ __forceinline__ void address_tail(
    float* x, float g, float s0, float s1, float s2, float gamma,
    const float* __restrict__ wpb, float* __restrict__ woutb,
    float* wg, float* rbuf)
{
    int tid = threadIdx.x;
    float mx = fmaxf(fmaxf(x[0], x[1]), fmaxf(x[2], x[3]));
    float bmax = block_reduce_max512(mx, rbuf);
    float lsum = 0.f;
    #pragma unroll
    for (int i = 0; i < 4; i++) {
        float e = __expf(x[i] - bmax);
        wg[tid + i*512] = e;
        lsum += e;
    }
    float bsum = block_reduce_sum512(lsum, rbuf);
    float inv = 1.f / bsum;
    #pragma unroll
    for (int i = 0; i < 4; i++) {
        int n = tid + i*512;
        wg[n] = g * (wg[n]*inv) + (1.f-g) * wpb[n];
    }
    __syncthreads();
    float wpow[4];
    lsum = 0.f;
    #pragma unroll
    for (int i = 0; i < 4; i++) {
        int n = tid + i*512;
        float ws = s0*wg[(n+1)&(N_-1)] + s1*wg[n] + s2*wg[(n-1)&(N_-1)];
        float t = __powf(ws + EPSF, gamma);
        wpow[i] = t;
        lsum += t;
    }
    float psum = block_reduce_sum512(lsum, rbuf);
    float ip = 1.f / psum;
    #pragma unroll
    for (int i = 0; i < 4; i++) {
        float wv = wpow[i]*ip;
        woutb[tid + i*512] = wv;
        x[i] = wv;
    }
}

__device__ __forceinline__ void head_scalars(const float* __restrict__ p, float ksum, float* sc)
{
    sc[0] = sqrtf(ksum);
    sc[1] = softplusf(p[64]);
    sc[2] = sigmoidf(p[65]);
    float a0 = p[66], a1 = p[67], a2 = p[68];
    float mx = fmaxf(a0, fmaxf(a1, a2));
    float e0 = expf(a0-mx), e1 = expf(a1-mx), e2 = expf(a2-mx);
    float es = e0 + e1 + e2;
    sc[3] = e0/es; sc[4] = e1/es; sc[5] = e2/es;
    sc[6] = 1.f + softplusf(p[69]);
}

// poly eval (512 threads, 4 items/thread): x[i] = beta * cos for next head
__device__ __forceinline__ void poly_x(
    float* x, const float* wdone, size_t base,
    float CC, float UU, float knorm, float beta)
{
    int tid = threadIdx.x;
    const size_t P = (size_t)B_*N_;
    const float* nrmp = g_norm + base;
    #pragma unroll
    for (int i = 0; i < 4; i++) {
        int n = tid + i*512;
        float w  = wdone[i];
        float Da = g_base[0*P + base + n];
        float Db = g_base[1*P + base + n];
        float S1 = g_base[2*P + base + n];
        float S2 = g_base[3*P + base + n];
        float T0 = g_base[4*P + base + n];
        float T1 = g_base[5*P + base + n];
        float nr = nrmp[n];
        float S0 = nr*nr;
        float dotv = Da - w*Db + w*CC;
        float w2 = w*w;
        float nsq = S0 - 2.f*w*S1 + w2*S2 + 2.f*w*T0 - 2.f*w2*T1 + w2*UU;
        float nn = sqrtf(fmaxf(nsq, 0.f));
        x[i] = beta * (dotv / (nn*knorm + EPSF));
    }
}

// ---------------- fused addressing: 4 read heads (y=0..3) + write heads 0&1 (y=4) -------------
__global__ void __launch_bounds__(512) address5_kernel(
    const float* __restrict__ prw,
    const float* __restrict__ pww,
    float* __restrict__ o_rw,
    float* __restrict__ o_ww)
{
    __shared__ float wg[2048];
    __shared__ float rbuf[32];
    __shared__ float sc[16];
    int b = blockIdx.x, h = blockIdx.y, tid = threadIdx.x;
    size_t base = (size_t)b*N_;
    const size_t P = (size_t)B_*N_;

    if (h < 4) {
        const float* p = g_rp + ((size_t)h*B_ + b)*PR_;
        float kv = 0.f;
        if (tid < 64) { float xx = p[tid]; kv = xx*xx; }
        float ksum = block_reduce_sum512(kv, rbuf);
        if (tid == 0) head_scalars(p, ksum, sc);
        __syncthreads();
        float knorm = sc[0], beta = sc[1], g = sc[2];
        float s0 = sc[3], s1 = sc[4], s2 = sc[5], gamma = sc[6];

        const float* dotb = g_dot + (size_t)h*P + base;
        const float* nrmb = g_norm + base;
        float x[4];
        #pragma unroll
        for (int i = 0; i < 4; i++) {
            int n = tid + i*512;
            x[i] = beta * (dotb[n] / (nrmb[n]*knorm + EPSF));
        }
        address_tail(x, g, s0, s1, s2, gamma,
                     prw + (size_t)h*P + base, o_rw + (size_t)h*P + base, wg, rbuf);
    } else {
        const float* p0 = g_wp + (size_t)b*PW_;
        const float* p1 = g_wp + ((size_t)1*B_ + b)*PW_;
        float kv0 = 0.f, kv1 = 0.f, c1 = 0.f, c2 = 0.f;
        if (tid < 64) {
            float k0 = p0[tid], k1 = p1[tid];
            float a0 = tanhf(p0[134 + tid]);
            kv0 = k0*k0; kv1 = k1*k1; c1 = a0*k1; c2 = a0*a0;
        }
        float ks0 = block_reduce_sum512(kv0, rbuf);
        float ks1 = block_reduce_sum512(kv1, rbuf);
        float Cc  = block_reduce_sum512(c1, rbuf);
        float U   = block_reduce_sum512(c2, rbuf);
        if (tid == 0) {
            head_scalars(p0, ks0, sc);
            head_scalars(p1, ks1, sc + 7);
            sc[14] = Cc; sc[15] = U;
        }
        __syncthreads();

        float knorm = sc[0], beta = sc[1], g = sc[2];
        float s0 = sc[3], s1 = sc[4], s2 = sc[5], gamma = sc[6];
        const float* dotb = g_dot + 4*P + base;
        const float* nrmb = g_norm + base;
        float x[4];
        #pragma unroll
        for (int i = 0; i < 4; i++) {
            int n = tid + i*512;
            x[i] = beta * (dotb[n] / (nrmb[n]*knorm + EPSF));
        }
        address_tail(x, g, s0, s1, s2, gamma, pww + base, o_ww + base, wg, rbuf);
        __syncthreads();
        float y[4];
        poly_x(y, x, base, sc[14], sc[15], sc[7], sc[8]);
        address_tail(y, sc[9], sc[10], sc[11], sc[12], sc[13],
                     pww + P + base, o_ww + P + base, wg, rbuf);
    }
}

// ---------------- fused write heads 2 & 3 ----------------
__global__ void __launch_bounds__(512) addr23_kernel(
    const float* __restrict__ pww,
    float* __restrict__ o_ww)
{
    __shared__ float wg[2048];
    __shared__ float rbuf[32];
    __shared__ float sc[16];
    int b = blockIdx.x, tid = threadIdx.x;
    size_t base = (size_t)b*N_;
    const size_t P = (size_t)B_*N_;

    const float* p2 = g_wp + ((size_t)2*B_ + b)*PW_;
    const float* p3 = g_wp + ((size_t)3*B_ + b)*PW_;
    float kv2 = 0.f, kv3 = 0.f, c1 = 0.f, c2 = 0.f;
    if (tid < 64) {
        float k2 = p2[tid], k3 = p3[tid];
        float a2 = tanhf(p2[134 + tid]);
        kv2 = k2*k2; kv3 = k3*k3; c1 = a2*k3; c2 = a2*a2;
    }
    float ks2 = block_reduce_sum512(kv2, rbuf);
    float ks3 = block_reduce_sum512(kv3, rbuf);
    float Cc  = block_reduce_sum512(c1, rbuf);
    float U   = block_reduce_sum512(c2, rbuf);
    if (tid == 0) {
        head_scalars(p2, ks2, sc);
        head_scalars(p3, ks3, sc + 7);
        sc[14] = Cc; sc[15] = U;
    }
    __syncthreads();

    float knorm = sc[0], beta = sc[1], g = sc[2];
    float s0 = sc[3], s1 = sc[4], s2 = sc[5], gamma = sc[6];
    const float* dotb = g_dot + 4*P + base;
    const float* nrmb = g_norm + base;
    float x[4];
    #pragma unroll
    for (int i = 0; i < 4; i++) {
        int n = tid + i*512;
        x[i] = beta * (dotb[n] / (nrmb[n]*knorm + EPSF));
    }
    address_tail(x, g, s0, s1, s2, gamma, pww + 2*P + base, o_ww + 2*P + base, wg, rbuf);
    __syncthreads();
    float y[4];
    poly_x(y, x, base, sc[14], sc[15], sc[7], sc[8]);
    address_tail(y, sc[9], sc[10], sc[11], sc[12], sc[13],
                 pww + 3*P + base, o_ww + 3*P + base, wg, rbuf);
}

// ---------------- Sweep 1: reads einsum + dot2/norm2 + head-3 bases (no memory write) ---------
__global__ void __launch_bounds__(256) sweep1_kernel(
    const float* __restrict__ mem_in,
    const float* __restrict__ wr,
    const float* __restrict__ wwp,
    float* __restrict__ ro_part)
{
    int bc = blockIdx.x; int b = bc >> 2; int nb = (bc & 3) << 9;
    int tid = threadIdx.x, wid = tid >> 5, lane = tid & 31;
    int hw = lane >> 4, l16 = lane & 15;

    __shared__ float4 sred[8][4][32];

    const float* p0 = g_wp + (size_t)b*PW_;
    const float* p1 = g_wp + ((size_t)1*B_ + b)*PW_;
    const float* p2 = g_wp + ((size_t)2*B_ + b)*PW_;
    const float* p3 = g_wp + ((size_t)3*B_ + b)*PW_;
    float e0[4], a0[4], e1[4], a1[4], k2[4], e2[4], a2[4], k3[4];
    float e2k3[4], e2sq[4], e2a2[4];
    #pragma unroll
    for (int j = 0; j < 4; j++) {
        int m = l16*4 + j;
        e0[j] = sigmoidf(p0[70 + m]);  a0[j] = tanhf(p0[134 + m]);
        e1[j] = sigmoidf(p1[70 + m]);  a1[j] = tanhf(p1[134 + m]);
        k2[j] = p2[m];
        e2[j] = sigmoidf(p2[70 + m]);  a2[j] = tanhf(p2[134 + m]);
        k3[j] = p3[m];
        e2k3[j] = e2[j]*k3[j];
        e2sq[j] = e2[j]*e2[j];
        e2a2[j] = e2[j]*a2[j];
    }

    float4 racc[4] = {{0,0,0,0},{0,0,0,0},{0,0,0,0},{0,0,0,0}};
    const size_t P = (size_t)B_*N_;
    float* dot2p = g_dot + 4*P;

    for (int it = 0; it < 32; it += 2) {
        int rA = it*16 + wid*2 + hw;
        int rB = rA + 16;
        size_t ixA = (size_t)b*N_ + nb + rA;
        size_t ixB = (size_t)b*N_ + nb + rB;

        float4 va = *(const float4*)(mem_in + ixA*M_ + l16*4);
        float4 vb = *(const float4*)(mem_in + ixB*M_ + l16*4);
        float w0A = wwp[ixA],     w0B = wwp[ixB];
        float w1A = wwp[P + ixA], w1B = wwp[P + ixB];
        float wvA[4], wvB[4];
        #pragma unroll
        for (int h = 0; h < 4; h++) {
            wvA[h] = wr[(size_t)h*P + ixA];
            wvB[h] = wr[(size_t)h*P + ixB];
        }

        float v[4]  = {va.x, va.y, va.z, va.w};
        float u[4]  = {vb.x, vb.y, vb.z, vb.w};
        float accA[8] = {}, accB[8] = {};
        #pragma unroll
        for (int j = 0; j < 4; j++) {
            float m1a = v[j]*(1.f - w0A*e0[j]) + w0A*a0[j];
            float m1b = u[j]*(1.f - w0B*e0[j]) + w0B*a0[j];
            float m2a = m1a*(1.f - w1A*e1[j]) + w1A*a1[j];
            float m2b = m1b*(1.f - w1B*e1[j]) + w1B*a1[j];
            float sa = m2a*m2a, sb = m2b*m2b;
            accA[0] += m2a*k2[j];    accB[0] += m2b*k2[j];
            accA[1] += sa;           accB[1] += sb;
            accA[2] += m2a*k3[j];    accB[2] += m2b*k3[j];
            accA[3] += m2a*e2k3[j];  accB[3] += m2b*e2k3[j];
            accA[4] += sa*e2[j];     accB[4] += sb*e2[j];
            accA[5] += sa*e2sq[j];   accB[5] += sb*e2sq[j];
            accA[6] += m2a*a2[j];    accB[6] += m2b*a2[j];
            accA[7] += m2a*e2a2[j];  accB[7] += m2b*e2a2[j];
        }
        #pragma unroll
        for (int h = 0; h < 4; h++) {
            racc[h].x += wvA[h]*v[0] + wvB[h]*u[0];
            racc[h].y += wvA[h]*v[1] + wvB[h]*u[1];
            racc[h].z += wvA[h]*v[2] + wvB[h]*u[2];
            racc[h].w += wvA[h]*v[3] + wvB[h]*u[3];
        }

        #pragma unroll
        for (int o = 8; o > 0; o >>= 1) {
            #pragma unroll
            for (int r = 0; r < 8; r++) {
                accA[r] += __shfl_xor_sync(0xffffffffu, accA[r], o);
                accB[r] += __shfl_xor_sync(0xffffffffu, accB[r], o);
            }
        }
        if (l16 == 0) {
            dot2p[ixA] = accA[0];            dot2p[ixB] = accB[0];
            g_norm[ixA] = sqrtf(accA[1]);    g_norm[ixB] = sqrtf(accB[1]);
            #pragma unroll
            for (int r = 0; r < 6; r++) {
                g_base[(size_t)r*P + ixA] = accA[2+r];
                g_base[(size_t)r*P + ixB] = accB[2+r];
            }
        }
    }

    #pragma unroll
    for (int h = 0; h < 4; h++) sred[wid][h][lane] = racc[h];
    __syncthreads();
    int h = tid >> 6, m = tid & 63;
    int l = m >> 2, c = m & 3;
    float s = 0.f;
    #pragma unroll
    for (int w = 0; w < 8; w++) {
        s += ((const float*)&sred[w][h][l])[c];
        s += ((const float*)&sred[w][h][l + 16])[c];
    }
    ro_part[(size_t)(bc & 3)*B_*256 + (size_t)b*256 + h*64 + m] = s;
}

// ---------------- Fused tail: sweep2 (blocks 0..1023) + output GEMM (blocks 1024..1055) -------
__global__ void __launch_bounds__(256) tail_kernel(
    const float* __restrict__ mem_in, float* __restrict__ mem_out,
    const float* __restrict__ wwp,
    const float* __restrict__ ctrl, const float* __restrict__ part,
    const float* __restrict__ W, const float* __restrict__ bias,
    float* __restrict__ out, float* __restrict__ o_ro)
{
    __shared__ float As[32][33];
    __shared__ float Ws[32][64];
    int tid = threadIdx.x;

    if (blockIdx.x < 1024) {
        // ---- sweep2: all 4 head updates, original mem -> final mem ----
        int bc = blockIdx.x; int b = bc >> 2; int nb = (bc & 3) << 9;
        int wid = tid >> 5, lane = tid & 31;
        int hw = lane >> 4, l16 = lane & 15;

        float e[4][4], a[4][4];
        #pragma unroll
        for (int h = 0; h < 4; h++) {
            const float* ph = g_wp + ((size_t)h*B_ + b)*PW_;
            #pragma unroll
            for (int j = 0; j < 4; j++) {
                int m = l16*4 + j;
                e[h][j] = sigmoidf(ph[70 + m]);
                a[h][j] = tanhf(ph[134 + m]);
            }
        }

        const size_t P = (size_t)B_*N_;
        for (int it = 0; it < 32; it += 4) {
            int r0 = it*16 + wid*2 + hw;
            size_t ix[4];
            float4 v[4];
            #pragma unroll
            for (int q = 0; q < 4; q++) {
                ix[q] = (size_t)b*N_ + nb + r0 + q*16;
                v[q] = *(const float4*)(mem_in + ix[q]*M_ + l16*4);
            }
            float w[4][4];
            #pragma unroll
            for (int q = 0; q < 4; q++)
                #pragma unroll
                for (int h = 0; h < 4; h++)
                    w[q][h] = wwp[(size_t)h*P + ix[q]];

            #pragma unroll
            for (int q = 0; q < 4; q++) {
                float vv[4] = {v[q].x, v[q].y, v[q].z, v[q].w};
                #pragma unroll
                for (int j = 0; j < 4; j++) {
                    float m = vv[j];
                    #pragma unroll
                    for (int h = 0; h < 4; h++)
                        m = m*(1.f - w[q][h]*e[h][j]) + w[q][h]*a[h][j];
                    vv[j] = m;
                }
                *(float4*)(mem_out + ix[q]*M_ + l16*4) = make_float4(vv[0], vv[1], vv[2], vv[3]);
            }
        }
    } else {
        // ---- output GEMM with fused ro-sum: A = [ctrl | sum4(ro_part)] ----
        constexpr int Nc = 256;
        int t = blockIdx.x - 1024;      // 0..31
        int cx = t & 3, ry = t >> 2;    // col tile 0..3, row tile 0..7
        int col0 = cx * 64;
        int row0 = ry * 32;
        int tx = tid & 15, ty = tid >> 4;
        float acc[2][4] = {};

        for (int k0 = 0; k0 < 768; k0 += 32) {
            {
                int m  = tid >> 3;
                int kk = (tid & 7) * 4;
                int r = row0 + m, c = k0 + kk;
                float4 v;
                if (c < 512) {
                    v = *(const float4*)(ctrl + (size_t)r*512 + c);
                } else {
                    int cc = c - 512;
                    const float* p = part + (size_t)r*256 + cc;
                    float4 v0 = *(const float4*)p;
                    float4 v1 = *(const float4*)(p + (size_t)B_*256);
                    float4 v2 = *(const float4*)(p + (size_t)2*B_*256);
                    float4 v3 = *(const float4*)(p + (size_t)3*B_*256);
                    v.x = (v0.x + v1.x) + (v2.x + v3.x);
                    v.y = (v0.y + v1.y) + (v2.y + v3.y);
                    v.z = (v0.z + v1.z) + (v2.z + v3.z);
                    v.w = (v0.w + v1.w) + (v2.w + v3.w);
                    if (cx == 0)
                        *(float4*)(o_ro + (size_t)r*256 + cc) = v;
                }
                As[m][kk] = v.x; As[m][kk+1] = v.y; As[m][kk+2] = v.z; As[m][kk+3] = v.w;
            }
            {
                int kk = tid >> 3;
                int n0 = (tid & 7) * 8;
                const float* wrow = W + (size_t)(k0 + kk)*Nc + col0 + n0;
                #pragma unroll
                for (int j = 0; j < 8; j++)
                    Ws[kk][n0 + j] = wrow[j];
            }
            __syncthreads();
            #pragma unroll
            for (int kk = 0; kk < 32; kk++) {
                float a0 = As[ty*2 + 0][kk];
                float a1 = As[ty*2 + 1][kk];
                float4 w4 = *(const float4*)&Ws[kk][tx*4];
                acc[0][0] += a0*w4.x; acc[0][1] += a0*w4.y; acc[0][2] += a0*w4.z; acc[0][3] += a0*w4.w;
                acc[1][0] += a1*w4.x; acc[1][1] += a1*w4.y; acc[1][2] += a1*w4.z; acc[1][3] += a1*w4.w;
            }
            __syncthreads();
        }
        #pragma unroll
        for (int i = 0; i < 2; i++) {
            int gm = row0 + ty*2 + i;
            #pragma unroll
            for (int j = 0; j < 4; j++) {
                int gn = col0 + tx*4 + j;
                out[(size_t)gm*Nc + gn] = acc[i][j] + bias[gn];
            }
        }
    }
}

// ---------------- host launcher ----------------
extern "C" void kernel_launch(void* const* d_in, const int* in_sizes, int n_in,
                              void* d_out, int out_size)
{
    const float* ext    = (const float*)d_in[0];
    const float* pread  = (const float*)d_in[1];
    const float* prw    = (const float*)d_in[2];
    const float* pww    = (const float*)d_in[3];
    const float* mem    = (const float*)d_in[4];
    const float* ctrlW  = (const float*)d_in[5];
    const float* ctrlb  = (const float*)d_in[6];
    const float* readW  = (const float*)d_in[7];
    const float* readb  = (const float*)d_in[8];
    const float* writeW = (const float*)d_in[9];
    const float* writeb = (const float*)d_in[10];
    const float* outW   = (const float*)d_in[11];
    const float* outb   = (const float*)d_in[12];
    float* out = (float*)d_out;

    float *ctrl, *rp, *wp, *ropart;
    cudaGetSymbolAddress((void**)&ctrl,   g_ctrl);
    cudaGetSymbolAddress((void**)&rp,     g_rp);
    cudaGetSymbolAddress((void**)&wp,     g_wp);
    cudaGetSymbolAddress((void**)&ropart, g_ropart);

    float* o_mem = out + OUT_MEM;
    float* o_ro  = out + OUT_RO;
    float* o_rw  = out + OUT_RW;
    float* o_ww  = out + OUT_WW;

    // Controller GEMM with fused concat
    gemm_cat_kernel<<<dim3(8, 8), 256>>>(ext, 256, pread, 256, ctrlW, ctrlb, ctrl, 512);

    // All 8 head parameter GEMMs in one launch
    gemm_heads_kernel<<<dim3(4, 8, 8), 256>>>(ctrl, readW, readb, rp, writeW, writeb, wp);

    // Pass A: norms + dots (reads + write head0) + head-1 base dots (thread-per-row)
    passA_kernel<<<2048, 256>>>(mem);

    // Addressing: 4 read heads + write heads 0&1 (fused, poly for head 1)
    address5_kernel<<<dim3(256, 5), 512>>>(prw, pww, o_rw, o_ww);

    // Sweep 1: reads einsum + dot2/norm2 + head-3 bases (no memory write)
    sweep1_kernel<<<1024, 256>>>(mem, o_rw, o_ww, ropart);

    // Write heads 2 & 3 (fused, poly for head 3)
    addr23_kernel<<<256, 512>>>(pww, o_ww);

    // Fused tail: sweep2 (all 4 head updates) + output GEMM (with ro-sum)
    tail_kernel<<<1056, 256>>>(mem, o_mem, o_ww, ctrl, ropart, outW, outb, out, o_ro);
}

// round 12
// speedup vs baseline: 1.4165x; 1.1015x over previous
#include <cuda_runtime.h>
#include <math.h>

// Problem constants
constexpr int B_  = 256;
constexpr int N_  = 2048;
constexpr int M_  = 64;
constexpr int C_  = 512;
constexpr int PR_ = 70;   // M + 3 + SHIFT
constexpr int PW_ = 198;  // PR + 2M
constexpr float EPSF = 1e-8f;

// Output layout (floats): ntm_out, memory, read_out, new_read_w, new_write_w
constexpr size_t OUT_MEM = 65536;
constexpr size_t OUT_RO  = 33619968;
constexpr size_t OUT_RW  = 33685504;
constexpr size_t OUT_WW  = 35782656;

// ---------------- device scratch ----------------
__device__ float g_ctrl[B_*C_];
__device__ float g_rp  [4*B_*PR_];
__device__ float g_wp  [4*B_*PW_];
__device__ float g_dot [5*(size_t)B_*N_];
__device__ float g_norm[(size_t)B_*N_];
__device__ float g_base[6*(size_t)B_*N_];   // base dots: Da,Db,S1,S2,T0,T1
__device__ float g_ropart[8*B_*256];

__device__ __forceinline__ float softplusf(float x){ return x > 20.f ? x : log1pf(expf(x)); }
__device__ __forceinline__ float sigmoidf (float x){ return 1.f/(1.f+expf(-x)); }

// ---------------- GEMM body (proven): tile 32x64, K-step 32, 256 threads ----------------
__device__ __forceinline__ void gemm_body(
    const float* __restrict__ A0, int ca,
    const float* __restrict__ A1, int cb,
    const float* __restrict__ W, const float* __restrict__ bias,
    float* __restrict__ out, int Nc)
{
    int col0 = blockIdx.x * 64;
    if (col0 >= Nc) return;
    int row0 = blockIdx.y * 32;
    int K = ca + cb;

    __shared__ float As[32][33];
    __shared__ float Ws[32][64];
    int tid = threadIdx.x;
    int tx = tid & 15, ty = tid >> 4;
    float acc[2][4] = {};

    for (int k0 = 0; k0 < K; k0 += 32) {
        {
            int m  = tid >> 3;
            int kk = (tid & 7) * 4;
            int r = row0 + m, c = k0 + kk;
            float4 v;
            if (c < ca) v = *(const float4*)(A0 + (size_t)r*ca + c);
            else        v = *(const float4*)(A1 + (size_t)r*cb + (c - ca));
            As[m][kk] = v.x; As[m][kk+1] = v.y; As[m][kk+2] = v.z; As[m][kk+3] = v.w;
        }
        {
            int kk = tid >> 3;
            int n0 = (tid & 7) * 8;
            const float* wrow = W + (size_t)(k0 + kk)*Nc + col0 + n0;
            #pragma unroll
            for (int j = 0; j < 8; j++) {
                int gn = col0 + n0 + j;
                Ws[kk][n0 + j] = (gn < Nc) ? wrow[j] : 0.f;
            }
        }
        __syncthreads();
        #pragma unroll
        for (int kk = 0; kk < 32; kk++) {
            float a0 = As[ty*2 + 0][kk];
            float a1 = As[ty*2 + 1][kk];
            float4 w4 = *(const float4*)&Ws[kk][tx*4];
            acc[0][0] += a0*w4.x; acc[0][1] += a0*w4.y; acc[0][2] += a0*w4.z; acc[0][3] += a0*w4.w;
            acc[1][0] += a1*w4.x; acc[1][1] += a1*w4.y; acc[1][2] += a1*w4.z; acc[1][3] += a1*w4.w;
        }
        __syncthreads();
    }
    #pragma unroll
    for (int i = 0; i < 2; i++) {
        int gm = row0 + ty*2 + i;
        #pragma unroll
        for (int j = 0; j < 4; j++) {
            int gn = col0 + tx*4 + j;
            if (gn < Nc) out[(size_t)gm*Nc + gn] = acc[i][j] + bias[gn];
        }
    }
}

__global__ void gemm_cat_kernel(const float* __restrict__ A0, int ca,
                                const float* __restrict__ A1, int cb,
                                const float* __restrict__ W, const float* __restrict__ bias,
                                float* __restrict__ out, int Nc)
{
    gemm_body(A0, ca, A1, cb, W, bias, out, Nc);
}

__global__ void gemm_heads_kernel(const float* __restrict__ ctrl,
                                  const float* __restrict__ readW, const float* __restrict__ readb,
                                  float* __restrict__ rp,
                                  const float* __restrict__ writeW, const float* __restrict__ writeb,
                                  float* __restrict__ wp)
{
    int h = blockIdx.z;
    const float *W, *bias; float* out; int Nc;
    if (h < 4) {
        W = readW + (size_t)h*C_*PR_; bias = readb + h*PR_;
        out = rp + (size_t)h*B_*PR_;  Nc = PR_;
    } else {
        int g = h - 4;
        W = writeW + (size_t)g*C_*PW_; bias = writeb + g*PW_;
        out = wp + (size_t)g*B_*PW_;   Nc = PW_;
    }
    gemm_body(ctrl, C_, nullptr, 0, W, bias, out, Nc);
}

// ---------------- Pass A: thread-per-row, smem constants, zero shuffles ----------------
__global__ void __launch_bounds__(256) passA_kernel(const float* __restrict__ mem)
{
    int bc = blockIdx.x; int b = bc >> 3; int nb = (bc & 7) << 8;
    int tid = threadIdx.x;

    // constants: [0..4]=5 dot keys; [5]=k1 [6]=e0*k1 [7]=e0 [8]=e0^2 [9]=a0 [10]=e0*a0
    __shared__ float cst[11][64];
    for (int i = tid; i < 5*64; i += 256) {
        int h = i >> 6, m = i & 63;
        cst[h][m] = (h < 4) ? g_rp[((size_t)h*B_ + b)*PR_ + m]
                            : g_wp[(size_t)b*PW_ + m];
    }
    if (tid < 64) {
        const float* wp0 = g_wp + (size_t)b*PW_;
        const float* wp1 = g_wp + ((size_t)B_ + b)*PW_;
        float e0 = sigmoidf(wp0[70 + tid]);
        float a0 = tanhf(wp0[134 + tid]);
        float k1 = wp1[tid];
        cst[5][tid]  = k1;
        cst[6][tid]  = e0*k1;
        cst[7][tid]  = e0;
        cst[8][tid]  = e0*e0;
        cst[9][tid]  = a0;
        cst[10][tid] = e0*a0;
    }
    __syncthreads();

    size_t ix = (size_t)b*N_ + nb + tid;
    const float4* rp4 = (const float4*)(mem + ix*M_);

    float acc[12] = {};
    #pragma unroll
    for (int mb = 0; mb < 16; mb++) {
        float4 d = rp4[mb];
        float4 c[11];
        #pragma unroll
        for (int ci = 0; ci < 11; ci++)
            c[ci] = *(const float4*)&cst[ci][mb*4];
        float vv[4] = {d.x, d.y, d.z, d.w};
        #pragma unroll
        for (int j = 0; j < 4; j++) {
            float v  = vv[j];
            float vs = v*v;
            acc[0]  += vs;
            acc[1]  += v * ((const float*)&c[0])[j];
            acc[2]  += v * ((const float*)&c[1])[j];
            acc[3]  += v * ((const float*)&c[2])[j];
            acc[4]  += v * ((const float*)&c[3])[j];
            acc[5]  += v * ((const float*)&c[4])[j];
            acc[6]  += v * ((const float*)&c[5])[j];
            acc[7]  += v * ((const float*)&c[6])[j];
            acc[8]  += vs * ((const float*)&c[7])[j];
            acc[9]  += vs * ((const float*)&c[8])[j];
            acc[10] += v * ((const float*)&c[9])[j];
            acc[11] += v * ((const float*)&c[10])[j];
        }
    }

    const size_t P = (size_t)B_*N_;
    g_norm[ix] = sqrtf(acc[0]);
    #pragma unroll
    for (int h = 0; h < 5; h++) g_dot[(size_t)h*P + ix] = acc[1+h];
    #pragma unroll
    for (int r = 0; r < 6; r++) g_base[(size_t)r*P + ix] = acc[6+r];
}

// ---------------- block reduction helpers (512 threads) ----------------
__device__ __forceinline__ float block_reduce_sum512(float v, float* sbuf)
{
    int tid = threadIdx.x;
    #pragma unroll
    for (int o = 16; o > 0; o >>= 1) v += __shfl_xor_sync(0xffffffffu, v, o);
    if ((tid & 31) == 0) sbuf[tid >> 5] = v;
    __syncthreads();
    if (tid < 32) {
        float x = (tid < 16) ? sbuf[tid] : 0.f;
        #pragma unroll
        for (int o = 8; o > 0; o >>= 1) x += __shfl_xor_sync(0xffffffffu, x, o);
        if (tid == 0) sbuf[0] = x;
    }
    __syncthreads();
    float r = sbuf[0];
    __syncthreads();
    return r;
}

__device__ __forceinline__ float block_reduce_max512(float v, float* sbuf)
{
    int tid = threadIdx.x;
    #pragma unroll
    for (int o = 16; o > 0; o >>= 1) v = fmaxf(v, __shfl_xor_sync(0xffffffffu, v, o));
    if ((tid & 31) == 0) sbuf[tid >> 5] = v;
    __syncthreads();
    if (tid < 32) {
        float x = (tid < 16) ? sbuf[tid] : -3.4e38f;
        #pragma unroll
        for (int o = 8; o > 0; o >>= 1) x = fmaxf(x, __shfl_xor_sync(0xffffffffu, x, o));
        if (tid == 0) sbuf[0] = x;
    }
    __syncthreads();
    float r = sbuf[0];
    __syncthreads();
    return r;
}

// ---------------- addressing tail (512 threads, 4 items/thread) ----------------
__device__ __forceinline__ void address_tail(
    float* x, float g, float s0, float s1, float s2, float gamma,
    const float* __restrict__ wpb, float* __restrict__ woutb,
    float* wg, float* rbuf)
{
    int tid = threadIdx.x;
    float mx = fmaxf(fmaxf(x[0], x[1]), fmaxf(x[2], x[3]));
    float bmax = block_reduce_max512(mx, rbuf);
    float lsum = 0.f;
    #pragma unroll
    for (int i = 0; i < 4; i++) {
        float e = __expf(x[i] - bmax);
        wg[tid + i*512] = e;
        lsum += e;
    }
    float bsum = block_reduce_sum512(lsum, rbuf);
    float inv = 1.f / bsum;
    #pragma unroll
    for (int i = 0; i < 4; i++) {
        int n = tid + i*512;
        wg[n] = g * (wg[n]*inv) + (1.f-g) * wpb[n];
    }
    __syncthreads();
    float wpow[4];
    lsum = 0.f;
    #pragma unroll
    for (int i = 0; i < 4; i++) {
        int n = tid + i*512;
        float ws = s0*wg[(n+1)&(N_-1)] + s1*wg[n] + s2*wg[(n-1)&(N_-1)];
        float t = __powf(ws + EPSF, gamma);
        wpow[i] = t;
        lsum += t;
    }
    float psum = block_reduce_sum512(lsum, rbuf);
    float ip = 1.f / psum;
    #pragma unroll
    for (int i = 0; i < 4; i++) {
        float wv = wpow[i]*ip;
        woutb[tid + i*512] = wv;
        x[i] = wv;
    }
}

__device__ __forceinline__ void head_scalars(const float* __restrict__ p, float ksum, float* sc)
{
    sc[0] = sqrtf(ksum);
    sc[1] = softplusf(p[64]);
    sc[2] = sigmoidf(p[65]);
    float a0 = p[66], a1 = p[67], a2 = p[68];
    float mx = fmaxf(a0, fmaxf(a1, a2));
    float e0 = expf(a0-mx), e1 = expf(a1-mx), e2 = expf(a2-mx);
    float es = e0 + e1 + e2;
    sc[3] = e0/es; sc[4] = e1/es; sc[5] = e2/es;
    sc[6] = 1.f + softplusf(p[69]);
}

__device__ __forceinline__ void poly_x(
    float* x, const float* wdone, size_t base,
    float CC, float UU, float knorm, float beta)
{
    int tid = threadIdx.x;
    const size_t P = (size_t)B_*N_;
    const float* nrmp = g_norm + base;
    #pragma unroll
    for (int i = 0; i < 4; i++) {
        int n = tid + i*512;
        float w  = wdone[i];
        float Da = g_base[0*P + base + n];
        float Db = g_base[1*P + base + n];
        float S1 = g_base[2*P + base + n];
        float S2 = g_base[3*P + base + n];
        float T0 = g_base[4*P + base + n];
        float T1 = g_base[5*P + base + n];
        float nr = nrmp[n];
        float S0 = nr*nr;
        float dotv = Da - w*Db + w*CC;
        float w2 = w*w;
        float nsq = S0 - 2.f*w*S1 + w2*S2 + 2.f*w*T0 - 2.f*w2*T1 + w2*UU;
        float nn = sqrtf(fmaxf(nsq, 0.f));
        x[i] = beta * (dotv / (nn*knorm + EPSF));
    }
}

// ---------------- fused addressing: 4 read heads (y=0..3) + write heads 0&1 (y=4) -------------
__global__ void __launch_bounds__(512) address5_kernel(
    const float* __restrict__ prw,
    const float* __restrict__ pww,
    float* __restrict__ o_rw,
    float* __restrict__ o_ww)
{
    __shared__ float wg[2048];
    __shared__ float rbuf[32];
    __shared__ float sc[16];
    int b = blockIdx.x, h = blockIdx.y, tid = threadIdx.x;
    size_t base = (size_t)b*N_;
    const size_t P = (size_t)B_*N_;

    if (h < 4) {
        const float* p = g_rp + ((size_t)h*B_ + b)*PR_;
        float kv = 0.f;
        if (tid < 64) { float xx = p[tid]; kv = xx*xx; }
        float ksum = block_reduce_sum512(kv, rbuf);
        if (tid == 0) head_scalars(p, ksum, sc);
        __syncthreads();
        float knorm = sc[0], beta = sc[1], g = sc[2];
        float s0 = sc[3], s1 = sc[4], s2 = sc[5], gamma = sc[6];

        const float* dotb = g_dot + (size_t)h*P + base;
        const float* nrmb = g_norm + base;
        float x[4];
        #pragma unroll
        for (int i = 0; i < 4; i++) {
            int n = tid + i*512;
            x[i] = beta * (dotb[n] / (nrmb[n]*knorm + EPSF));
        }
        address_tail(x, g, s0, s1, s2, gamma,
                     prw + (size_t)h*P + base, o_rw + (size_t)h*P + base, wg, rbuf);
    } else {
        const float* p0 = g_wp + (size_t)b*PW_;
        const float* p1 = g_wp + ((size_t)1*B_ + b)*PW_;
        float kv0 = 0.f, kv1 = 0.f, c1 = 0.f, c2 = 0.f;
        if (tid < 64) {
            float k0 = p0[tid], k1 = p1[tid];
            float a0 = tanhf(p0[134 + tid]);
            kv0 = k0*k0; kv1 = k1*k1; c1 = a0*k1; c2 = a0*a0;
        }
        float ks0 = block_reduce_sum512(kv0, rbuf);
        float ks1 = block_reduce_sum512(kv1, rbuf);
        float Cc  = block_reduce_sum512(c1, rbuf);
        float U   = block_reduce_sum512(c2, rbuf);
        if (tid == 0) {
            head_scalars(p0, ks0, sc);
            head_scalars(p1, ks1, sc + 7);
            sc[14] = Cc; sc[15] = U;
        }
        __syncthreads();

        float knorm = sc[0], beta = sc[1], g = sc[2];
        float s0 = sc[3], s1 = sc[4], s2 = sc[5], gamma = sc[6];
        const float* dotb = g_dot + 4*P + base;
        const float* nrmb = g_norm + base;
        float x[4];
        #pragma unroll
        for (int i = 0; i < 4; i++) {
            int n = tid + i*512;
            x[i] = beta * (dotb[n] / (nrmb[n]*knorm + EPSF));
        }
        address_tail(x, g, s0, s1, s2, gamma, pww + base, o_ww + base, wg, rbuf);
        __syncthreads();
        float y[4];
        poly_x(y, x, base, sc[14], sc[15], sc[7], sc[8]);
        address_tail(y, sc[9], sc[10], sc[11], sc[12], sc[13],
                     pww + P + base, o_ww + P + base, wg, rbuf);
    }
}

// ---------------- fused write heads 2 & 3 ----------------
__global__ void __launch_bounds__(512) addr23_kernel(
    const float* __restrict__ pww,
    float* __restrict__ o_ww)
{
    __shared__ float wg[2048];
    __shared__ float rbuf[32];
    __shared__ float sc[16];
    int b = blockIdx.x, tid = threadIdx.x;
    size_t base = (size_t)b*N_;
    const size_t P = (size_t)B_*N_;

    const float* p2 = g_wp + ((size_t)2*B_ + b)*PW_;
    const float* p3 = g_wp + ((size_t)3*B_ + b)*PW_;
    float kv2 = 0.f, kv3 = 0.f, c1 = 0.f, c2 = 0.f;
    if (tid < 64) {
        float k2 = p2[tid], k3 = p3[tid];
        float a2 = tanhf(p2[134 + tid]);
        kv2 = k2*k2; kv3 = k3*k3; c1 = a2*k3; c2 = a2*a2;
    }
    float ks2 = block_reduce_sum512(kv2, rbuf);
    float ks3 = block_reduce_sum512(kv3, rbuf);
    float Cc  = block_reduce_sum512(c1, rbuf);
    float U   = block_reduce_sum512(c2, rbuf);
    if (tid == 0) {
        head_scalars(p2, ks2, sc);
        head_scalars(p3, ks3, sc + 7);
        sc[14] = Cc; sc[15] = U;
    }
    __syncthreads();

    float knorm = sc[0], beta = sc[1], g = sc[2];
    float s0 = sc[3], s1 = sc[4], s2 = sc[5], gamma = sc[6];
    const float* dotb = g_dot + 4*P + base;
    const float* nrmb = g_norm + base;
    float x[4];
    #pragma unroll
    for (int i = 0; i < 4; i++) {
        int n = tid + i*512;
        x[i] = beta * (dotb[n] / (nrmb[n]*knorm + EPSF));
    }
    address_tail(x, g, s0, s1, s2, gamma, pww + 2*P + base, o_ww + 2*P + base, wg, rbuf);
    __syncthreads();
    float y[4];
    poly_x(y, x, base, sc[14], sc[15], sc[7], sc[8]);
    address_tail(y, sc[9], sc[10], sc[11], sc[12], sc[13],
                 pww + 3*P + base, o_ww + 3*P + base, wg, rbuf);
}

// ---------------- Sweep 1 (two-phase thread-per-row): stats + reads einsum ----------------
// grid 2048 = (b, eighthN=256 rows), 256 threads.
__global__ void __launch_bounds__(256) sweep1_kernel(
    const float* __restrict__ mem_in,
    const float* __restrict__ wr,    // new_read_w [4][B][N]
    const float* __restrict__ wwp,   // new_write_w planes (0,1 used)
    float* __restrict__ ro_part)
{
    int bc = blockIdx.x; int b = bc >> 3; int nb = (bc & 7) << 8;
    int tid = threadIdx.x, wid = tid >> 5, lane = tid & 31;
    const size_t P = (size_t)B_*N_;

    // constants: [0]=k2 [1]=e2k3 [2]=e2 [3]=e2sq [4]=a2 [5]=e2a2 [6]=k3 [7]=e0 [8]=a0 [9]=e1 [10]=a1
    __shared__ float cst[11][64];
    __shared__ float ws4[256][4];      // read weights per row (4 heads)
    __shared__ float2 sred[8][4][32];  // einsum warp partials
    if (tid < 64) {
        const float* p0 = g_wp + (size_t)b*PW_;
        const float* p1 = g_wp + ((size_t)1*B_ + b)*PW_;
        const float* p2 = g_wp + ((size_t)2*B_ + b)*PW_;
        const float* p3 = g_wp + ((size_t)3*B_ + b)*PW_;
        float e2 = sigmoidf(p2[70 + tid]);
        float a2 = tanhf(p2[134 + tid]);
        float k3 = p3[tid];
        cst[0][tid]  = p2[tid];
        cst[1][tid]  = e2*k3;
        cst[2][tid]  = e2;
        cst[3][tid]  = e2*e2;
        cst[4][tid]  = a2;
        cst[5][tid]  = e2*a2;
        cst[6][tid]  = k3;
        cst[7][tid]  = sigmoidf(p0[70 + tid]);
        cst[8][tid]  = tanhf(p0[134 + tid]);
        cst[9][tid]  = sigmoidf(p1[70 + tid]);
        cst[10][tid] = tanhf(p1[134 + tid]);
    }
    size_t ix = (size_t)b*N_ + nb + tid;
    #pragma unroll
    for (int h = 0; h < 4; h++) ws4[tid][h] = wr[(size_t)h*P + ix];
    __syncthreads();

    // ---- phase 1: per-row stats (thread-per-row, zero shuffles) ----
    float w0 = wwp[ix], w1 = wwp[P + ix];
    const float4* rp4 = (const float4*)(mem_in + ix*M_);
    float acc[8] = {};
    #pragma unroll
    for (int mb = 0; mb < 16; mb++) {
        float4 d = rp4[mb];
        float4 c[11];
        #pragma unroll
        for (int ci = 0; ci < 11; ci++)
            c[ci] = *(const float4*)&cst[ci][mb*4];
        float vv[4] = {d.x, d.y, d.z, d.w};
        #pragma unroll
        for (int j = 0; j < 4; j++) {
            float v  = vv[j];
            float e0 = ((const float*)&c[7])[j], a0 = ((const float*)&c[8])[j];
            float e1 = ((const float*)&c[9])[j], a1 = ((const float*)&c[10])[j];
            float m1 = v*(1.f - w0*e0) + w0*a0;
            float m2 = m1*(1.f - w1*e1) + w1*a1;
            float s  = m2*m2;
            acc[0] += m2 * ((const float*)&c[0])[j];  // dot2
            acc[1] += s;                               // norm2^2
            acc[2] += m2 * ((const float*)&c[6])[j];  // Da (k3)
            acc[3] += m2 * ((const float*)&c[1])[j];  // Db (e2k3)
            acc[4] += s  * ((const float*)&c[2])[j];  // S1
            acc[5] += s  * ((const float*)&c[3])[j];  // S2
            acc[6] += m2 * ((const float*)&c[4])[j];  // T0
            acc[7] += m2 * ((const float*)&c[5])[j];  // T1
        }
    }
    g_dot[4*P + ix] = acc[0];
    g_norm[ix] = sqrtf(acc[1]);
    #pragma unroll
    for (int r = 0; r < 6; r++) g_base[(size_t)r*P + ix] = acc[2+r];

    // ---- phase 2: reads einsum (lane-per-m, warp over its 32 rows; tiles are L1/L2 hot) ----
    float2 racc[4] = {{0,0},{0,0},{0,0},{0,0}};
    size_t rowbase = (size_t)b*N_ + nb + wid*32;
    #pragma unroll 4
    for (int r = 0; r < 32; r++) {
        float2 v2 = *(const float2*)(mem_in + (rowbase + r)*M_ + 2*lane);
        float4 w4 = *(const float4*)&ws4[wid*32 + r][0];
        racc[0].x += w4.x*v2.x; racc[0].y += w4.x*v2.y;
        racc[1].x += w4.y*v2.x; racc[1].y += w4.y*v2.y;
        racc[2].x += w4.z*v2.x; racc[2].y += w4.z*v2.y;
        racc[3].x += w4.w*v2.x; racc[3].y += w4.w*v2.y;
    }
    #pragma unroll
    for (int h = 0; h < 4; h++) sred[wid][h][lane] = racc[h];
    __syncthreads();
    int h = tid >> 6, m = tid & 63;
    int l = m >> 1, c = m & 1;
    float s = 0.f;
    #pragma unroll
    for (int w = 0; w < 8; w++) {
        float2 t = sred[w][h][l];
        s += c ? t.y : t.x;
    }
    ro_part[(size_t)(bc & 7)*B_*256 + (size_t)b*256 + h*64 + m] = s;
}

// ---------------- Fused tail: sweep2 (blocks 0..1023) + output GEMM (blocks 1024..1055) -------
__global__ void __launch_bounds__(256) tail_kernel(
    const float* __restrict__ mem_in, float* __restrict__ mem_out,
    const float* __restrict__ wwp,
    const float* __restrict__ ctrl, const float* __restrict__ part,
    const float* __restrict__ W, const float* __restrict__ bias,
    float* __restrict__ out, float* __restrict__ o_ro)
{
    __shared__ float As[32][33];
    __shared__ float Ws[32][64];
    int tid = threadIdx.x;

    if (blockIdx.x < 1024) {
        // ---- sweep2: all 4 head updates, original mem -> final mem ----
        int bc = blockIdx.x; int b = bc >> 2; int nb = (bc & 3) << 9;
        int wid = tid >> 5, lane = tid & 31;
        int hw = lane >> 4, l16 = lane & 15;

        float e[4][4], a[4][4];
        #pragma unroll
        for (int h = 0; h < 4; h++) {
            const float* ph = g_wp + ((size_t)h*B_ + b)*PW_;
            #pragma unroll
            for (int j = 0; j < 4; j++) {
                int m = l16*4 + j;
                e[h][j] = sigmoidf(ph[70 + m]);
                a[h][j] = tanhf(ph[134 + m]);
            }
        }

        const size_t P = (size_t)B_*N_;
        for (int it = 0; it < 32; it += 4) {
            int r0 = it*16 + wid*2 + hw;
            size_t ix[4];
            float4 v[4];
            #pragma unroll
            for (int q = 0; q < 4; q++) {
                ix[q] = (size_t)b*N_ + nb + r0 + q*16;
                v[q] = *(const float4*)(mem_in + ix[q]*M_ + l16*4);
            }
            float w[4][4];
            #pragma unroll
            for (int q = 0; q < 4; q++)
                #pragma unroll
                for (int h = 0; h < 4; h++)
                    w[q][h] = wwp[(size_t)h*P + ix[q]];

            #pragma unroll
            for (int q = 0; q < 4; q++) {
                float vv[4] = {v[q].x, v[q].y, v[q].z, v[q].w};
                #pragma unroll
                for (int j = 0; j < 4; j++) {
                    float m = vv[j];
                    #pragma unroll
                    for (int h = 0; h < 4; h++)
                        m = m*(1.f - w[q][h]*e[h][j]) + w[q][h]*a[h][j];
                    vv[j] = m;
                }
                *(float4*)(mem_out + ix[q]*M_ + l16*4) = make_float4(vv[0], vv[1], vv[2], vv[3]);
            }
        }
    } else {
        // ---- output GEMM with fused ro-sum: A = [ctrl | sum8(ro_part)] ----
        constexpr int Nc = 256;
        int t = blockIdx.x - 1024;
        int cx = t & 3, ry = t >> 2;
        int col0 = cx * 64;
        int row0 = ry * 32;
        int tx = tid & 15, ty = tid >> 4;
        float acc[2][4] = {};

        for (int k0 = 0; k0 < 768; k0 += 32) {
            {
                int m  = tid >> 3;
                int kk = (tid & 7) * 4;
                int r = row0 + m, c = k0 + kk;
                float4 v;
                if (c < 512) {
                    v = *(const float4*)(ctrl + (size_t)r*512 + c);
                } else {
                    int cc = c - 512;
                    const float* p = part + (size_t)r*256 + cc;
                    v = *(const float4*)p;
                    #pragma unroll
                    for (int q = 1; q < 8; q++) {
                        float4 vq = *(const float4*)(p + (size_t)q*B_*256);
                        v.x += vq.x; v.y += vq.y; v.z += vq.z; v.w += vq.w;
                    }
                    if (cx == 0)
                        *(float4*)(o_ro + (size_t)r*256 + cc) = v;
                }
                As[m][kk] = v.x; As[m][kk+1] = v.y; As[m][kk+2] = v.z; As[m][kk+3] = v.w;
            }
            {
                int kk = tid >> 3;
                int n0 = (tid & 7) * 8;
                const float* wrow = W + (size_t)(k0 + kk)*Nc + col0 + n0;
                #pragma unroll
                for (int j = 0; j < 8; j++)
                    Ws[kk][n0 + j] = wrow[j];
            }
            __syncthreads();
            #pragma unroll
            for (int kk = 0; kk < 32; kk++) {
                float a0 = As[ty*2 + 0][kk];
                float a1 = As[ty*2 + 1][kk];
                float4 w4 = *(const float4*)&Ws[kk][tx*4];
                acc[0][0] += a0*w4.x; acc[0][1] += a0*w4.y; acc[0][2] += a0*w4.z; acc[0][3] += a0*w4.w;
                acc[1][0] += a1*w4.x; acc[1][1] += a1*w4.y; acc[1][2] += a1*w4.z; acc[1][3] += a1*w4.w;
            }
            __syncthreads();
        }
        #pragma unroll
        for (int i = 0; i < 2; i++) {
            int gm = row0 + ty*2 + i;
            #pragma unroll
            for (int j = 0; j < 4; j++) {
                int gn = col0 + tx*4 + j;
                out[(size_t)gm*Nc + gn] = acc[i][j] + bias[gn];
            }
        }
    }
}

// ---------------- host launcher ----------------
extern "C" void kernel_launch(void* const* d_in, const int* in_sizes, int n_in,
                              void* d_out, int out_size)
{
    const float* ext    = (const float*)d_in[0];
    const float* pread  = (const float*)d_in[1];
    const float* prw    = (const float*)d_in[2];
    const float* pww    = (const float*)d_in[3];
    const float* mem    = (const float*)d_in[4];
    const float* ctrlW  = (const float*)d_in[5];
    const float* ctrlb  = (const float*)d_in[6];
    const float* readW  = (const float*)d_in[7];
    const float* readb  = (const float*)d_in[8];
    const float* writeW = (const float*)d_in[9];
    const float* writeb = (const float*)d_in[10];
    const float* outW   = (const float*)d_in[11];
    const float* outb   = (const float*)d_in[12];
    float* out = (float*)d_out;

    float *ctrl, *rp, *wp, *ropart;
    cudaGetSymbolAddress((void**)&ctrl,   g_ctrl);
    cudaGetSymbolAddress((void**)&rp,     g_rp);
    cudaGetSymbolAddress((void**)&wp,     g_wp);
    cudaGetSymbolAddress((void**)&ropart, g_ropart);

    float* o_mem = out + OUT_MEM;
    float* o_ro  = out + OUT_RO;
    float* o_rw  = out + OUT_RW;
    float* o_ww  = out + OUT_WW;

    // Controller GEMM with fused concat
    gemm_cat_kernel<<<dim3(8, 8), 256>>>(ext, 256, pread, 256, ctrlW, ctrlb, ctrl, 512);

    // All 8 head parameter GEMMs in one launch
    gemm_heads_kernel<<<dim3(4, 8, 8), 256>>>(ctrl, readW, readb, rp, writeW, writeb, wp);

    // Pass A (thread-per-row)
    passA_kernel<<<2048, 256>>>(mem);

    // Addressing: 4 read heads + write heads 0&1
    address5_kernel<<<dim3(256, 5), 512>>>(prw, pww, o_rw, o_ww);

    // Sweep 1: stats (thread-per-row) + reads einsum (lane-per-m)
    sweep1_kernel<<<2048, 256>>>(mem, o_rw, o_ww, ropart);

    // Write heads 2 & 3
    addr23_kernel<<<256, 512>>>(pww, o_ww);

    // Fused tail: sweep2 + output GEMM (with 8-plane ro-sum)
    tail_kernel<<<1056, 256>>>(mem, o_mem, o_ww, ctrl, ropart, outW, outb, out, o_ro);
}